// round 10
// baseline (speedup 1.0000x reference)
#include <cuda_runtime.h>
#include <cuda_fp16.h>
#include <math.h>

#define BB   64
#define NN   512
#define FIN  256
#define DD   128
#define KTOP 20
#define HIDN 512

// ---- scratch (device globals; no allocations) ----
static __device__ __half d_xl16[BB*NN*DD];     // [b,n,d] lin(x), fp16
static __device__ __half d_gT16[BB*DD*NN];     // [b,d,n] gated GCN output (transposed), fp16
static __device__ __half d_o116[BB*DD*HIDN];   // [b,d,h] first linear, fp16
static __device__ __half d_w116[HIDN*NN];      // w1 fp16
static __device__ __half d_w216[HIDN*HIDN];    // w2 fp16
static __device__ float  d_p [BB*NN];
static __device__ float  d_q [BB*NN];
static __device__ float  d_rinv[NN];
static __device__ float  d_r [NN];
static __device__ float  d_s [NN];
static __device__ int    d_topk[NN*KTOP];

// ---------------- MMA / cp.async helpers ----------------
__device__ __forceinline__ void mma_tf32(float c[4],
        unsigned a0, unsigned a1, unsigned a2, unsigned a3,
        unsigned b0, unsigned b1) {
    asm volatile(
        "mma.sync.aligned.m16n8k8.row.col.f32.tf32.tf32.f32 "
        "{%0,%1,%2,%3}, {%4,%5,%6,%7}, {%8,%9}, {%0,%1,%2,%3};\n"
        : "+f"(c[0]), "+f"(c[1]), "+f"(c[2]), "+f"(c[3])
        : "r"(a0), "r"(a1), "r"(a2), "r"(a3), "r"(b0), "r"(b1));
}
__device__ __forceinline__ void mma_f16(float c[4],
        unsigned a0, unsigned a1, unsigned a2, unsigned a3,
        unsigned b0, unsigned b1) {
    asm volatile(
        "mma.sync.aligned.m16n8k16.row.col.f32.f16.f16.f32 "
        "{%0,%1,%2,%3}, {%4,%5,%6,%7}, {%8,%9}, {%0,%1,%2,%3};\n"
        : "+f"(c[0]), "+f"(c[1]), "+f"(c[2]), "+f"(c[3])
        : "r"(a0), "r"(a1), "r"(a2), "r"(a3), "r"(b0), "r"(b1));
}
__device__ __forceinline__ void cpa16(void* dst, const void* src) {
    unsigned ds = (unsigned)__cvta_generic_to_shared(dst);
    asm volatile("cp.async.cg.shared.global [%0], [%1], 16;" :: "r"(ds), "l"(src));
}
#define CP_COMMIT asm volatile("cp.async.commit_group;")
#define CP_WAIT1  asm volatile("cp.async.wait_group 1;")
#define CP_WAIT0  asm volatile("cp.async.wait_group 0;")
#define NSTAGE    3

// ---- tf32 k_xl geometry ----
#define A_KN_WORDS 4352          // [32 k][136]
#define B_KN_WORDS 4608          // [128][36]
#define STG_KN     (A_KN_WORDS + B_KN_WORDS)   // 8960 w

// ---- fp16 gemm geometry ----
#define HROW_W     36
#define H_OP_WORDS (128*HROW_W)                 // 4608 words per operand
#define STG_H      (2*H_OP_WORDS)               // 9216 words per stage

// tf32 chunk: A [k][136], B [m][36]
#define CHUNK_KN(pA, pB)                                                        \
    _Pragma("unroll")                                                            \
    for (int ks = 0; ks < 4; ks++) {                                             \
        int k8 = ks*8;                                                           \
        unsigned af[4][4], bf[4][2];                                             \
        _Pragma("unroll")                                                        \
        for (int mi = 0; mi < 4; mi++) {                                         \
            int r = wm + mi*16 + g;                                              \
            af[mi][0] = (pA)[(k8+t4  )*136 + r    ];                             \
            af[mi][1] = (pA)[(k8+t4  )*136 + r + 8];                             \
            af[mi][2] = (pA)[(k8+t4+4)*136 + r    ];                             \
            af[mi][3] = (pA)[(k8+t4+4)*136 + r + 8];                             \
        }                                                                        \
        _Pragma("unroll")                                                        \
        for (int ni = 0; ni < 4; ni++) {                                         \
            int rn = wn + ni*8 + g;                                              \
            bf[ni][0] = (pB)[rn*36 + k8+t4    ];                                 \
            bf[ni][1] = (pB)[rn*36 + k8+t4 + 4];                                 \
        }                                                                        \
        _Pragma("unroll")                                                        \
        for (int mi = 0; mi < 4; mi++)                                           \
            _Pragma("unroll")                                                    \
            for (int ni = 0; ni < 4; ni++)                                       \
                mma_tf32(c[mi][ni], af[mi][0], af[mi][1], af[mi][2],             \
                         af[mi][3], bf[ni][0], bf[ni][1]);                       \
    }

// fp16 chunk (K=64): A [m][36w], B [n][36w]
#define CHUNK_H(pA, pB)                                                         \
    _Pragma("unroll")                                                            \
    for (int ks = 0; ks < 4; ks++) {                                             \
        int kw = ks*8;                                                           \
        unsigned af[4][4], bf[4][2];                                             \
        _Pragma("unroll")                                                        \
        for (int mi = 0; mi < 4; mi++) {                                         \
            int r = wm + mi*16 + g;                                              \
            af[mi][0] = (pA)[(r    )*HROW_W + kw + t4    ];                      \
            af[mi][1] = (pA)[(r + 8)*HROW_W + kw + t4    ];                      \
            af[mi][2] = (pA)[(r    )*HROW_W + kw + t4 + 4];                      \
            af[mi][3] = (pA)[(r + 8)*HROW_W + kw + t4 + 4];                      \
        }                                                                        \
        _Pragma("unroll")                                                        \
        for (int ni = 0; ni < 4; ni++) {                                         \
            int rn = wn + ni*8 + g;                                              \
            bf[ni][0] = (pB)[rn*HROW_W + kw + t4    ];                           \
            bf[ni][1] = (pB)[rn*HROW_W + kw + t4 + 4];                           \
        }                                                                        \
        _Pragma("unroll")                                                        \
        for (int mi = 0; mi < 4; mi++)                                           \
            _Pragma("unroll")                                                    \
            for (int ni = 0; ni < 4; ni++)                                       \
                mma_f16(c[mi][ni], af[mi][0], af[mi][1], af[mi][2],              \
                        af[mi][3], bf[ni][0], bf[ni][1]);                        \
    }

// ---------------------------------------------------------------
// K0: per-node norms + emb dot att_em
// ---------------------------------------------------------------
__global__ void k_norm(const float* __restrict__ emb,
                       const float* __restrict__ aei,
                       const float* __restrict__ aej) {
    int n = blockIdx.x, t = threadIdx.x;
    float w  = emb[n*DD + t];
    float v0 = w*w, v1 = w*aei[t], v2 = w*aej[t];
    #pragma unroll
    for (int o = 16; o; o >>= 1) {
        v0 += __shfl_xor_sync(0xffffffffu, v0, o);
        v1 += __shfl_xor_sync(0xffffffffu, v1, o);
        v2 += __shfl_xor_sync(0xffffffffu, v2, o);
    }
    __shared__ float s0[4], s1[4], s2[4];
    int wid = t >> 5, lane = t & 31;
    if (lane == 0) { s0[wid]=v0; s1[wid]=v1; s2[wid]=v2; }
    __syncthreads();
    if (t == 0) {
        d_rinv[n] = rsqrtf(s0[0]+s0[1]+s0[2]+s0[3]);
        d_r[n] = s1[0]+s1[1]+s1[2]+s1[3];
        d_s[n] = s2[0]+s2[1]+s2[2]+s2[3];
    }
}

// ---------------------------------------------------------------
// K1: FUSED cosine row + top-20.  One block per row i (512 blocks).
//   256 threads compute cos(i, :) into smem; warp 0 does topk
//   (ties -> lower index, same semantics as the proven k_topk).
// ---------------------------------------------------------------
__global__ void __launch_bounds__(256) k_costopk(const float* __restrict__ emb) {
    __shared__ float embi[DD];
    __shared__ float cv[NN];
    int i = blockIdx.x;
    int tid = threadIdx.x;
    if (tid < DD) embi[tid] = emb[i*DD + tid];
    __syncthreads();
    float ri = d_rinv[i];
    #pragma unroll
    for (int c = 0; c < 2; c++) {
        int j = tid + c*256;
        const float4* er = (const float4*)(emb + (size_t)j*DD);
        float dot = 0.f;
        #pragma unroll 8
        for (int k = 0; k < 32; k++) {
            float4 v = er[k];
            float4 w = *(const float4*)&embi[k*4];
            dot += v.x*w.x + v.y*w.y + v.z*w.z + v.w*w.w;
        }
        cv[j] = dot * ri * d_rinv[j];
    }
    __syncthreads();
    if (tid < 32) {                 // warp 0: register topk over the row
        int lane = tid;
        float v[16];
        #pragma unroll
        for (int j2 = 0; j2 < 16; j2++) v[j2] = cv[lane + 32*j2];
        for (int t = 0; t < KTOP; t++) {
            float bv = v[0]; int bj = 0;
            #pragma unroll
            for (int j2 = 1; j2 < 16; j2++)
                if (v[j2] > bv) { bv = v[j2]; bj = j2; }
            int bidx = lane + 32*bj;
            #pragma unroll
            for (int o = 16; o; o >>= 1) {
                float ov = __shfl_xor_sync(0xffffffffu, bv, o);
                int   oi = __shfl_xor_sync(0xffffffffu, bidx, o);
                if (ov > bv || (ov == bv && oi < bidx)) { bv = ov; bidx = oi; }
            }
            if (lane == 0) d_topk[i*KTOP + t] = bidx;
            #pragma unroll
            for (int j2 = 0; j2 < 16; j2++)
                if (lane + 32*j2 == bidx) v[j2] = -INFINITY;
        }
    }
}

// ---------------------------------------------------------------
// K_cvtw: both weight converts in one launch. Destinations are
// __device__ globals referenced from device code only.
// ---------------------------------------------------------------
__global__ void k_cvtw(const float* __restrict__ w1, const float* __restrict__ w2) {
    int idx = blockIdx.x*256 + threadIdx.x;
    const int N1 = HIDN*NN/4;       // 65536 float4 groups in w1
    if (idx < N1) {
        float4 v = *(const float4*)(w1 + (size_t)idx*4);
        __half2* d2 = (__half2*)(d_w116 + (size_t)idx*4);
        d2[0] = __floats2half2_rn(v.x, v.y);
        d2[1] = __floats2half2_rn(v.z, v.w);
    } else {
        int j = idx - N1;
        float4 v = *(const float4*)(w2 + (size_t)j*4);
        __half2* d2 = (__half2*)(d_w216 + (size_t)j*4);
        d2[0] = __floats2half2_rn(v.x, v.y);
        d2[1] = __floats2half2_rn(v.z, v.w);
    }
}

// ---------------------------------------------------------------
// K3: xl (tf32 MMA, 3-stage) + fused p/q epilogue.
// ---------------------------------------------------------------
__global__ void __launch_bounds__(256, 2) k_xl(const float* __restrict__ data,
                                               const float* __restrict__ linw,
                                               const float* __restrict__ ai,
                                               const float* __restrict__ aj) {
    extern __shared__ unsigned smu[];
    __shared__ float spq[DD][2];
    int b = blockIdx.y, n0 = blockIdx.x * 128;
    int tid = threadIdx.x;
    int w = tid >> 5, lane = tid & 31;
    int g = lane >> 2, t4 = lane & 3;
    int wm = (w & 1) * 64, wn = (w >> 1) * 32;
    if (tid < DD) { spq[tid][0] = 0.f; spq[tid][1] = 0.f; }
    float c[4][4][4] = {};

    #define XL_LOAD(st, f0)                                                      \
        {                                                                        \
            unsigned* pA = smu + (st)*STG_KN;                                    \
            unsigned* pB = pA + A_KN_WORDS;                                      \
            _Pragma("unroll")                                                    \
            for (int a = 0; a < 4; a++) {                                        \
                int idx = tid + a*256;                                           \
                int kk = idx >> 5, n4 = idx & 31;                                \
                cpa16(pA + kk*136 + n4*4,                                        \
                      data + ((size_t)b*FIN + (f0) + kk)*NN + n0 + n4*4);        \
            }                                                                    \
            _Pragma("unroll")                                                    \
            for (int a = 0; a < 4; a++) {                                        \
                int idx = tid + a*256;                                           \
                int dd = idx >> 3, k4 = idx & 7;                                 \
                cpa16(pB + dd*36 + k4*4, linw + dd*FIN + (f0) + k4*4);           \
            }                                                                    \
        }

    XL_LOAD(0, 0) CP_COMMIT;
    XL_LOAD(1, 32) CP_COMMIT;
    #pragma unroll 1
    for (int it = 0; it < FIN/32; it++) {
        if (it + 1 < FIN/32) { CP_WAIT1; } else { CP_WAIT0; }
        __syncthreads();
        if (it + 2 < FIN/32) { XL_LOAD((it+2)%NSTAGE, (it+2)*32) CP_COMMIT; }
        unsigned* pA = smu + (it%NSTAGE)*STG_KN;
        unsigned* pB = pA + A_KN_WORDS;
        CHUNK_KN(pA, pB)
    }
    #undef XL_LOAD

    float pv[8] = {}, qv[8] = {};
    #pragma unroll
    for (int mi = 0; mi < 4; mi++)
        #pragma unroll
        for (int ni = 0; ni < 4; ni++) {
            int row = n0 + wm + mi*16 + g, col = wn + ni*8 + t4*2;
            size_t i0 = ((size_t)b*NN + row    )*DD + col;
            size_t i1 = ((size_t)b*NN + row + 8)*DD + col;
            *(__half2*)&d_xl16[i0] = __floats2half2_rn(c[mi][ni][0], c[mi][ni][1]);
            *(__half2*)&d_xl16[i1] = __floats2half2_rn(c[mi][ni][2], c[mi][ni][3]);
            float a0 = ai[col], a1 = ai[col+1];
            float j0 = aj[col], j1 = aj[col+1];
            pv[mi*2  ] += c[mi][ni][0]*a0 + c[mi][ni][1]*a1;
            pv[mi*2+1] += c[mi][ni][2]*a0 + c[mi][ni][3]*a1;
            qv[mi*2  ] += c[mi][ni][0]*j0 + c[mi][ni][1]*j1;
            qv[mi*2+1] += c[mi][ni][2]*j0 + c[mi][ni][3]*j1;
        }
    #pragma unroll
    for (int r = 0; r < 8; r++) {
        pv[r] += __shfl_xor_sync(0xffffffffu, pv[r], 1);
        pv[r] += __shfl_xor_sync(0xffffffffu, pv[r], 2);
        qv[r] += __shfl_xor_sync(0xffffffffu, qv[r], 1);
        qv[r] += __shfl_xor_sync(0xffffffffu, qv[r], 2);
    }
    if (t4 == 0) {
        #pragma unroll
        for (int mi = 0; mi < 4; mi++) {
            int r0 = wm + mi*16 + g;
            atomicAdd(&spq[r0][0],   pv[mi*2]);
            atomicAdd(&spq[r0][1],   qv[mi*2]);
            atomicAdd(&spq[r0+8][0], pv[mi*2+1]);
            atomicAdd(&spq[r0+8][1], qv[mi*2+1]);
        }
    }
    __syncthreads();
    if (tid < 2*DD) {
        int row = tid >> 1, which = tid & 1;
        float v = spq[row][which];
        if (which == 0) d_p[b*NN + n0 + row] = v;
        else            d_q[b*NN + n0 + row] = v;
    }
}

// ---------------------------------------------------------------
// K5: attention softmax + aggregate (fp16 gather) + BN/ReLU/gate,
//     emit gT[b][d][n] via smem staging.
// ---------------------------------------------------------------
#define GTS_PITCH 264
__global__ void __launch_bounds__(256, 1) k_attn2(const float* __restrict__ emb,
                                                  const float* __restrict__ gbias,
                                                  const float* __restrict__ gamma,
                                                  const float* __restrict__ beta) {
    extern __shared__ __half gts[];    // [128][GTS_PITCH] = 67584 B
    int b = blockIdx.x >> 1, nhalf = blockIdx.x & 1;
    int n0 = nhalf * 256;
    int tid = threadIdx.x, wrp = tid >> 5, lane = tid & 31;

    const float inv = rsqrtf(1.0f + 1e-5f);
    for (int i = 0; i < 32; i++) {
        int n = n0 + wrp*32 + i;
        int widx = b*NN + n;
        int src_k = 0; float alpha = -1e30f;
        if (lane < KTOP) {
            src_k = d_topk[n*KTOP + lane];
            alpha = d_p[widx] + d_r[n] + d_q[b*NN + src_k] + d_s[src_k];
            alpha = alpha > 0.f ? alpha : 0.2f*alpha;
        }
        float m = alpha;
        #pragma unroll
        for (int o = 16; o; o >>= 1) m = fmaxf(m, __shfl_xor_sync(0xffffffffu, m, o));
        float ex = (lane < KTOP) ? expf(alpha - m) : 0.f;
        float sm = ex;
        #pragma unroll
        for (int o = 16; o; o >>= 1) sm += __shfl_xor_sync(0xffffffffu, sm, o);
        float aw = ex / sm;

        float2 acc0 = {0.f,0.f}, acc1 = {0.f,0.f};
        #pragma unroll
        for (int k = 0; k < KTOP; k++) {
            int   sk = __shfl_sync(0xffffffffu, src_k, k);
            float ak = __shfl_sync(0xffffffffu, aw,  k);
            const __half2* xr = (const __half2*)(d_xl16 + ((size_t)b*NN + sk)*DD);
            float2 f0 = __half22float2(xr[lane]);
            float2 f1 = __half22float2(xr[lane + 32]);
            acc0.x += ak*f0.x; acc0.y += ak*f0.y;
            acc1.x += ak*f1.x; acc1.y += ak*f1.y;
        }
        int d0 = 2*lane, d1 = 2*lane + 64;
        float h0 = fmaxf((acc0.x + gbias[d0  ])*(gamma[d0  ]*inv) + beta[d0  ], 0.f) * emb[n*DD + d0];
        float h1 = fmaxf((acc0.y + gbias[d0+1])*(gamma[d0+1]*inv) + beta[d0+1], 0.f) * emb[n*DD + d0+1];
        float h2 = fmaxf((acc1.x + gbias[d1  ])*(gamma[d1  ]*inv) + beta[d1  ], 0.f) * emb[n*DD + d1];
        float h3 = fmaxf((acc1.y + gbias[d1+1])*(gamma[d1+1]*inv) + beta[d1+1], 0.f) * emb[n*DD + d1+1];
        int nn = n - n0;
        gts[(d0  )*GTS_PITCH + nn] = __float2half(h0);
        gts[(d0+1)*GTS_PITCH + nn] = __float2half(h1);
        gts[(d1  )*GTS_PITCH + nn] = __float2half(h2);
        gts[(d1+1)*GTS_PITCH + nn] = __float2half(h3);
    }
    __syncthreads();
    for (int row = wrp; row < DD; row += 8) {
        *(uint4*)(d_gT16 + ((size_t)b*DD + row)*NN + n0 + lane*8) =
            *(uint4*)(gts + row*GTS_PITCH + lane*8);
    }
}

// ---------------------------------------------------------------
// K6 (fp16 MMA): o1[b,d,h] = sum_n gT[b,d,n] * w1[h,n]
// ---------------------------------------------------------------
__global__ void __launch_bounds__(256, 2) k_gemm1() {
    extern __shared__ unsigned smu[];
    int b = blockIdx.y, h0 = blockIdx.x * 128;
    int tid = threadIdx.x;
    int w = tid >> 5, lane = tid & 31;
    int g = lane >> 2, t4 = lane & 3;
    int wm = (w & 1) * 64, wn = (w >> 1) * 32;
    float c[4][4][4] = {};

    #define G1_LOAD(st, k0)                                                      \
        {                                                                        \
            unsigned* pA = smu + (st)*STG_H;                                     \
            unsigned* pB = pA + H_OP_WORDS;                                      \
            _Pragma("unroll")                                                    \
            for (int a = 0; a < 4; a++) {                                        \
                int idx = tid + a*256;                                           \
                int row = idx >> 3, seg = idx & 7;                               \
                cpa16(pA + row*HROW_W + seg*4,                                   \
                      d_gT16 + ((size_t)b*DD + row)*NN + (k0) + seg*8);          \
            }                                                                    \
            _Pragma("unroll")                                                    \
            for (int a = 0; a < 4; a++) {                                        \
                int idx = tid + a*256;                                           \
                int row = idx >> 3, seg = idx & 7;                               \
                cpa16(pB + row*HROW_W + seg*4,                                   \
                      d_w116 + (size_t)(h0 + row)*NN + (k0) + seg*8);            \
            }                                                                    \
        }

    G1_LOAD(0, 0) CP_COMMIT;
    G1_LOAD(1, 64) CP_COMMIT;
    #pragma unroll 1
    for (int it = 0; it < NN/64; it++) {
        if (it + 1 < NN/64) { CP_WAIT1; } else { CP_WAIT0; }
        __syncthreads();
        if (it + 2 < NN/64) { G1_LOAD((it+2)%NSTAGE, (it+2)*64) CP_COMMIT; }
        unsigned* pA = smu + (it%NSTAGE)*STG_H;
        unsigned* pB = pA + H_OP_WORDS;
        CHUNK_H(pA, pB)
    }
    #undef G1_LOAD
    #pragma unroll
    for (int mi = 0; mi < 4; mi++)
        #pragma unroll
        for (int ni = 0; ni < 4; ni++) {
            int row = wm + mi*16 + g, col = h0 + wn + ni*8 + t4*2;
            *(__half2*)&d_o116[((size_t)b*DD + row    )*HIDN + col] =
                __floats2half2_rn(c[mi][ni][0], c[mi][ni][1]);
            *(__half2*)&d_o116[((size_t)b*DD + row + 8)*HIDN + col] =
                __floats2half2_rn(c[mi][ni][2], c[mi][ni][3]);
        }
}

// ---------------------------------------------------------------
// K7 (fp16 MMA): out[b,d,h2] = sigmoid(sum_h o1[b,d,h]*w2[h2,h] + b2)
// ---------------------------------------------------------------
__global__ void __launch_bounds__(256, 2) k_gemm2(const float* __restrict__ b2,
                                                  float* __restrict__ out) {
    extern __shared__ unsigned smu[];
    int b = blockIdx.y, h20 = blockIdx.x * 128;
    int tid = threadIdx.x;
    int w = tid >> 5, lane = tid & 31;
    int g = lane >> 2, t4 = lane & 3;
    int wm = (w & 1) * 64, wn = (w >> 1) * 32;
    float c[4][4][4] = {};

    #define G2_LOAD(st, k0)                                                      \
        {                                                                        \
            unsigned* pA = smu + (st)*STG_H;                                     \
            unsigned* pB = pA + H_OP_WORDS;                                      \
            _Pragma("unroll")                                                    \
            for (int a = 0; a < 4; a++) {                                        \
                int idx = tid + a*256;                                           \
                int row = idx >> 3, seg = idx & 7;                               \
                cpa16(pA + row*HROW_W + seg*4,                                   \
                      d_o116 + ((size_t)b*DD + row)*HIDN + (k0) + seg*8);        \
            }                                                                    \
            _Pragma("unroll")                                                    \
            for (int a = 0; a < 4; a++) {                                        \
                int idx = tid + a*256;                                           \
                int row = idx >> 3, seg = idx & 7;                               \
                cpa16(pB + row*HROW_W + seg*4,                                   \
                      d_w216 + (size_t)(h20 + row)*HIDN + (k0) + seg*8);         \
            }                                                                    \
        }

    G2_LOAD(0, 0) CP_COMMIT;
    G2_LOAD(1, 64) CP_COMMIT;
    #pragma unroll 1
    for (int it = 0; it < HIDN/64; it++) {
        if (it + 1 < HIDN/64) { CP_WAIT1; } else { CP_WAIT0; }
        __syncthreads();
        if (it + 2 < HIDN/64) { G2_LOAD((it+2)%NSTAGE, (it+2)*64) CP_COMMIT; }
        unsigned* pA = smu + (it%NSTAGE)*STG_H;
        unsigned* pB = pA + H_OP_WORDS;
        CHUNK_H(pA, pB)
    }
    #undef G2_LOAD
    #pragma unroll
    for (int mi = 0; mi < 4; mi++)
        #pragma unroll
        for (int ni = 0; ni < 4; ni++) {
            int row = wm + mi*16 + g, col = h20 + wn + ni*8 + t4*2;
            float bb0 = b2[col], bb1 = b2[col + 1];
            float2 v0, v1;
            v0.x = 1.0f/(1.0f + expf(-(c[mi][ni][0] + bb0)));
            v0.y = 1.0f/(1.0f + expf(-(c[mi][ni][1] + bb1)));
            v1.x = 1.0f/(1.0f + expf(-(c[mi][ni][2] + bb0)));
            v1.y = 1.0f/(1.0f + expf(-(c[mi][ni][3] + bb1)));
            *(float2*)&out[((size_t)b*DD + row    )*HIDN + col] = v0;
            *(float2*)&out[((size_t)b*DD + row + 8)*HIDN + col] = v1;
        }
}

// ---------------------------------------------------------------
// K8: pack trailing outputs (emb_weight copy, topk_idx as float)
// ---------------------------------------------------------------
__global__ void k_pack(const float* __restrict__ emb, float* __restrict__ out, int mode) {
    int i = blockIdx.x*256 + threadIdx.x;
    const int OUT0 = BB*DD*HIDN;
    if (i < NN*DD) out[OUT0 + i] = emb[i];
    if (mode && i < NN*KTOP) out[OUT0 + NN*DD + i] = (float)d_topk[i];
}

extern "C" void kernel_launch(void* const* d_in, const int* in_sizes, int n_in,
                              void* d_out, int out_size) {
    const float* data  = (const float*)d_in[0];
    const float* emb   = (const float*)d_in[1];
    const float* linw  = (const float*)d_in[2];
    const float* ai    = (const float*)d_in[3];
    const float* aj    = (const float*)d_in[4];
    const float* aei   = (const float*)d_in[5];
    const float* aej   = (const float*)d_in[6];
    const float* gbias = (const float*)d_in[7];
    const float* gamma = (const float*)d_in[8];
    const float* beta  = (const float*)d_in[9];
    const float* w1    = (const float*)d_in[10];
    const float* w2    = (const float*)d_in[11];
    const float* b2    = (const float*)d_in[12];
    float* out = (float*)d_out;

    static cudaStream_t s2 = nullptr;
    static cudaEvent_t evFork = nullptr, evJoin = nullptr, evJoin2 = nullptr;
    static bool init_done = false;
    const int smem_kn   = NSTAGE*STG_KN*4;   // 107520 B
    const int smem_h    = NSTAGE*STG_H*4;    // 110592 B
    const int smem_attn = DD*GTS_PITCH*2;    // 67584 B
    if (!init_done) {
        cudaFuncSetAttribute(k_xl,    cudaFuncAttributeMaxDynamicSharedMemorySize, smem_kn);
        cudaFuncSetAttribute(k_gemm1, cudaFuncAttributeMaxDynamicSharedMemorySize, smem_h);
        cudaFuncSetAttribute(k_gemm2, cudaFuncAttributeMaxDynamicSharedMemorySize, smem_h);
        cudaFuncSetAttribute(k_attn2, cudaFuncAttributeMaxDynamicSharedMemorySize, smem_attn);
        cudaStreamCreateWithFlags(&s2, cudaStreamNonBlocking);
        cudaEventCreateWithFlags(&evFork,  cudaEventDisableTiming);
        cudaEventCreateWithFlags(&evJoin,  cudaEventDisableTiming);
        cudaEventCreateWithFlags(&evJoin2, cudaEventDisableTiming);
        init_done = true;
    }

    const int OUT0 = BB*DD*HIDN;
    int tail = (out_size >= OUT0 + NN*DD) ? 1 : 0;
    int mode = (out_size >= OUT0 + NN*DD + NN*KTOP) ? 1 : 0;

    // fork: side stream runs attn's deps FIRST, then the late-needed work
    cudaEventRecord(evFork, 0);
    cudaStreamWaitEvent(s2, evFork, 0);

    k_norm   <<<NN, 128, 0, s2>>>(emb, aei, aej);
    k_costopk<<<NN, 256, 0, s2>>>(emb);
    cudaEventRecord(evJoin, s2);                  // attn deps ready

    k_cvtw<<<(HIDN*NN/4 + HIDN*HIDN/4)/256, 256, 0, s2>>>(w1, w2);
    if (tail) k_pack<<<(NN*DD + 255)/256, 256, 0, s2>>>(emb, out, mode);
    cudaEventRecord(evJoin2, s2);                 // gemm1 deps ready

    k_xl<<<dim3(4, BB), 256, smem_kn>>>(data, linw, ai, aj);

    cudaStreamWaitEvent(0, evJoin, 0);
    k_attn2<<<2*BB, 256, smem_attn>>>(emb, gbias, gamma, beta);

    cudaStreamWaitEvent(0, evJoin2, 0);
    k_gemm1<<<dim3(4, BB), 256, smem_h>>>();
    k_gemm2<<<dim3(4, BB), 256, smem_h>>>(b2, out);
}

// round 11
// speedup vs baseline: 1.2295x; 1.2295x over previous
#include <cuda_runtime.h>
#include <cuda_fp16.h>
#include <math.h>

#define BB   64
#define NN   512
#define FIN  256
#define DD   128
#define KTOP 20
#define HIDN 512

// ---- scratch (device globals; no allocations) ----
static __device__ __half d_xl16[BB*NN*DD];     // [b,n,d] lin(x), fp16
static __device__ __half d_gT16[BB*DD*NN];     // [b,d,n] gated GCN output (transposed), fp16
static __device__ __half d_o116[BB*DD*HIDN];   // [b,d,h] first linear, fp16
static __device__ __half d_w116[HIDN*NN];      // w1 fp16
static __device__ __half d_w216[HIDN*HIDN];    // w2 fp16
static __device__ float  d_p [BB*NN];
static __device__ float  d_q [BB*NN];
static __device__ float  d_rinv[NN];
static __device__ float  d_r [NN];
static __device__ float  d_s [NN];
static __device__ float  d_cosm[NN*NN];
static __device__ int    d_topk[NN*KTOP];

// ---------------- MMA / cp.async helpers ----------------
__device__ __forceinline__ void mma_tf32(float c[4],
        unsigned a0, unsigned a1, unsigned a2, unsigned a3,
        unsigned b0, unsigned b1) {
    asm volatile(
        "mma.sync.aligned.m16n8k8.row.col.f32.tf32.tf32.f32 "
        "{%0,%1,%2,%3}, {%4,%5,%6,%7}, {%8,%9}, {%0,%1,%2,%3};\n"
        : "+f"(c[0]), "+f"(c[1]), "+f"(c[2]), "+f"(c[3])
        : "r"(a0), "r"(a1), "r"(a2), "r"(a3), "r"(b0), "r"(b1));
}
__device__ __forceinline__ void mma_f16(float c[4],
        unsigned a0, unsigned a1, unsigned a2, unsigned a3,
        unsigned b0, unsigned b1) {
    asm volatile(
        "mma.sync.aligned.m16n8k16.row.col.f32.f16.f16.f32 "
        "{%0,%1,%2,%3}, {%4,%5,%6,%7}, {%8,%9}, {%0,%1,%2,%3};\n"
        : "+f"(c[0]), "+f"(c[1]), "+f"(c[2]), "+f"(c[3])
        : "r"(a0), "r"(a1), "r"(a2), "r"(a3), "r"(b0), "r"(b1));
}
__device__ __forceinline__ void cpa16(void* dst, const void* src) {
    unsigned ds = (unsigned)__cvta_generic_to_shared(dst);
    asm volatile("cp.async.cg.shared.global [%0], [%1], 16;" :: "r"(ds), "l"(src));
}
#define CP_COMMIT asm volatile("cp.async.commit_group;")
#define CP_WAIT1  asm volatile("cp.async.wait_group 1;")
#define CP_WAIT0  asm volatile("cp.async.wait_group 0;")
#define NSTAGE    3

// ---- tf32 k_xl geometry ----
#define A_KN_WORDS 4352          // [32 k][136]
#define B_KN_WORDS 4608          // [128][36]
#define STG_KN     (A_KN_WORDS + B_KN_WORDS)   // 8960 w

// ---- fp16 gemm geometry ----
#define HROW_W     36
#define H_OP_WORDS (128*HROW_W)                 // 4608 words per operand
#define STG_H      (2*H_OP_WORDS)               // 9216 words per stage

// tf32 chunk: A [k][136], B [m][36]
#define CHUNK_KN(pA, pB)                                                        \
    _Pragma("unroll")                                                            \
    for (int ks = 0; ks < 4; ks++) {                                             \
        int k8 = ks*8;                                                           \
        unsigned af[4][4], bf[4][2];                                             \
        _Pragma("unroll")                                                        \
        for (int mi = 0; mi < 4; mi++) {                                         \
            int r = wm + mi*16 + g;                                              \
            af[mi][0] = (pA)[(k8+t4  )*136 + r    ];                             \
            af[mi][1] = (pA)[(k8+t4  )*136 + r + 8];                             \
            af[mi][2] = (pA)[(k8+t4+4)*136 + r    ];                             \
            af[mi][3] = (pA)[(k8+t4+4)*136 + r + 8];                             \
        }                                                                        \
        _Pragma("unroll")                                                        \
        for (int ni = 0; ni < 4; ni++) {                                         \
            int rn = wn + ni*8 + g;                                              \
            bf[ni][0] = (pB)[rn*36 + k8+t4    ];                                 \
            bf[ni][1] = (pB)[rn*36 + k8+t4 + 4];                                 \
        }                                                                        \
        _Pragma("unroll")                                                        \
        for (int mi = 0; mi < 4; mi++)                                           \
            _Pragma("unroll")                                                    \
            for (int ni = 0; ni < 4; ni++)                                       \
                mma_tf32(c[mi][ni], af[mi][0], af[mi][1], af[mi][2],             \
                         af[mi][3], bf[ni][0], bf[ni][1]);                       \
    }

// fp16 chunk (K=64): A [m][36w], B [n][36w]
#define CHUNK_H(pA, pB)                                                         \
    _Pragma("unroll")                                                            \
    for (int ks = 0; ks < 4; ks++) {                                             \
        int kw = ks*8;                                                           \
        unsigned af[4][4], bf[4][2];                                             \
        _Pragma("unroll")                                                        \
        for (int mi = 0; mi < 4; mi++) {                                         \
            int r = wm + mi*16 + g;                                              \
            af[mi][0] = (pA)[(r    )*HROW_W + kw + t4    ];                      \
            af[mi][1] = (pA)[(r + 8)*HROW_W + kw + t4    ];                      \
            af[mi][2] = (pA)[(r    )*HROW_W + kw + t4 + 4];                      \
            af[mi][3] = (pA)[(r + 8)*HROW_W + kw + t4 + 4];                      \
        }                                                                        \
        _Pragma("unroll")                                                        \
        for (int ni = 0; ni < 4; ni++) {                                         \
            int rn = wn + ni*8 + g;                                              \
            bf[ni][0] = (pB)[rn*HROW_W + kw + t4    ];                           \
            bf[ni][1] = (pB)[rn*HROW_W + kw + t4 + 4];                           \
        }                                                                        \
        _Pragma("unroll")                                                        \
        for (int mi = 0; mi < 4; mi++)                                           \
            _Pragma("unroll")                                                    \
            for (int ni = 0; ni < 4; ni++)                                       \
                mma_f16(c[mi][ni], af[mi][0], af[mi][1], af[mi][2],              \
                        af[mi][3], bf[ni][0], bf[ni][1]);                        \
    }

// ---------------------------------------------------------------
// K0: per-node norms + emb dot att_em
// ---------------------------------------------------------------
__global__ void k_norm(const float* __restrict__ emb,
                       const float* __restrict__ aei,
                       const float* __restrict__ aej) {
    int n = blockIdx.x, t = threadIdx.x;
    float w  = emb[n*DD + t];
    float v0 = w*w, v1 = w*aei[t], v2 = w*aej[t];
    #pragma unroll
    for (int o = 16; o; o >>= 1) {
        v0 += __shfl_xor_sync(0xffffffffu, v0, o);
        v1 += __shfl_xor_sync(0xffffffffu, v1, o);
        v2 += __shfl_xor_sync(0xffffffffu, v2, o);
    }
    __shared__ float s0[4], s1[4], s2[4];
    int wid = t >> 5, lane = t & 31;
    if (lane == 0) { s0[wid]=v0; s1[wid]=v1; s2[wid]=v2; }
    __syncthreads();
    if (t == 0) {
        d_rinv[n] = rsqrtf(s0[0]+s0[1]+s0[2]+s0[3]);
        d_r[n] = s1[0]+s1[1]+s1[2]+s1[3];
        d_s[n] = s2[0]+s2[1]+s2[2]+s2[3];
    }
}

// ---------------------------------------------------------------
// K1: cosine matrix — PROVEN round-9 tiled form (smem reuse,
//     minimal L2 traffic; must not contend with k_xl).
// ---------------------------------------------------------------
__global__ void k_cos(const float* __restrict__ emb) {
    __shared__ float sAt[32][68];
    __shared__ float sBt[32][68];
    int i0 = blockIdx.y * 64, j0 = blockIdx.x * 64;
    int tid = threadIdx.x;
    int tx = tid & 15, ty = tid >> 4;
    float c[4][4] = {};
    for (int k0 = 0; k0 < DD; k0 += 32) {
        #pragma unroll
        for (int a = 0; a < 8; a++) {
            int idx = tid + a*256;
            int row = idx >> 5, kk = idx & 31;
            sAt[kk][row] = emb[(i0+row)*DD + k0 + kk];
            sBt[kk][row] = emb[(j0+row)*DD + k0 + kk];
        }
        __syncthreads();
        #pragma unroll
        for (int kk = 0; kk < 32; kk++) {
            float av[4], bv[4];
            *(float4*)av = *(const float4*)&sAt[kk][ty*4];
            *(float4*)bv = *(const float4*)&sBt[kk][tx*4];
            #pragma unroll
            for (int ii = 0; ii < 4; ii++)
                #pragma unroll
                for (int jj = 0; jj < 4; jj++)
                    c[ii][jj] += av[ii]*bv[jj];
        }
        __syncthreads();
    }
    float rj[4];
    #pragma unroll
    for (int jj = 0; jj < 4; jj++) rj[jj] = d_rinv[j0 + tx*4 + jj];
    #pragma unroll
    for (int ii = 0; ii < 4; ii++) {
        float ri = d_rinv[i0 + ty*4 + ii];
        float4 v;
        v.x = c[ii][0]*ri*rj[0]; v.y = c[ii][1]*ri*rj[1];
        v.z = c[ii][2]*ri*rj[2]; v.w = c[ii][3]*ri*rj[3];
        *(float4*)&d_cosm[(i0 + ty*4 + ii)*NN + j0 + tx*4] = v;
    }
}

// ---------------------------------------------------------------
// K2: top-20 per row — PROVEN round-9 warp-register form
// ---------------------------------------------------------------
__global__ void k_topk() {
    int row  = (blockIdx.x*256 + threadIdx.x) >> 5;
    int lane = threadIdx.x & 31;
    float v[16];
    #pragma unroll
    for (int j = 0; j < 16; j++) v[j] = d_cosm[row*NN + lane + 32*j];
    for (int t = 0; t < KTOP; t++) {
        float bv = v[0]; int bj = 0;
        #pragma unroll
        for (int j = 1; j < 16; j++)
            if (v[j] > bv) { bv = v[j]; bj = j; }
        int bidx = lane + 32*bj;
        #pragma unroll
        for (int o = 16; o; o >>= 1) {
            float ov = __shfl_xor_sync(0xffffffffu, bv, o);
            int   oi = __shfl_xor_sync(0xffffffffu, bidx, o);
            if (ov > bv || (ov == bv && oi < bidx)) { bv = ov; bidx = oi; }
        }
        if (lane == 0) d_topk[row*KTOP + t] = bidx;
        #pragma unroll
        for (int j = 0; j < 16; j++)
            if (lane + 32*j == bidx) v[j] = -INFINITY;
    }
}

// ---------------------------------------------------------------
// K_cvtw: both weight converts in one launch. Destinations are
// __device__ globals referenced from device code only.
// ---------------------------------------------------------------
__global__ void k_cvtw(const float* __restrict__ w1, const float* __restrict__ w2) {
    int idx = blockIdx.x*256 + threadIdx.x;
    const int N1 = HIDN*NN/4;
    if (idx < N1) {
        float4 v = *(const float4*)(w1 + (size_t)idx*4);
        __half2* d2 = (__half2*)(d_w116 + (size_t)idx*4);
        d2[0] = __floats2half2_rn(v.x, v.y);
        d2[1] = __floats2half2_rn(v.z, v.w);
    } else {
        int j = idx - N1;
        float4 v = *(const float4*)(w2 + (size_t)j*4);
        __half2* d2 = (__half2*)(d_w216 + (size_t)j*4);
        d2[0] = __floats2half2_rn(v.x, v.y);
        d2[1] = __floats2half2_rn(v.z, v.w);
    }
}

// ---------------------------------------------------------------
// K3: xl (tf32 MMA, 3-stage) + fused p/q epilogue.
// ---------------------------------------------------------------
__global__ void __launch_bounds__(256, 2) k_xl(const float* __restrict__ data,
                                               const float* __restrict__ linw,
                                               const float* __restrict__ ai,
                                               const float* __restrict__ aj) {
    extern __shared__ unsigned smu[];
    __shared__ float spq[DD][2];
    int b = blockIdx.y, n0 = blockIdx.x * 128;
    int tid = threadIdx.x;
    int w = tid >> 5, lane = tid & 31;
    int g = lane >> 2, t4 = lane & 3;
    int wm = (w & 1) * 64, wn = (w >> 1) * 32;
    if (tid < DD) { spq[tid][0] = 0.f; spq[tid][1] = 0.f; }
    float c[4][4][4] = {};

    #define XL_LOAD(st, f0)                                                      \
        {                                                                        \
            unsigned* pA = smu + (st)*STG_KN;                                    \
            unsigned* pB = pA + A_KN_WORDS;                                      \
            _Pragma("unroll")                                                    \
            for (int a = 0; a < 4; a++) {                                        \
                int idx = tid + a*256;                                           \
                int kk = idx >> 5, n4 = idx & 31;                                \
                cpa16(pA + kk*136 + n4*4,                                        \
                      data + ((size_t)b*FIN + (f0) + kk)*NN + n0 + n4*4);        \
            }                                                                    \
            _Pragma("unroll")                                                    \
            for (int a = 0; a < 4; a++) {                                        \
                int idx = tid + a*256;                                           \
                int dd = idx >> 3, k4 = idx & 7;                                 \
                cpa16(pB + dd*36 + k4*4, linw + dd*FIN + (f0) + k4*4);           \
            }                                                                    \
        }

    XL_LOAD(0, 0) CP_COMMIT;
    XL_LOAD(1, 32) CP_COMMIT;
    #pragma unroll 1
    for (int it = 0; it < FIN/32; it++) {
        if (it + 1 < FIN/32) { CP_WAIT1; } else { CP_WAIT0; }
        __syncthreads();
        if (it + 2 < FIN/32) { XL_LOAD((it+2)%NSTAGE, (it+2)*32) CP_COMMIT; }
        unsigned* pA = smu + (it%NSTAGE)*STG_KN;
        unsigned* pB = pA + A_KN_WORDS;
        CHUNK_KN(pA, pB)
    }
    #undef XL_LOAD

    float pv[8] = {}, qv[8] = {};
    #pragma unroll
    for (int mi = 0; mi < 4; mi++)
        #pragma unroll
        for (int ni = 0; ni < 4; ni++) {
            int row = n0 + wm + mi*16 + g, col = wn + ni*8 + t4*2;
            size_t i0 = ((size_t)b*NN + row    )*DD + col;
            size_t i1 = ((size_t)b*NN + row + 8)*DD + col;
            *(__half2*)&d_xl16[i0] = __floats2half2_rn(c[mi][ni][0], c[mi][ni][1]);
            *(__half2*)&d_xl16[i1] = __floats2half2_rn(c[mi][ni][2], c[mi][ni][3]);
            float a0 = ai[col], a1 = ai[col+1];
            float j0 = aj[col], j1 = aj[col+1];
            pv[mi*2  ] += c[mi][ni][0]*a0 + c[mi][ni][1]*a1;
            pv[mi*2+1] += c[mi][ni][2]*a0 + c[mi][ni][3]*a1;
            qv[mi*2  ] += c[mi][ni][0]*j0 + c[mi][ni][1]*j1;
            qv[mi*2+1] += c[mi][ni][2]*j0 + c[mi][ni][3]*j1;
        }
    #pragma unroll
    for (int r = 0; r < 8; r++) {
        pv[r] += __shfl_xor_sync(0xffffffffu, pv[r], 1);
        pv[r] += __shfl_xor_sync(0xffffffffu, pv[r], 2);
        qv[r] += __shfl_xor_sync(0xffffffffu, qv[r], 1);
        qv[r] += __shfl_xor_sync(0xffffffffu, qv[r], 2);
    }
    if (t4 == 0) {
        #pragma unroll
        for (int mi = 0; mi < 4; mi++) {
            int r0 = wm + mi*16 + g;
            atomicAdd(&spq[r0][0],   pv[mi*2]);
            atomicAdd(&spq[r0][1],   qv[mi*2]);
            atomicAdd(&spq[r0+8][0], pv[mi*2+1]);
            atomicAdd(&spq[r0+8][1], qv[mi*2+1]);
        }
    }
    __syncthreads();
    if (tid < 2*DD) {
        int row = tid >> 1, which = tid & 1;
        float v = spq[row][which];
        if (which == 0) d_p[b*NN + n0 + row] = v;
        else            d_q[b*NN + n0 + row] = v;
    }
}

// ---------------------------------------------------------------
// K5: attention softmax + aggregate (fp16 gather) + BN/ReLU/gate,
//     emit gT[b][d][n] via smem staging.
// ---------------------------------------------------------------
#define GTS_PITCH 264
__global__ void __launch_bounds__(256, 1) k_attn2(const float* __restrict__ emb,
                                                  const float* __restrict__ gbias,
                                                  const float* __restrict__ gamma,
                                                  const float* __restrict__ beta) {
    extern __shared__ __half gts[];    // [128][GTS_PITCH] = 67584 B
    int b = blockIdx.x >> 1, nhalf = blockIdx.x & 1;
    int n0 = nhalf * 256;
    int tid = threadIdx.x, wrp = tid >> 5, lane = tid & 31;

    const float inv = rsqrtf(1.0f + 1e-5f);
    for (int i = 0; i < 32; i++) {
        int n = n0 + wrp*32 + i;
        int widx = b*NN + n;
        int src_k = 0; float alpha = -1e30f;
        if (lane < KTOP) {
            src_k = d_topk[n*KTOP + lane];
            alpha = d_p[widx] + d_r[n] + d_q[b*NN + src_k] + d_s[src_k];
            alpha = alpha > 0.f ? alpha : 0.2f*alpha;
        }
        float m = alpha;
        #pragma unroll
        for (int o = 16; o; o >>= 1) m = fmaxf(m, __shfl_xor_sync(0xffffffffu, m, o));
        float ex = (lane < KTOP) ? expf(alpha - m) : 0.f;
        float sm = ex;
        #pragma unroll
        for (int o = 16; o; o >>= 1) sm += __shfl_xor_sync(0xffffffffu, sm, o);
        float aw = ex / sm;

        float2 acc0 = {0.f,0.f}, acc1 = {0.f,0.f};
        #pragma unroll
        for (int k = 0; k < KTOP; k++) {
            int   sk = __shfl_sync(0xffffffffu, src_k, k);
            float ak = __shfl_sync(0xffffffffu, aw,  k);
            const __half2* xr = (const __half2*)(d_xl16 + ((size_t)b*NN + sk)*DD);
            float2 f0 = __half22float2(xr[lane]);
            float2 f1 = __half22float2(xr[lane + 32]);
            acc0.x += ak*f0.x; acc0.y += ak*f0.y;
            acc1.x += ak*f1.x; acc1.y += ak*f1.y;
        }
        int d0 = 2*lane, d1 = 2*lane + 64;
        float h0 = fmaxf((acc0.x + gbias[d0  ])*(gamma[d0  ]*inv) + beta[d0  ], 0.f) * emb[n*DD + d0];
        float h1 = fmaxf((acc0.y + gbias[d0+1])*(gamma[d0+1]*inv) + beta[d0+1], 0.f) * emb[n*DD + d0+1];
        float h2 = fmaxf((acc1.x + gbias[d1  ])*(gamma[d1  ]*inv) + beta[d1  ], 0.f) * emb[n*DD + d1];
        float h3 = fmaxf((acc1.y + gbias[d1+1])*(gamma[d1+1]*inv) + beta[d1+1], 0.f) * emb[n*DD + d1+1];
        int nn = n - n0;
        gts[(d0  )*GTS_PITCH + nn] = __float2half(h0);
        gts[(d0+1)*GTS_PITCH + nn] = __float2half(h1);
        gts[(d1  )*GTS_PITCH + nn] = __float2half(h2);
        gts[(d1+1)*GTS_PITCH + nn] = __float2half(h3);
    }
    __syncthreads();
    for (int row = wrp; row < DD; row += 8) {
        *(uint4*)(d_gT16 + ((size_t)b*DD + row)*NN + n0 + lane*8) =
            *(uint4*)(gts + row*GTS_PITCH + lane*8);
    }
}

// ---------------------------------------------------------------
// K6 (fp16 MMA): o1[b,d,h] = sum_n gT[b,d,n] * w1[h,n]
// ---------------------------------------------------------------
__global__ void __launch_bounds__(256, 2) k_gemm1() {
    extern __shared__ unsigned smu[];
    int b = blockIdx.y, h0 = blockIdx.x * 128;
    int tid = threadIdx.x;
    int w = tid >> 5, lane = tid & 31;
    int g = lane >> 2, t4 = lane & 3;
    int wm = (w & 1) * 64, wn = (w >> 1) * 32;
    float c[4][4][4] = {};

    #define G1_LOAD(st, k0)                                                      \
        {                                                                        \
            unsigned* pA = smu + (st)*STG_H;                                     \
            unsigned* pB = pA + H_OP_WORDS;                                      \
            _Pragma("unroll")                                                    \
            for (int a = 0; a < 4; a++) {                                        \
                int idx = tid + a*256;                                           \
                int row = idx >> 3, seg = idx & 7;                               \
                cpa16(pA + row*HROW_W + seg*4,                                   \
                      d_gT16 + ((size_t)b*DD + row)*NN + (k0) + seg*8);          \
            }                                                                    \
            _Pragma("unroll")                                                    \
            for (int a = 0; a < 4; a++) {                                        \
                int idx = tid + a*256;                                           \
                int row = idx >> 3, seg = idx & 7;                               \
                cpa16(pB + row*HROW_W + seg*4,                                   \
                      d_w116 + (size_t)(h0 + row)*NN + (k0) + seg*8);            \
            }                                                                    \
        }

    G1_LOAD(0, 0) CP_COMMIT;
    G1_LOAD(1, 64) CP_COMMIT;
    #pragma unroll 1
    for (int it = 0; it < NN/64; it++) {
        if (it + 1 < NN/64) { CP_WAIT1; } else { CP_WAIT0; }
        __syncthreads();
        if (it + 2 < NN/64) { G1_LOAD((it+2)%NSTAGE, (it+2)*64) CP_COMMIT; }
        unsigned* pA = smu + (it%NSTAGE)*STG_H;
        unsigned* pB = pA + H_OP_WORDS;
        CHUNK_H(pA, pB)
    }
    #undef G1_LOAD
    #pragma unroll
    for (int mi = 0; mi < 4; mi++)
        #pragma unroll
        for (int ni = 0; ni < 4; ni++) {
            int row = wm + mi*16 + g, col = h0 + wn + ni*8 + t4*2;
            *(__half2*)&d_o116[((size_t)b*DD + row    )*HIDN + col] =
                __floats2half2_rn(c[mi][ni][0], c[mi][ni][1]);
            *(__half2*)&d_o116[((size_t)b*DD + row + 8)*HIDN + col] =
                __floats2half2_rn(c[mi][ni][2], c[mi][ni][3]);
        }
}

// ---------------------------------------------------------------
// K7 (fp16 MMA): out[b,d,h2] = sigmoid(sum_h o1[b,d,h]*w2[h2,h] + b2)
// ---------------------------------------------------------------
__global__ void __launch_bounds__(256, 2) k_gemm2(const float* __restrict__ b2,
                                                  float* __restrict__ out) {
    extern __shared__ unsigned smu[];
    int b = blockIdx.y, h20 = blockIdx.x * 128;
    int tid = threadIdx.x;
    int w = tid >> 5, lane = tid & 31;
    int g = lane >> 2, t4 = lane & 3;
    int wm = (w & 1) * 64, wn = (w >> 1) * 32;
    float c[4][4][4] = {};

    #define G2_LOAD(st, k0)                                                      \
        {                                                                        \
            unsigned* pA = smu + (st)*STG_H;                                     \
            unsigned* pB = pA + H_OP_WORDS;                                      \
            _Pragma("unroll")                                                    \
            for (int a = 0; a < 4; a++) {                                        \
                int idx = tid + a*256;                                           \
                int row = idx >> 3, seg = idx & 7;                               \
                cpa16(pA + row*HROW_W + seg*4,                                   \
                      d_o116 + ((size_t)b*DD + row)*HIDN + (k0) + seg*8);        \
            }                                                                    \
            _Pragma("unroll")                                                    \
            for (int a = 0; a < 4; a++) {                                        \
                int idx = tid + a*256;                                           \
                int row = idx >> 3, seg = idx & 7;                               \
                cpa16(pB + row*HROW_W + seg*4,                                   \
                      d_w216 + (size_t)(h20 + row)*HIDN + (k0) + seg*8);         \
            }                                                                    \
        }

    G2_LOAD(0, 0) CP_COMMIT;
    G2_LOAD(1, 64) CP_COMMIT;
    #pragma unroll 1
    for (int it = 0; it < HIDN/64; it++) {
        if (it + 1 < HIDN/64) { CP_WAIT1; } else { CP_WAIT0; }
        __syncthreads();
        if (it + 2 < HIDN/64) { G2_LOAD((it+2)%NSTAGE, (it+2)*64) CP_COMMIT; }
        unsigned* pA = smu + (it%NSTAGE)*STG_H;
        unsigned* pB = pA + H_OP_WORDS;
        CHUNK_H(pA, pB)
    }
    #undef G2_LOAD
    #pragma unroll
    for (int mi = 0; mi < 4; mi++)
        #pragma unroll
        for (int ni = 0; ni < 4; ni++) {
            int row = wm + mi*16 + g, col = h20 + wn + ni*8 + t4*2;
            float bb0 = b2[col], bb1 = b2[col + 1];
            float2 v0, v1;
            v0.x = 1.0f/(1.0f + expf(-(c[mi][ni][0] + bb0)));
            v0.y = 1.0f/(1.0f + expf(-(c[mi][ni][1] + bb1)));
            v1.x = 1.0f/(1.0f + expf(-(c[mi][ni][2] + bb0)));
            v1.y = 1.0f/(1.0f + expf(-(c[mi][ni][3] + bb1)));
            *(float2*)&out[((size_t)b*DD + row    )*HIDN + col] = v0;
            *(float2*)&out[((size_t)b*DD + row + 8)*HIDN + col] = v1;
        }
}

// ---------------------------------------------------------------
// K8: pack trailing outputs (emb_weight copy, topk_idx as float)
// ---------------------------------------------------------------
__global__ void k_pack(const float* __restrict__ emb, float* __restrict__ out, int mode) {
    int i = blockIdx.x*256 + threadIdx.x;
    const int OUT0 = BB*DD*HIDN;
    if (i < NN*DD) out[OUT0 + i] = emb[i];
    if (mode && i < NN*KTOP) out[OUT0 + NN*DD + i] = (float)d_topk[i];
}

extern "C" void kernel_launch(void* const* d_in, const int* in_sizes, int n_in,
                              void* d_out, int out_size) {
    const float* data  = (const float*)d_in[0];
    const float* emb   = (const float*)d_in[1];
    const float* linw  = (const float*)d_in[2];
    const float* ai    = (const float*)d_in[3];
    const float* aj    = (const float*)d_in[4];
    const float* aei   = (const float*)d_in[5];
    const float* aej   = (const float*)d_in[6];
    const float* gbias = (const float*)d_in[7];
    const float* gamma = (const float*)d_in[8];
    const float* beta  = (const float*)d_in[9];
    const float* w1    = (const float*)d_in[10];
    const float* w2    = (const float*)d_in[11];
    const float* b2    = (const float*)d_in[12];
    float* out = (float*)d_out;

    static cudaStream_t s2 = nullptr;
    static cudaEvent_t evFork = nullptr, evJoin = nullptr, evJoin2 = nullptr;
    static bool init_done = false;
    const int smem_kn   = NSTAGE*STG_KN*4;   // 107520 B
    const int smem_h    = NSTAGE*STG_H*4;    // 110592 B
    const int smem_attn = DD*GTS_PITCH*2;    // 67584 B
    if (!init_done) {
        cudaFuncSetAttribute(k_xl,    cudaFuncAttributeMaxDynamicSharedMemorySize, smem_kn);
        cudaFuncSetAttribute(k_gemm1, cudaFuncAttributeMaxDynamicSharedMemorySize, smem_h);
        cudaFuncSetAttribute(k_gemm2, cudaFuncAttributeMaxDynamicSharedMemorySize, smem_h);
        cudaFuncSetAttribute(k_attn2, cudaFuncAttributeMaxDynamicSharedMemorySize, smem_attn);
        cudaStreamCreateWithFlags(&s2, cudaStreamNonBlocking);
        cudaEventCreateWithFlags(&evFork,  cudaEventDisableTiming);
        cudaEventCreateWithFlags(&evJoin,  cudaEventDisableTiming);
        cudaEventCreateWithFlags(&evJoin2, cudaEventDisableTiming);
        init_done = true;
    }

    const int OUT0 = BB*DD*HIDN;
    int tail = (out_size >= OUT0 + NN*DD) ? 1 : 0;
    int mode = (out_size >= OUT0 + NN*DD + NN*KTOP) ? 1 : 0;

    // fork: side stream runs attn's deps FIRST (proven tiled kernels),
    // then the late-needed weight converts + pack.
    cudaEventRecord(evFork, 0);
    cudaStreamWaitEvent(s2, evFork, 0);

    k_norm<<<NN, 128, 0, s2>>>(emb, aei, aej);
    k_cos <<<dim3(8, 8), 256, 0, s2>>>(emb);
    k_topk<<<NN/8, 256, 0, s2>>>();
    cudaEventRecord(evJoin, s2);                  // attn deps ready

    k_cvtw<<<(HIDN*NN/4 + HIDN*HIDN/4)/256, 256, 0, s2>>>(w1, w2);
    if (tail) k_pack<<<(NN*DD + 255)/256, 256, 0, s2>>>(emb, out, mode);
    cudaEventRecord(evJoin2, s2);                 // gemm1 deps ready

    k_xl<<<dim3(4, BB), 256, smem_kn>>>(data, linw, ai, aj);

    cudaStreamWaitEvent(0, evJoin, 0);
    k_attn2<<<2*BB, 256, smem_attn>>>(emb, gbias, gamma, beta);

    cudaStreamWaitEvent(0, evJoin2, 0);
    k_gemm1<<<dim3(4, BB), 256, smem_h>>>();
    k_gemm2<<<dim3(4, BB), 256, smem_h>>>(b2, out);
}

// round 12
// speedup vs baseline: 1.3235x; 1.0765x over previous
#include <cuda_runtime.h>
#include <cuda_fp16.h>
#include <math.h>

#define BB   64
#define NN   512
#define FIN  256
#define DD   128
#define KTOP 20
#define HIDN 512

// ---- scratch (device globals; no allocations) ----
static __device__ __half d_xl16[BB*NN*DD];     // [b,n,d] lin(x), fp16
static __device__ __half d_gT16[BB*DD*NN];     // [b,d,n] gated GCN output (transposed), fp16
static __device__ __half d_o116[BB*DD*HIDN];   // [b,d,h] first linear, fp16
static __device__ __half d_w116[HIDN*NN];      // w1 fp16
static __device__ __half d_w216[HIDN*HIDN];    // w2 fp16
static __device__ float  d_p [BB*NN];
static __device__ float  d_q [BB*NN];
static __device__ float  d_rinv[NN];
static __device__ float  d_r [NN];
static __device__ float  d_s [NN];
static __device__ float  d_cosm[NN*NN];
static __device__ int    d_topk[NN*KTOP];

// ---------------- MMA / cp.async helpers ----------------
__device__ __forceinline__ void mma_tf32(float c[4],
        unsigned a0, unsigned a1, unsigned a2, unsigned a3,
        unsigned b0, unsigned b1) {
    asm volatile(
        "mma.sync.aligned.m16n8k8.row.col.f32.tf32.tf32.f32 "
        "{%0,%1,%2,%3}, {%4,%5,%6,%7}, {%8,%9}, {%0,%1,%2,%3};\n"
        : "+f"(c[0]), "+f"(c[1]), "+f"(c[2]), "+f"(c[3])
        : "r"(a0), "r"(a1), "r"(a2), "r"(a3), "r"(b0), "r"(b1));
}
__device__ __forceinline__ void mma_f16(float c[4],
        unsigned a0, unsigned a1, unsigned a2, unsigned a3,
        unsigned b0, unsigned b1) {
    asm volatile(
        "mma.sync.aligned.m16n8k16.row.col.f32.f16.f16.f32 "
        "{%0,%1,%2,%3}, {%4,%5,%6,%7}, {%8,%9}, {%0,%1,%2,%3};\n"
        : "+f"(c[0]), "+f"(c[1]), "+f"(c[2]), "+f"(c[3])
        : "r"(a0), "r"(a1), "r"(a2), "r"(a3), "r"(b0), "r"(b1));
}
__device__ __forceinline__ void cpa16(void* dst, const void* src) {
    unsigned ds = (unsigned)__cvta_generic_to_shared(dst);
    asm volatile("cp.async.cg.shared.global [%0], [%1], 16;" :: "r"(ds), "l"(src));
}
#define CP_COMMIT asm volatile("cp.async.commit_group;")
#define CP_WAIT1  asm volatile("cp.async.wait_group 1;")
#define CP_WAIT0  asm volatile("cp.async.wait_group 0;")
#define NSTAGE    3

// ---- tf32 k_xl geometry ----
#define A_KN_WORDS 4352          // [32 k][136]
#define B_KN_WORDS 4608          // [128][36]
#define STG_KN     (A_KN_WORDS + B_KN_WORDS)   // 8960 w

// ---- fp16 gemm geometry ----
#define HROW_W     36
#define H_OP_WORDS (128*HROW_W)                 // 4608 words per operand
#define STG_H      (2*H_OP_WORDS)               // 9216 words per stage

// tf32 chunk: A [k][136], B [m][36]
#define CHUNK_KN(pA, pB)                                                        \
    _Pragma("unroll")                                                            \
    for (int ks = 0; ks < 4; ks++) {                                             \
        int k8 = ks*8;                                                           \
        unsigned af[4][4], bf[4][2];                                             \
        _Pragma("unroll")                                                        \
        for (int mi = 0; mi < 4; mi++) {                                         \
            int r = wm + mi*16 + g;                                              \
            af[mi][0] = (pA)[(k8+t4  )*136 + r    ];                             \
            af[mi][1] = (pA)[(k8+t4  )*136 + r + 8];                             \
            af[mi][2] = (pA)[(k8+t4+4)*136 + r    ];                             \
            af[mi][3] = (pA)[(k8+t4+4)*136 + r + 8];                             \
        }                                                                        \
        _Pragma("unroll")                                                        \
        for (int ni = 0; ni < 4; ni++) {                                         \
            int rn = wn + ni*8 + g;                                              \
            bf[ni][0] = (pB)[rn*36 + k8+t4    ];                                 \
            bf[ni][1] = (pB)[rn*36 + k8+t4 + 4];                                 \
        }                                                                        \
        _Pragma("unroll")                                                        \
        for (int mi = 0; mi < 4; mi++)                                           \
            _Pragma("unroll")                                                    \
            for (int ni = 0; ni < 4; ni++)                                       \
                mma_tf32(c[mi][ni], af[mi][0], af[mi][1], af[mi][2],             \
                         af[mi][3], bf[ni][0], bf[ni][1]);                       \
    }

// fp16 chunk (K=64): A [m][36w], B [n][36w]
#define CHUNK_H(pA, pB)                                                         \
    _Pragma("unroll")                                                            \
    for (int ks = 0; ks < 4; ks++) {                                             \
        int kw = ks*8;                                                           \
        unsigned af[4][4], bf[4][2];                                             \
        _Pragma("unroll")                                                        \
        for (int mi = 0; mi < 4; mi++) {                                         \
            int r = wm + mi*16 + g;                                              \
            af[mi][0] = (pA)[(r    )*HROW_W + kw + t4    ];                      \
            af[mi][1] = (pA)[(r + 8)*HROW_W + kw + t4    ];                      \
            af[mi][2] = (pA)[(r    )*HROW_W + kw + t4 + 4];                      \
            af[mi][3] = (pA)[(r + 8)*HROW_W + kw + t4 + 4];                      \
        }                                                                        \
        _Pragma("unroll")                                                        \
        for (int ni = 0; ni < 4; ni++) {                                         \
            int rn = wn + ni*8 + g;                                              \
            bf[ni][0] = (pB)[rn*HROW_W + kw + t4    ];                           \
            bf[ni][1] = (pB)[rn*HROW_W + kw + t4 + 4];                           \
        }                                                                        \
        _Pragma("unroll")                                                        \
        for (int mi = 0; mi < 4; mi++)                                           \
            _Pragma("unroll")                                                    \
            for (int ni = 0; ni < 4; ni++)                                       \
                mma_f16(c[mi][ni], af[mi][0], af[mi][1], af[mi][2],              \
                        af[mi][3], bf[ni][0], bf[ni][1]);                        \
    }

// ---------------------------------------------------------------
// K0: per-node norms + emb dot att_em
// ---------------------------------------------------------------
__global__ void k_norm(const float* __restrict__ emb,
                       const float* __restrict__ aei,
                       const float* __restrict__ aej) {
    int n = blockIdx.x, t = threadIdx.x;
    float w  = emb[n*DD + t];
    float v0 = w*w, v1 = w*aei[t], v2 = w*aej[t];
    #pragma unroll
    for (int o = 16; o; o >>= 1) {
        v0 += __shfl_xor_sync(0xffffffffu, v0, o);
        v1 += __shfl_xor_sync(0xffffffffu, v1, o);
        v2 += __shfl_xor_sync(0xffffffffu, v2, o);
    }
    __shared__ float s0[4], s1[4], s2[4];
    int wid = t >> 5, lane = t & 31;
    if (lane == 0) { s0[wid]=v0; s1[wid]=v1; s2[wid]=v2; }
    __syncthreads();
    if (t == 0) {
        d_rinv[n] = rsqrtf(s0[0]+s0[1]+s0[2]+s0[3]);
        d_r[n] = s1[0]+s1[1]+s1[2]+s1[3];
        d_s[n] = s2[0]+s2[1]+s2[2]+s2[3];
    }
}

// ---------------------------------------------------------------
// K1: cosine matrix — proven tiled form
// ---------------------------------------------------------------
__global__ void k_cos(const float* __restrict__ emb) {
    __shared__ float sAt[32][68];
    __shared__ float sBt[32][68];
    int i0 = blockIdx.y * 64, j0 = blockIdx.x * 64;
    int tid = threadIdx.x;
    int tx = tid & 15, ty = tid >> 4;
    float c[4][4] = {};
    for (int k0 = 0; k0 < DD; k0 += 32) {
        #pragma unroll
        for (int a = 0; a < 8; a++) {
            int idx = tid + a*256;
            int row = idx >> 5, kk = idx & 31;
            sAt[kk][row] = emb[(i0+row)*DD + k0 + kk];
            sBt[kk][row] = emb[(j0+row)*DD + k0 + kk];
        }
        __syncthreads();
        #pragma unroll
        for (int kk = 0; kk < 32; kk++) {
            float av[4], bv[4];
            *(float4*)av = *(const float4*)&sAt[kk][ty*4];
            *(float4*)bv = *(const float4*)&sBt[kk][tx*4];
            #pragma unroll
            for (int ii = 0; ii < 4; ii++)
                #pragma unroll
                for (int jj = 0; jj < 4; jj++)
                    c[ii][jj] += av[ii]*bv[jj];
        }
        __syncthreads();
    }
    float rj[4];
    #pragma unroll
    for (int jj = 0; jj < 4; jj++) rj[jj] = d_rinv[j0 + tx*4 + jj];
    #pragma unroll
    for (int ii = 0; ii < 4; ii++) {
        float ri = d_rinv[i0 + ty*4 + ii];
        float4 v;
        v.x = c[ii][0]*ri*rj[0]; v.y = c[ii][1]*ri*rj[1];
        v.z = c[ii][2]*ri*rj[2]; v.w = c[ii][3]*ri*rj[3];
        *(float4*)&d_cosm[(i0 + ty*4 + ii)*NN + j0 + tx*4] = v;
    }
}

// ---------------------------------------------------------------
// K2: top-20 per row — proven warp-register form
// ---------------------------------------------------------------
__global__ void k_topk() {
    int row  = (blockIdx.x*256 + threadIdx.x) >> 5;
    int lane = threadIdx.x & 31;
    float v[16];
    #pragma unroll
    for (int j = 0; j < 16; j++) v[j] = d_cosm[row*NN + lane + 32*j];
    for (int t = 0; t < KTOP; t++) {
        float bv = v[0]; int bj = 0;
        #pragma unroll
        for (int j = 1; j < 16; j++)
            if (v[j] > bv) { bv = v[j]; bj = j; }
        int bidx = lane + 32*bj;
        #pragma unroll
        for (int o = 16; o; o >>= 1) {
            float ov = __shfl_xor_sync(0xffffffffu, bv, o);
            int   oi = __shfl_xor_sync(0xffffffffu, bidx, o);
            if (ov > bv || (ov == bv && oi < bidx)) { bv = ov; bidx = oi; }
        }
        if (lane == 0) d_topk[row*KTOP + t] = bidx;
        #pragma unroll
        for (int j = 0; j < 16; j++)
            if (lane + 32*j == bidx) v[j] = -INFINITY;
    }
}

// ---------------------------------------------------------------
// K_cvtw: both weight converts in one launch (device-global dests).
// ---------------------------------------------------------------
__global__ void k_cvtw(const float* __restrict__ w1, const float* __restrict__ w2) {
    int idx = blockIdx.x*256 + threadIdx.x;
    const int N1 = HIDN*NN/4;
    if (idx < N1) {
        float4 v = *(const float4*)(w1 + (size_t)idx*4);
        __half2* d2 = (__half2*)(d_w116 + (size_t)idx*4);
        d2[0] = __floats2half2_rn(v.x, v.y);
        d2[1] = __floats2half2_rn(v.z, v.w);
    } else {
        int j = idx - N1;
        float4 v = *(const float4*)(w2 + (size_t)j*4);
        __half2* d2 = (__half2*)(d_w216 + (size_t)j*4);
        d2[0] = __floats2half2_rn(v.x, v.y);
        d2[1] = __floats2half2_rn(v.z, v.w);
    }
}

// ---------------------------------------------------------------
// K3: xl (tf32 MMA, 3-stage) + fused p/q epilogue.
// ---------------------------------------------------------------
__global__ void __launch_bounds__(256, 2) k_xl(const float* __restrict__ data,
                                               const float* __restrict__ linw,
                                               const float* __restrict__ ai,
                                               const float* __restrict__ aj) {
    extern __shared__ unsigned smu[];
    __shared__ float spq[DD][2];
    int b = blockIdx.y, n0 = blockIdx.x * 128;
    int tid = threadIdx.x;
    int w = tid >> 5, lane = tid & 31;
    int g = lane >> 2, t4 = lane & 3;
    int wm = (w & 1) * 64, wn = (w >> 1) * 32;
    if (tid < DD) { spq[tid][0] = 0.f; spq[tid][1] = 0.f; }
    float c[4][4][4] = {};

    #define XL_LOAD(st, f0)                                                      \
        {                                                                        \
            unsigned* pA = smu + (st)*STG_KN;                                    \
            unsigned* pB = pA + A_KN_WORDS;                                      \
            _Pragma("unroll")                                                    \
            for (int a = 0; a < 4; a++) {                                        \
                int idx = tid + a*256;                                           \
                int kk = idx >> 5, n4 = idx & 31;                                \
                cpa16(pA + kk*136 + n4*4,                                        \
                      data + ((size_t)b*FIN + (f0) + kk)*NN + n0 + n4*4);        \
            }                                                                    \
            _Pragma("unroll")                                                    \
            for (int a = 0; a < 4; a++) {                                        \
                int idx = tid + a*256;                                           \
                int dd = idx >> 3, k4 = idx & 7;                                 \
                cpa16(pB + dd*36 + k4*4, linw + dd*FIN + (f0) + k4*4);           \
            }                                                                    \
        }

    XL_LOAD(0, 0) CP_COMMIT;
    XL_LOAD(1, 32) CP_COMMIT;
    #pragma unroll 1
    for (int it = 0; it < FIN/32; it++) {
        if (it + 1 < FIN/32) { CP_WAIT1; } else { CP_WAIT0; }
        __syncthreads();
        if (it + 2 < FIN/32) { XL_LOAD((it+2)%NSTAGE, (it+2)*32) CP_COMMIT; }
        unsigned* pA = smu + (it%NSTAGE)*STG_KN;
        unsigned* pB = pA + A_KN_WORDS;
        CHUNK_KN(pA, pB)
    }
    #undef XL_LOAD

    float pv[8] = {}, qv[8] = {};
    #pragma unroll
    for (int mi = 0; mi < 4; mi++)
        #pragma unroll
        for (int ni = 0; ni < 4; ni++) {
            int row = n0 + wm + mi*16 + g, col = wn + ni*8 + t4*2;
            size_t i0 = ((size_t)b*NN + row    )*DD + col;
            size_t i1 = ((size_t)b*NN + row + 8)*DD + col;
            *(__half2*)&d_xl16[i0] = __floats2half2_rn(c[mi][ni][0], c[mi][ni][1]);
            *(__half2*)&d_xl16[i1] = __floats2half2_rn(c[mi][ni][2], c[mi][ni][3]);
            float a0 = ai[col], a1 = ai[col+1];
            float j0 = aj[col], j1 = aj[col+1];
            pv[mi*2  ] += c[mi][ni][0]*a0 + c[mi][ni][1]*a1;
            pv[mi*2+1] += c[mi][ni][2]*a0 + c[mi][ni][3]*a1;
            qv[mi*2  ] += c[mi][ni][0]*j0 + c[mi][ni][1]*j1;
            qv[mi*2+1] += c[mi][ni][2]*j0 + c[mi][ni][3]*j1;
        }
    #pragma unroll
    for (int r = 0; r < 8; r++) {
        pv[r] += __shfl_xor_sync(0xffffffffu, pv[r], 1);
        pv[r] += __shfl_xor_sync(0xffffffffu, pv[r], 2);
        qv[r] += __shfl_xor_sync(0xffffffffu, qv[r], 1);
        qv[r] += __shfl_xor_sync(0xffffffffu, qv[r], 2);
    }
    if (t4 == 0) {
        #pragma unroll
        for (int mi = 0; mi < 4; mi++) {
            int r0 = wm + mi*16 + g;
            atomicAdd(&spq[r0][0],   pv[mi*2]);
            atomicAdd(&spq[r0][1],   qv[mi*2]);
            atomicAdd(&spq[r0+8][0], pv[mi*2+1]);
            atomicAdd(&spq[r0+8][1], qv[mi*2+1]);
        }
    }
    __syncthreads();
    if (tid < 2*DD) {
        int row = tid >> 1, which = tid & 1;
        float v = spq[row][which];
        if (which == 0) d_p[b*NN + n0 + row] = v;
        else            d_q[b*NN + n0 + row] = v;
    }
}

// ---------------------------------------------------------------
// K5: attention with SMEM-CACHED xl16 batch slice (131072 B) +
//     gts transpose staging (67584 B) = 198656 B dynamic smem.
//     Cuts the 20-edge gather from ~167 MB L2 traffic to ~16 MB.
// ---------------------------------------------------------------
#define GTS_PITCH 264
__global__ void __launch_bounds__(256, 1) k_attn2(const float* __restrict__ emb,
                                                  const float* __restrict__ gbias,
                                                  const float* __restrict__ gamma,
                                                  const float* __restrict__ beta) {
    extern __shared__ __half smh[];
    __half* xlc = smh;                 // [512][128] fp16 = 131072 B
    __half* gts = smh + NN*DD;         // [128][GTS_PITCH] = 67584 B
    int b = blockIdx.x >> 1, nhalf = blockIdx.x & 1;
    int n0 = nhalf * 256;
    int tid = threadIdx.x, wrp = tid >> 5, lane = tid & 31;

    // cache this batch's xl16 slice (128 KB) via cp.async
    const __half* src = d_xl16 + (size_t)b*NN*DD;
    #pragma unroll
    for (int a = 0; a < 32; a++) {
        int idx = tid + a*256;
        cpa16(xlc + idx*8, src + idx*8);
    }
    CP_COMMIT; CP_WAIT0;
    __syncthreads();

    const float inv = rsqrtf(1.0f + 1e-5f);
    for (int i = 0; i < 32; i++) {
        int n = n0 + wrp*32 + i;
        int widx = b*NN + n;
        int src_k = 0; float alpha = -1e30f;
        if (lane < KTOP) {
            src_k = d_topk[n*KTOP + lane];
            alpha = d_p[widx] + d_r[n] + d_q[b*NN + src_k] + d_s[src_k];
            alpha = alpha > 0.f ? alpha : 0.2f*alpha;
        }
        float m = alpha;
        #pragma unroll
        for (int o = 16; o; o >>= 1) m = fmaxf(m, __shfl_xor_sync(0xffffffffu, m, o));
        float ex = (lane < KTOP) ? expf(alpha - m) : 0.f;
        float sm = ex;
        #pragma unroll
        for (int o = 16; o; o >>= 1) sm += __shfl_xor_sync(0xffffffffu, sm, o);
        float aw = ex / sm;

        float2 acc0 = {0.f,0.f}, acc1 = {0.f,0.f};
        #pragma unroll
        for (int k = 0; k < KTOP; k++) {
            int   sk = __shfl_sync(0xffffffffu, src_k, k);
            float ak = __shfl_sync(0xffffffffu, aw,  k);
            const __half2* xr = (const __half2*)(xlc + sk*DD);
            float2 f0 = __half22float2(xr[lane]);
            float2 f1 = __half22float2(xr[lane + 32]);
            acc0.x += ak*f0.x; acc0.y += ak*f0.y;
            acc1.x += ak*f1.x; acc1.y += ak*f1.y;
        }
        int d0 = 2*lane, d1 = 2*lane + 64;
        float h0 = fmaxf((acc0.x + gbias[d0  ])*(gamma[d0  ]*inv) + beta[d0  ], 0.f) * emb[n*DD + d0];
        float h1 = fmaxf((acc0.y + gbias[d0+1])*(gamma[d0+1]*inv) + beta[d0+1], 0.f) * emb[n*DD + d0+1];
        float h2 = fmaxf((acc1.x + gbias[d1  ])*(gamma[d1  ]*inv) + beta[d1  ], 0.f) * emb[n*DD + d1];
        float h3 = fmaxf((acc1.y + gbias[d1+1])*(gamma[d1+1]*inv) + beta[d1+1], 0.f) * emb[n*DD + d1+1];
        int nn = n - n0;
        gts[(d0  )*GTS_PITCH + nn] = __float2half(h0);
        gts[(d0+1)*GTS_PITCH + nn] = __float2half(h1);
        gts[(d1  )*GTS_PITCH + nn] = __float2half(h2);
        gts[(d1+1)*GTS_PITCH + nn] = __float2half(h3);
    }
    __syncthreads();
    for (int row = wrp; row < DD; row += 8) {
        *(uint4*)(d_gT16 + ((size_t)b*DD + row)*NN + n0 + lane*8) =
            *(uint4*)(gts + row*GTS_PITCH + lane*8);
    }
}

// ---------------------------------------------------------------
// K6 (fp16 MMA): o1[b,d,h] = sum_n gT[b,d,n] * w1[h,n]
// ---------------------------------------------------------------
__global__ void __launch_bounds__(256, 2) k_gemm1() {
    extern __shared__ unsigned smu[];
    int b = blockIdx.y, h0 = blockIdx.x * 128;
    int tid = threadIdx.x;
    int w = tid >> 5, lane = tid & 31;
    int g = lane >> 2, t4 = lane & 3;
    int wm = (w & 1) * 64, wn = (w >> 1) * 32;
    float c[4][4][4] = {};

    #define G1_LOAD(st, k0)                                                      \
        {                                                                        \
            unsigned* pA = smu + (st)*STG_H;                                     \
            unsigned* pB = pA + H_OP_WORDS;                                      \
            _Pragma("unroll")                                                    \
            for (int a = 0; a < 4; a++) {                                        \
                int idx = tid + a*256;                                           \
                int row = idx >> 3, seg = idx & 7;                               \
                cpa16(pA + row*HROW_W + seg*4,                                   \
                      d_gT16 + ((size_t)b*DD + row)*NN + (k0) + seg*8);          \
            }                                                                    \
            _Pragma("unroll")                                                    \
            for (int a = 0; a < 4; a++) {                                        \
                int idx = tid + a*256;                                           \
                int row = idx >> 3, seg = idx & 7;                               \
                cpa16(pB + row*HROW_W + seg*4,                                   \
                      d_w116 + (size_t)(h0 + row)*NN + (k0) + seg*8);            \
            }                                                                    \
        }

    G1_LOAD(0, 0) CP_COMMIT;
    G1_LOAD(1, 64) CP_COMMIT;
    #pragma unroll 1
    for (int it = 0; it < NN/64; it++) {
        if (it + 1 < NN/64) { CP_WAIT1; } else { CP_WAIT0; }
        __syncthreads();
        if (it + 2 < NN/64) { G1_LOAD((it+2)%NSTAGE, (it+2)*64) CP_COMMIT; }
        unsigned* pA = smu + (it%NSTAGE)*STG_H;
        unsigned* pB = pA + H_OP_WORDS;
        CHUNK_H(pA, pB)
    }
    #undef G1_LOAD
    #pragma unroll
    for (int mi = 0; mi < 4; mi++)
        #pragma unroll
        for (int ni = 0; ni < 4; ni++) {
            int row = wm + mi*16 + g, col = h0 + wn + ni*8 + t4*2;
            *(__half2*)&d_o116[((size_t)b*DD + row    )*HIDN + col] =
                __floats2half2_rn(c[mi][ni][0], c[mi][ni][1]);
            *(__half2*)&d_o116[((size_t)b*DD + row + 8)*HIDN + col] =
                __floats2half2_rn(c[mi][ni][2], c[mi][ni][3]);
        }
}

// ---------------------------------------------------------------
// K7 (fp16 MMA): out[b,d,h2] = sigmoid(sum_h o1[b,d,h]*w2[h2,h] + b2)
// ---------------------------------------------------------------
__global__ void __launch_bounds__(256, 2) k_gemm2(const float* __restrict__ b2,
                                                  float* __restrict__ out) {
    extern __shared__ unsigned smu[];
    int b = blockIdx.y, h20 = blockIdx.x * 128;
    int tid = threadIdx.x;
    int w = tid >> 5, lane = tid & 31;
    int g = lane >> 2, t4 = lane & 3;
    int wm = (w & 1) * 64, wn = (w >> 1) * 32;
    float c[4][4][4] = {};

    #define G2_LOAD(st, k0)                                                      \
        {                                                                        \
            unsigned* pA = smu + (st)*STG_H;                                     \
            unsigned* pB = pA + H_OP_WORDS;                                      \
            _Pragma("unroll")                                                    \
            for (int a = 0; a < 4; a++) {                                        \
                int idx = tid + a*256;                                           \
                int row = idx >> 3, seg = idx & 7;                               \
                cpa16(pA + row*HROW_W + seg*4,                                   \
                      d_o116 + ((size_t)b*DD + row)*HIDN + (k0) + seg*8);        \
            }                                                                    \
            _Pragma("unroll")                                                    \
            for (int a = 0; a < 4; a++) {                                        \
                int idx = tid + a*256;                                           \
                int row = idx >> 3, seg = idx & 7;                               \
                cpa16(pB + row*HROW_W + seg*4,                                   \
                      d_w216 + (size_t)(h20 + row)*HIDN + (k0) + seg*8);         \
            }                                                                    \
        }

    G2_LOAD(0, 0) CP_COMMIT;
    G2_LOAD(1, 64) CP_COMMIT;
    #pragma unroll 1
    for (int it = 0; it < HIDN/64; it++) {
        if (it + 1 < HIDN/64) { CP_WAIT1; } else { CP_WAIT0; }
        __syncthreads();
        if (it + 2 < HIDN/64) { G2_LOAD((it+2)%NSTAGE, (it+2)*64) CP_COMMIT; }
        unsigned* pA = smu + (it%NSTAGE)*STG_H;
        unsigned* pB = pA + H_OP_WORDS;
        CHUNK_H(pA, pB)
    }
    #undef G2_LOAD
    #pragma unroll
    for (int mi = 0; mi < 4; mi++)
        #pragma unroll
        for (int ni = 0; ni < 4; ni++) {
            int row = wm + mi*16 + g, col = h20 + wn + ni*8 + t4*2;
            float bb0 = b2[col], bb1 = b2[col + 1];
            float2 v0, v1;
            v0.x = 1.0f/(1.0f + expf(-(c[mi][ni][0] + bb0)));
            v0.y = 1.0f/(1.0f + expf(-(c[mi][ni][1] + bb1)));
            v1.x = 1.0f/(1.0f + expf(-(c[mi][ni][2] + bb0)));
            v1.y = 1.0f/(1.0f + expf(-(c[mi][ni][3] + bb1)));
            *(float2*)&out[((size_t)b*DD + row    )*HIDN + col] = v0;
            *(float2*)&out[((size_t)b*DD + row + 8)*HIDN + col] = v1;
        }
}

// ---------------------------------------------------------------
// K8: pack trailing outputs (emb_weight copy, topk_idx as float)
// ---------------------------------------------------------------
__global__ void k_pack(const float* __restrict__ emb, float* __restrict__ out, int mode) {
    int i = blockIdx.x*256 + threadIdx.x;
    const int OUT0 = BB*DD*HIDN;
    if (i < NN*DD) out[OUT0 + i] = emb[i];
    if (mode && i < NN*KTOP) out[OUT0 + NN*DD + i] = (float)d_topk[i];
}

extern "C" void kernel_launch(void* const* d_in, const int* in_sizes, int n_in,
                              void* d_out, int out_size) {
    const float* data  = (const float*)d_in[0];
    const float* emb   = (const float*)d_in[1];
    const float* linw  = (const float*)d_in[2];
    const float* ai    = (const float*)d_in[3];
    const float* aj    = (const float*)d_in[4];
    const float* aei   = (const float*)d_in[5];
    const float* aej   = (const float*)d_in[6];
    const float* gbias = (const float*)d_in[7];
    const float* gamma = (const float*)d_in[8];
    const float* beta  = (const float*)d_in[9];
    const float* w1    = (const float*)d_in[10];
    const float* w2    = (const float*)d_in[11];
    const float* b2    = (const float*)d_in[12];
    float* out = (float*)d_out;

    static cudaStream_t s2 = nullptr;
    static cudaEvent_t evFork = nullptr, evJoin = nullptr, evJoin2 = nullptr;
    static bool init_done = false;
    const int smem_kn   = NSTAGE*STG_KN*4;           // 107520 B
    const int smem_h    = NSTAGE*STG_H*4;            // 110592 B
    const int smem_attn = (NN*DD + DD*GTS_PITCH)*2;  // 198656 B
    if (!init_done) {
        cudaFuncSetAttribute(k_xl,    cudaFuncAttributeMaxDynamicSharedMemorySize, smem_kn);
        cudaFuncSetAttribute(k_gemm1, cudaFuncAttributeMaxDynamicSharedMemorySize, smem_h);
        cudaFuncSetAttribute(k_gemm2, cudaFuncAttributeMaxDynamicSharedMemorySize, smem_h);
        cudaFuncSetAttribute(k_attn2, cudaFuncAttributeMaxDynamicSharedMemorySize, smem_attn);
        cudaStreamCreateWithFlags(&s2, cudaStreamNonBlocking);
        cudaEventCreateWithFlags(&evFork,  cudaEventDisableTiming);
        cudaEventCreateWithFlags(&evJoin,  cudaEventDisableTiming);
        cudaEventCreateWithFlags(&evJoin2, cudaEventDisableTiming);
        init_done = true;
    }

    const int OUT0 = BB*DD*HIDN;
    int tail = (out_size >= OUT0 + NN*DD) ? 1 : 0;
    int mode = (out_size >= OUT0 + NN*DD + NN*KTOP) ? 1 : 0;

    cudaEventRecord(evFork, 0);
    cudaStreamWaitEvent(s2, evFork, 0);

    k_norm<<<NN, 128, 0, s2>>>(emb, aei, aej);
    k_cos <<<dim3(8, 8), 256, 0, s2>>>(emb);
    k_topk<<<NN/8, 256, 0, s2>>>();
    cudaEventRecord(evJoin, s2);                  // attn deps ready

    k_cvtw<<<(HIDN*NN/4 + HIDN*HIDN/4)/256, 256, 0, s2>>>(w1, w2);
    if (tail) k_pack<<<(NN*DD + 255)/256, 256, 0, s2>>>(emb, out, mode);
    cudaEventRecord(evJoin2, s2);                 // gemm1 deps ready

    k_xl<<<dim3(4, BB), 256, smem_kn>>>(data, linw, ai, aj);

    cudaStreamWaitEvent(0, evJoin, 0);
    k_attn2<<<2*BB, 256, smem_attn>>>(emb, gbias, gamma, beta);

    cudaStreamWaitEvent(0, evJoin2, 0);
    k_gemm1<<<dim3(4, BB), 256, smem_h>>>();
    k_gemm2<<<dim3(4, BB), 256, smem_h>>>(b2, out);
}

// round 13
// speedup vs baseline: 1.3478x; 1.0183x over previous
#include <cuda_runtime.h>
#include <cuda_fp16.h>
#include <math.h>

#define BB   64
#define NN   512
#define FIN  256
#define DD   128
#define KTOP 20
#define HIDN 512

// ---- scratch (device globals; no allocations) ----
static __device__ __half d_xl16[BB*NN*DD];     // [b,n,d] lin(x), fp16
static __device__ __half d_gT16[BB*DD*NN];     // [b,d,n] gated GCN output (transposed), fp16
static __device__ __half d_o116[BB*DD*HIDN];   // [b,d,h] first linear, fp16
static __device__ __half d_w116[HIDN*NN];      // w1 fp16
static __device__ __half d_w216[HIDN*HIDN];    // w2 fp16
static __device__ float  d_p [BB*NN];
static __device__ float  d_q [BB*NN];
static __device__ float  d_rinv[NN];
static __device__ float  d_r [NN];
static __device__ float  d_s [NN];
static __device__ float  d_cosm[NN*NN];
static __device__ int    d_topk[NN*KTOP];
static __device__ int    d_bar;                // global barrier for k_gemm12

// ---------------- MMA / cp.async helpers ----------------
__device__ __forceinline__ void mma_tf32(float c[4],
        unsigned a0, unsigned a1, unsigned a2, unsigned a3,
        unsigned b0, unsigned b1) {
    asm volatile(
        "mma.sync.aligned.m16n8k8.row.col.f32.tf32.tf32.f32 "
        "{%0,%1,%2,%3}, {%4,%5,%6,%7}, {%8,%9}, {%0,%1,%2,%3};\n"
        : "+f"(c[0]), "+f"(c[1]), "+f"(c[2]), "+f"(c[3])
        : "r"(a0), "r"(a1), "r"(a2), "r"(a3), "r"(b0), "r"(b1));
}
__device__ __forceinline__ void mma_f16(float c[4],
        unsigned a0, unsigned a1, unsigned a2, unsigned a3,
        unsigned b0, unsigned b1) {
    asm volatile(
        "mma.sync.aligned.m16n8k16.row.col.f32.f16.f16.f32 "
        "{%0,%1,%2,%3}, {%4,%5,%6,%7}, {%8,%9}, {%0,%1,%2,%3};\n"
        : "+f"(c[0]), "+f"(c[1]), "+f"(c[2]), "+f"(c[3])
        : "r"(a0), "r"(a1), "r"(a2), "r"(a3), "r"(b0), "r"(b1));
}
__device__ __forceinline__ void cpa16(void* dst, const void* src) {
    unsigned ds = (unsigned)__cvta_generic_to_shared(dst);
    asm volatile("cp.async.cg.shared.global [%0], [%1], 16;" :: "r"(ds), "l"(src));
}
#define CP_COMMIT asm volatile("cp.async.commit_group;")
#define CP_WAIT1  asm volatile("cp.async.wait_group 1;")
#define CP_WAIT0  asm volatile("cp.async.wait_group 0;")
#define NSTAGE    3

// ---- tf32 k_xl geometry ----
#define A_KN_WORDS 4352          // [32 k][136]
#define B_KN_WORDS 4608          // [128][36]
#define STG_KN     (A_KN_WORDS + B_KN_WORDS)   // 8960 w

// ---- fp16 gemm geometry ----
#define HROW_W     36
#define H_OP_WORDS (128*HROW_W)                 // 4608 words per operand
#define STG_H      (2*H_OP_WORDS)               // 9216 words per stage

// tf32 chunk: A [k][136], B [m][36]
#define CHUNK_KN(pA, pB)                                                        \
    _Pragma("unroll")                                                            \
    for (int ks = 0; ks < 4; ks++) {                                             \
        int k8 = ks*8;                                                           \
        unsigned af[4][4], bf[4][2];                                             \
        _Pragma("unroll")                                                        \
        for (int mi = 0; mi < 4; mi++) {                                         \
            int r = wm + mi*16 + g;                                              \
            af[mi][0] = (pA)[(k8+t4  )*136 + r    ];                             \
            af[mi][1] = (pA)[(k8+t4  )*136 + r + 8];                             \
            af[mi][2] = (pA)[(k8+t4+4)*136 + r    ];                             \
            af[mi][3] = (pA)[(k8+t4+4)*136 + r + 8];                             \
        }                                                                        \
        _Pragma("unroll")                                                        \
        for (int ni = 0; ni < 4; ni++) {                                         \
            int rn = wn + ni*8 + g;                                              \
            bf[ni][0] = (pB)[rn*36 + k8+t4    ];                                 \
            bf[ni][1] = (pB)[rn*36 + k8+t4 + 4];                                 \
        }                                                                        \
        _Pragma("unroll")                                                        \
        for (int mi = 0; mi < 4; mi++)                                           \
            _Pragma("unroll")                                                    \
            for (int ni = 0; ni < 4; ni++)                                       \
                mma_tf32(c[mi][ni], af[mi][0], af[mi][1], af[mi][2],             \
                         af[mi][3], bf[ni][0], bf[ni][1]);                       \
    }

// fp16 chunk (K=64): A [m][36w], B [n][36w]
#define CHUNK_H(pA, pB)                                                         \
    _Pragma("unroll")                                                            \
    for (int ks = 0; ks < 4; ks++) {                                             \
        int kw = ks*8;                                                           \
        unsigned af[4][4], bf[4][2];                                             \
        _Pragma("unroll")                                                        \
        for (int mi = 0; mi < 4; mi++) {                                         \
            int r = wm + mi*16 + g;                                              \
            af[mi][0] = (pA)[(r    )*HROW_W + kw + t4    ];                      \
            af[mi][1] = (pA)[(r + 8)*HROW_W + kw + t4    ];                      \
            af[mi][2] = (pA)[(r    )*HROW_W + kw + t4 + 4];                      \
            af[mi][3] = (pA)[(r + 8)*HROW_W + kw + t4 + 4];                      \
        }                                                                        \
        _Pragma("unroll")                                                        \
        for (int ni = 0; ni < 4; ni++) {                                         \
            int rn = wn + ni*8 + g;                                              \
            bf[ni][0] = (pB)[rn*HROW_W + kw + t4    ];                           \
            bf[ni][1] = (pB)[rn*HROW_W + kw + t4 + 4];                           \
        }                                                                        \
        _Pragma("unroll")                                                        \
        for (int mi = 0; mi < 4; mi++)                                           \
            _Pragma("unroll")                                                    \
            for (int ni = 0; ni < 4; ni++)                                       \
                mma_f16(c[mi][ni], af[mi][0], af[mi][1], af[mi][2],              \
                        af[mi][3], bf[ni][0], bf[ni][1]);                        \
    }

// ---------------------------------------------------------------
// K_misc: fused norm + weight converts + pack + barrier reset.
//   blocks [0,256): norm, 2 rows/block
//   blocks [256,768): cvtw (w1 then w2)
//   blocks [768,1024): pack (only launched when tail)
// ---------------------------------------------------------------
__global__ void __launch_bounds__(256) k_misc(const float* __restrict__ emb,
                                              const float* __restrict__ aei,
                                              const float* __restrict__ aej,
                                              const float* __restrict__ w1,
                                              const float* __restrict__ w2,
                                              float* __restrict__ out, int mode) {
    int blk = blockIdx.x, tid = threadIdx.x;
    if (blk == 0 && tid == 0) d_bar = 0;        // reset gemm12 barrier
    if (blk < 256) {
        // norm: rows 2*blk + (tid>=128)
        int half = tid >> 7, t = tid & 127;
        int n = blk*2 + half;
        float w  = emb[n*DD + t];
        float v0 = w*w, v1 = w*aei[t], v2 = w*aej[t];
        #pragma unroll
        for (int o = 16; o; o >>= 1) {
            v0 += __shfl_xor_sync(0xffffffffu, v0, o);
            v1 += __shfl_xor_sync(0xffffffffu, v1, o);
            v2 += __shfl_xor_sync(0xffffffffu, v2, o);
        }
        __shared__ float s0[2][4], s1[2][4], s2[2][4];
        int wid = t >> 5, lane = t & 31;
        if (lane == 0) { s0[half][wid]=v0; s1[half][wid]=v1; s2[half][wid]=v2; }
        __syncthreads();
        if (t == 0) {
            d_rinv[n] = rsqrtf(s0[half][0]+s0[half][1]+s0[half][2]+s0[half][3]);
            d_r[n] = s1[half][0]+s1[half][1]+s1[half][2]+s1[half][3];
            d_s[n] = s2[half][0]+s2[half][1]+s2[half][2]+s2[half][3];
        }
    } else if (blk < 768) {
        int idx = (blk - 256)*256 + tid;        // 131072 float4 groups
        const int N1 = HIDN*NN/4;
        if (idx < N1) {
            float4 v = *(const float4*)(w1 + (size_t)idx*4);
            __half2* d2 = (__half2*)(d_w116 + (size_t)idx*4);
            d2[0] = __floats2half2_rn(v.x, v.y);
            d2[1] = __floats2half2_rn(v.z, v.w);
        } else {
            int j = idx - N1;
            float4 v = *(const float4*)(w2 + (size_t)j*4);
            __half2* d2 = (__half2*)(d_w216 + (size_t)j*4);
            d2[0] = __floats2half2_rn(v.x, v.y);
            d2[1] = __floats2half2_rn(v.z, v.w);
        }
    } else {
        int i = (blk - 768)*256 + tid;
        const int OUT0 = BB*DD*HIDN;
        if (i < NN*DD) out[OUT0 + i] = emb[i];
        // topk not ready here; pack of topk handled by k_topk epilogue
        (void)mode;
    }
}

// ---------------------------------------------------------------
// K1: cosine matrix — proven tiled form
// ---------------------------------------------------------------
__global__ void k_cos(const float* __restrict__ emb) {
    __shared__ float sAt[32][68];
    __shared__ float sBt[32][68];
    int i0 = blockIdx.y * 64, j0 = blockIdx.x * 64;
    int tid = threadIdx.x;
    int tx = tid & 15, ty = tid >> 4;
    float c[4][4] = {};
    for (int k0 = 0; k0 < DD; k0 += 32) {
        #pragma unroll
        for (int a = 0; a < 8; a++) {
            int idx = tid + a*256;
            int row = idx >> 5, kk = idx & 31;
            sAt[kk][row] = emb[(i0+row)*DD + k0 + kk];
            sBt[kk][row] = emb[(j0+row)*DD + k0 + kk];
        }
        __syncthreads();
        #pragma unroll
        for (int kk = 0; kk < 32; kk++) {
            float av[4], bv[4];
            *(float4*)av = *(const float4*)&sAt[kk][ty*4];
            *(float4*)bv = *(const float4*)&sBt[kk][tx*4];
            #pragma unroll
            for (int ii = 0; ii < 4; ii++)
                #pragma unroll
                for (int jj = 0; jj < 4; jj++)
                    c[ii][jj] += av[ii]*bv[jj];
        }
        __syncthreads();
    }
    float rj[4];
    #pragma unroll
    for (int jj = 0; jj < 4; jj++) rj[jj] = d_rinv[j0 + tx*4 + jj];
    #pragma unroll
    for (int ii = 0; ii < 4; ii++) {
        float ri = d_rinv[i0 + ty*4 + ii];
        float4 v;
        v.x = c[ii][0]*ri*rj[0]; v.y = c[ii][1]*ri*rj[1];
        v.z = c[ii][2]*ri*rj[2]; v.w = c[ii][3]*ri*rj[3];
        *(float4*)&d_cosm[(i0 + ty*4 + ii)*NN + j0 + tx*4] = v;
    }
}

// ---------------------------------------------------------------
// K2: top-20 per row (+ optional topk pack into out tail)
// ---------------------------------------------------------------
__global__ void k_topk(float* __restrict__ out, int mode) {
    int row  = (blockIdx.x*256 + threadIdx.x) >> 5;
    int lane = threadIdx.x & 31;
    float v[16];
    #pragma unroll
    for (int j = 0; j < 16; j++) v[j] = d_cosm[row*NN + lane + 32*j];
    for (int t = 0; t < KTOP; t++) {
        float bv = v[0]; int bj = 0;
        #pragma unroll
        for (int j = 1; j < 16; j++)
            if (v[j] > bv) { bv = v[j]; bj = j; }
        int bidx = lane + 32*bj;
        #pragma unroll
        for (int o = 16; o; o >>= 1) {
            float ov = __shfl_xor_sync(0xffffffffu, bv, o);
            int   oi = __shfl_xor_sync(0xffffffffu, bidx, o);
            if (ov > bv || (ov == bv && oi < bidx)) { bv = ov; bidx = oi; }
        }
        if (lane == 0) {
            d_topk[row*KTOP + t] = bidx;
            if (mode) out[BB*DD*HIDN + NN*DD + row*KTOP + t] = (float)bidx;
        }
        #pragma unroll
        for (int j = 0; j < 16; j++)
            if (lane + 32*j == bidx) v[j] = -INFINITY;
    }
}

// ---------------------------------------------------------------
// K3: xl (tf32 MMA, 3-stage) + fused p/q epilogue.
// ---------------------------------------------------------------
__global__ void __launch_bounds__(256, 2) k_xl(const float* __restrict__ data,
                                               const float* __restrict__ linw,
                                               const float* __restrict__ ai,
                                               const float* __restrict__ aj) {
    extern __shared__ unsigned smu[];
    __shared__ float spq[DD][2];
    int b = blockIdx.y, n0 = blockIdx.x * 128;
    int tid = threadIdx.x;
    int w = tid >> 5, lane = tid & 31;
    int g = lane >> 2, t4 = lane & 3;
    int wm = (w & 1) * 64, wn = (w >> 1) * 32;
    if (tid < DD) { spq[tid][0] = 0.f; spq[tid][1] = 0.f; }
    float c[4][4][4] = {};

    #define XL_LOAD(st, f0)                                                      \
        {                                                                        \
            unsigned* pA = smu + (st)*STG_KN;                                    \
            unsigned* pB = pA + A_KN_WORDS;                                      \
            _Pragma("unroll")                                                    \
            for (int a = 0; a < 4; a++) {                                        \
                int idx = tid + a*256;                                           \
                int kk = idx >> 5, n4 = idx & 31;                                \
                cpa16(pA + kk*136 + n4*4,                                        \
                      data + ((size_t)b*FIN + (f0) + kk)*NN + n0 + n4*4);        \
            }                                                                    \
            _Pragma("unroll")                                                    \
            for (int a = 0; a < 4; a++) {                                        \
                int idx = tid + a*256;                                           \
                int dd = idx >> 3, k4 = idx & 7;                                 \
                cpa16(pB + dd*36 + k4*4, linw + dd*FIN + (f0) + k4*4);           \
            }                                                                    \
        }

    XL_LOAD(0, 0) CP_COMMIT;
    XL_LOAD(1, 32) CP_COMMIT;
    #pragma unroll 1
    for (int it = 0; it < FIN/32; it++) {
        if (it + 1 < FIN/32) { CP_WAIT1; } else { CP_WAIT0; }
        __syncthreads();
        if (it + 2 < FIN/32) { XL_LOAD((it+2)%NSTAGE, (it+2)*32) CP_COMMIT; }
        unsigned* pA = smu + (it%NSTAGE)*STG_KN;
        unsigned* pB = pA + A_KN_WORDS;
        CHUNK_KN(pA, pB)
    }
    #undef XL_LOAD

    float pv[8] = {}, qv[8] = {};
    #pragma unroll
    for (int mi = 0; mi < 4; mi++)
        #pragma unroll
        for (int ni = 0; ni < 4; ni++) {
            int row = n0 + wm + mi*16 + g, col = wn + ni*8 + t4*2;
            size_t i0 = ((size_t)b*NN + row    )*DD + col;
            size_t i1 = ((size_t)b*NN + row + 8)*DD + col;
            *(__half2*)&d_xl16[i0] = __floats2half2_rn(c[mi][ni][0], c[mi][ni][1]);
            *(__half2*)&d_xl16[i1] = __floats2half2_rn(c[mi][ni][2], c[mi][ni][3]);
            float a0 = ai[col], a1 = ai[col+1];
            float j0 = aj[col], j1 = aj[col+1];
            pv[mi*2  ] += c[mi][ni][0]*a0 + c[mi][ni][1]*a1;
            pv[mi*2+1] += c[mi][ni][2]*a0 + c[mi][ni][3]*a1;
            qv[mi*2  ] += c[mi][ni][0]*j0 + c[mi][ni][1]*j1;
            qv[mi*2+1] += c[mi][ni][2]*j0 + c[mi][ni][3]*j1;
        }
    #pragma unroll
    for (int r = 0; r < 8; r++) {
        pv[r] += __shfl_xor_sync(0xffffffffu, pv[r], 1);
        pv[r] += __shfl_xor_sync(0xffffffffu, pv[r], 2);
        qv[r] += __shfl_xor_sync(0xffffffffu, qv[r], 1);
        qv[r] += __shfl_xor_sync(0xffffffffu, qv[r], 2);
    }
    if (t4 == 0) {
        #pragma unroll
        for (int mi = 0; mi < 4; mi++) {
            int r0 = wm + mi*16 + g;
            atomicAdd(&spq[r0][0],   pv[mi*2]);
            atomicAdd(&spq[r0][1],   qv[mi*2]);
            atomicAdd(&spq[r0+8][0], pv[mi*2+1]);
            atomicAdd(&spq[r0+8][1], qv[mi*2+1]);
        }
    }
    __syncthreads();
    if (tid < 2*DD) {
        int row = tid >> 1, which = tid & 1;
        float v = spq[row][which];
        if (which == 0) d_p[b*NN + n0 + row] = v;
        else            d_q[b*NN + n0 + row] = v;
    }
}

// ---------------------------------------------------------------
// K5: attention with smem-cached xl16 batch slice + gts staging.
// ---------------------------------------------------------------
#define GTS_PITCH 264
__global__ void __launch_bounds__(256, 1) k_attn2(const float* __restrict__ emb,
                                                  const float* __restrict__ gbias,
                                                  const float* __restrict__ gamma,
                                                  const float* __restrict__ beta) {
    extern __shared__ __half smh[];
    __half* xlc = smh;                 // [512][128] fp16 = 131072 B
    __half* gts = smh + NN*DD;         // [128][GTS_PITCH] = 67584 B
    int b = blockIdx.x >> 1, nhalf = blockIdx.x & 1;
    int n0 = nhalf * 256;
    int tid = threadIdx.x, wrp = tid >> 5, lane = tid & 31;

    const __half* src = d_xl16 + (size_t)b*NN*DD;
    #pragma unroll
    for (int a = 0; a < 32; a++) {
        int idx = tid + a*256;
        cpa16(xlc + idx*8, src + idx*8);
    }
    CP_COMMIT; CP_WAIT0;
    __syncthreads();

    const float inv = rsqrtf(1.0f + 1e-5f);
    for (int i = 0; i < 32; i++) {
        int n = n0 + wrp*32 + i;
        int widx = b*NN + n;
        int src_k = 0; float alpha = -1e30f;
        if (lane < KTOP) {
            src_k = d_topk[n*KTOP + lane];
            alpha = d_p[widx] + d_r[n] + d_q[b*NN + src_k] + d_s[src_k];
            alpha = alpha > 0.f ? alpha : 0.2f*alpha;
        }
        float m = alpha;
        #pragma unroll
        for (int o = 16; o; o >>= 1) m = fmaxf(m, __shfl_xor_sync(0xffffffffu, m, o));
        float ex = (lane < KTOP) ? expf(alpha - m) : 0.f;
        float sm = ex;
        #pragma unroll
        for (int o = 16; o; o >>= 1) sm += __shfl_xor_sync(0xffffffffu, sm, o);
        float aw = ex / sm;

        float2 acc0 = {0.f,0.f}, acc1 = {0.f,0.f};
        #pragma unroll
        for (int k = 0; k < KTOP; k++) {
            int   sk = __shfl_sync(0xffffffffu, src_k, k);
            float ak = __shfl_sync(0xffffffffu, aw,  k);
            const __half2* xr = (const __half2*)(xlc + sk*DD);
            float2 f0 = __half22float2(xr[lane]);
            float2 f1 = __half22float2(xr[lane + 32]);
            acc0.x += ak*f0.x; acc0.y += ak*f0.y;
            acc1.x += ak*f1.x; acc1.y += ak*f1.y;
        }
        int d0 = 2*lane, d1 = 2*lane + 64;
        float h0 = fmaxf((acc0.x + gbias[d0  ])*(gamma[d0  ]*inv) + beta[d0  ], 0.f) * emb[n*DD + d0];
        float h1 = fmaxf((acc0.y + gbias[d0+1])*(gamma[d0+1]*inv) + beta[d0+1], 0.f) * emb[n*DD + d0+1];
        float h2 = fmaxf((acc1.x + gbias[d1  ])*(gamma[d1  ]*inv) + beta[d1  ], 0.f) * emb[n*DD + d1];
        float h3 = fmaxf((acc1.y + gbias[d1+1])*(gamma[d1+1]*inv) + beta[d1+1], 0.f) * emb[n*DD + d1+1];
        int nn = n - n0;
        gts[(d0  )*GTS_PITCH + nn] = __float2half(h0);
        gts[(d0+1)*GTS_PITCH + nn] = __float2half(h1);
        gts[(d1  )*GTS_PITCH + nn] = __float2half(h2);
        gts[(d1+1)*GTS_PITCH + nn] = __float2half(h3);
    }
    __syncthreads();
    for (int row = wrp; row < DD; row += 8) {
        *(uint4*)(d_gT16 + ((size_t)b*DD + row)*NN + n0 + lane*8) =
            *(uint4*)(gts + row*GTS_PITCH + lane*8);
    }
}

// ---------------------------------------------------------------
// K67: FUSED gemm1 + global barrier + gemm2 (persistent, 256 CTAs,
//      2 CTAs/SM -> all co-resident; spin barrier is deadlock-free).
// ---------------------------------------------------------------
__global__ void __launch_bounds__(256, 2) k_gemm12(const float* __restrict__ b2,
                                                   float* __restrict__ out) {
    extern __shared__ unsigned smu[];
    int b = blockIdx.y, h0 = blockIdx.x * 128;
    int tid = threadIdx.x;
    int w = tid >> 5, lane = tid & 31;
    int g = lane >> 2, t4 = lane & 3;
    int wm = (w & 1) * 64, wn = (w >> 1) * 32;

    // ---------------- phase 1: o1 = gT @ w1^T ----------------
    {
        float c[4][4][4] = {};
        #define G1_LOAD(st, k0)                                                  \
            {                                                                    \
                unsigned* pA = smu + (st)*STG_H;                                 \
                unsigned* pB = pA + H_OP_WORDS;                                  \
                _Pragma("unroll")                                                \
                for (int a = 0; a < 4; a++) {                                    \
                    int idx = tid + a*256;                                       \
                    int row = idx >> 3, seg = idx & 7;                           \
                    cpa16(pA + row*HROW_W + seg*4,                               \
                          d_gT16 + ((size_t)b*DD + row)*NN + (k0) + seg*8);      \
                }                                                                \
                _Pragma("unroll")                                                \
                for (int a = 0; a < 4; a++) {                                    \
                    int idx = tid + a*256;                                       \
                    int row = idx >> 3, seg = idx & 7;                           \
                    cpa16(pB + row*HROW_W + seg*4,                               \
                          d_w116 + (size_t)(h0 + row)*NN + (k0) + seg*8);        \
                }                                                                \
            }
        G1_LOAD(0, 0) CP_COMMIT;
        G1_LOAD(1, 64) CP_COMMIT;
        #pragma unroll 1
        for (int it = 0; it < NN/64; it++) {
            if (it + 1 < NN/64) { CP_WAIT1; } else { CP_WAIT0; }
            __syncthreads();
            if (it + 2 < NN/64) { G1_LOAD((it+2)%NSTAGE, (it+2)*64) CP_COMMIT; }
            unsigned* pA = smu + (it%NSTAGE)*STG_H;
            unsigned* pB = pA + H_OP_WORDS;
            CHUNK_H(pA, pB)
        }
        #undef G1_LOAD
        #pragma unroll
        for (int mi = 0; mi < 4; mi++)
            #pragma unroll
            for (int ni = 0; ni < 4; ni++) {
                int row = wm + mi*16 + g, col = h0 + wn + ni*8 + t4*2;
                *(__half2*)&d_o116[((size_t)b*DD + row    )*HIDN + col] =
                    __floats2half2_rn(c[mi][ni][0], c[mi][ni][1]);
                *(__half2*)&d_o116[((size_t)b*DD + row + 8)*HIDN + col] =
                    __floats2half2_rn(c[mi][ni][2], c[mi][ni][3]);
            }
    }

    // ---------------- global barrier (all 256 CTAs) ----------------
    __syncthreads();
    __threadfence();
    if (tid == 0) {
        atomicAdd(&d_bar, 1);
        while (*(volatile int*)&d_bar < 256) { }
    }
    __syncthreads();
    __threadfence();

    // ---------------- phase 2: out = sigmoid(o1 @ w2^T + b2) -------
    {
        int h20 = h0;
        float c[4][4][4] = {};
        #define G2_LOAD(st, k0)                                                  \
            {                                                                    \
                unsigned* pA = smu + (st)*STG_H;                                 \
                unsigned* pB = pA + H_OP_WORDS;                                  \
                _Pragma("unroll")                                                \
                for (int a = 0; a < 4; a++) {                                    \
                    int idx = tid + a*256;                                       \
                    int row = idx >> 3, seg = idx & 7;                           \
                    cpa16(pA + row*HROW_W + seg*4,                               \
                          d_o116 + ((size_t)b*DD + row)*HIDN + (k0) + seg*8);    \
                }                                                                \
                _Pragma("unroll")                                                \
                for (int a = 0; a < 4; a++) {                                    \
                    int idx = tid + a*256;                                       \
                    int row = idx >> 3, seg = idx & 7;                           \
                    cpa16(pB + row*HROW_W + seg*4,                               \
                          d_w216 + (size_t)(h20 + row)*HIDN + (k0) + seg*8);     \
                }                                                                \
            }
        G2_LOAD(0, 0) CP_COMMIT;
        G2_LOAD(1, 64) CP_COMMIT;
        #pragma unroll 1
        for (int it = 0; it < HIDN/64; it++) {
            if (it + 1 < HIDN/64) { CP_WAIT1; } else { CP_WAIT0; }
            __syncthreads();
            if (it + 2 < HIDN/64) { G2_LOAD((it+2)%NSTAGE, (it+2)*64) CP_COMMIT; }
            unsigned* pA = smu + (it%NSTAGE)*STG_H;
            unsigned* pB = pA + H_OP_WORDS;
            CHUNK_H(pA, pB)
        }
        #undef G2_LOAD
        #pragma unroll
        for (int mi = 0; mi < 4; mi++)
            #pragma unroll
            for (int ni = 0; ni < 4; ni++) {
                int row = wm + mi*16 + g, col = h20 + wn + ni*8 + t4*2;
                float bb0 = b2[col], bb1 = b2[col + 1];
                float2 v0, v1;
                v0.x = 1.0f/(1.0f + expf(-(c[mi][ni][0] + bb0)));
                v0.y = 1.0f/(1.0f + expf(-(c[mi][ni][1] + bb1)));
                v1.x = 1.0f/(1.0f + expf(-(c[mi][ni][2] + bb0)));
                v1.y = 1.0f/(1.0f + expf(-(c[mi][ni][3] + bb1)));
                *(float2*)&out[((size_t)b*DD + row    )*HIDN + col] = v0;
                *(float2*)&out[((size_t)b*DD + row + 8)*HIDN + col] = v1;
            }
    }
}

extern "C" void kernel_launch(void* const* d_in, const int* in_sizes, int n_in,
                              void* d_out, int out_size) {
    const float* data  = (const float*)d_in[0];
    const float* emb   = (const float*)d_in[1];
    const float* linw  = (const float*)d_in[2];
    const float* ai    = (const float*)d_in[3];
    const float* aj    = (const float*)d_in[4];
    const float* aei   = (const float*)d_in[5];
    const float* aej   = (const float*)d_in[6];
    const float* gbias = (const float*)d_in[7];
    const float* gamma = (const float*)d_in[8];
    const float* beta  = (const float*)d_in[9];
    const float* w1    = (const float*)d_in[10];
    const float* w2    = (const float*)d_in[11];
    const float* b2    = (const float*)d_in[12];
    float* out = (float*)d_out;

    static cudaStream_t s2 = nullptr;
    static cudaEvent_t evFork = nullptr, evJoin = nullptr;
    static bool init_done = false;
    const int smem_kn   = NSTAGE*STG_KN*4;           // 107520 B
    const int smem_h    = NSTAGE*STG_H*4;            // 110592 B
    const int smem_attn = (NN*DD + DD*GTS_PITCH)*2;  // 198656 B
    if (!init_done) {
        cudaFuncSetAttribute(k_xl,     cudaFuncAttributeMaxDynamicSharedMemorySize, smem_kn);
        cudaFuncSetAttribute(k_gemm12, cudaFuncAttributeMaxDynamicSharedMemorySize, smem_h);
        cudaFuncSetAttribute(k_attn2,  cudaFuncAttributeMaxDynamicSharedMemorySize, smem_attn);
        cudaStreamCreateWithFlags(&s2, cudaStreamNonBlocking);
        cudaEventCreateWithFlags(&evFork, cudaEventDisableTiming);
        cudaEventCreateWithFlags(&evJoin, cudaEventDisableTiming);
        init_done = true;
    }

    const int OUT0 = BB*DD*HIDN;
    int tail = (out_size >= OUT0 + NN*DD) ? 1 : 0;
    int mode = (out_size >= OUT0 + NN*DD + NN*KTOP) ? 1 : 0;

    cudaEventRecord(evFork, 0);
    cudaStreamWaitEvent(s2, evFork, 0);

    int misc_blocks = 768 + (tail ? 256 : 0);
    k_misc<<<misc_blocks, 256, 0, s2>>>(emb, aei, aej, w1, w2, out, mode);
    k_cos <<<dim3(8, 8), 256, 0, s2>>>(emb);
    k_topk<<<NN/8, 256, 0, s2>>>(out, mode);
    cudaEventRecord(evJoin, s2);      // covers norm/cos/topk/cvtw/pack/bar-reset

    k_xl<<<dim3(4, BB), 256, smem_kn>>>(data, linw, ai, aj);

    cudaStreamWaitEvent(0, evJoin, 0);
    k_attn2<<<2*BB, 256, smem_attn>>>(emb, gbias, gamma, beta);
    k_gemm12<<<dim3(4, BB), 256, smem_h>>>(b2, out);
}

// round 14
// speedup vs baseline: 1.3648x; 1.0126x over previous
#include <cuda_runtime.h>
#include <cuda_fp16.h>
#include <math.h>

#define BB   64
#define NN   512
#define FIN  256
#define DD   128
#define KTOP 20
#define HIDN 512

// ---- scratch (device globals; no allocations) ----
static __device__ __half d_xl16[BB*NN*DD];     // [b,n,d] lin(x), fp16
static __device__ __half d_gT16[BB*DD*NN];     // [b,d,n] gated GCN output (transposed), fp16
static __device__ __half d_o116[BB*DD*HIDN];   // [b,d,h] first linear, fp16
static __device__ __half d_w116[HIDN*NN];      // w1 fp16
static __device__ __half d_w216[HIDN*HIDN];    // w2 fp16
static __device__ float  d_p [BB*NN];
static __device__ float  d_q [BB*NN];
static __device__ float  d_rinv[NN];
static __device__ float  d_r [NN];
static __device__ float  d_s [NN];
static __device__ float  d_cosm[NN*NN];
static __device__ int    d_topk[NN*KTOP];
static __device__ int    d_bar;                // global barrier for k_gemm12

// ---------------- MMA / cp.async / ldmatrix helpers ----------------
__device__ __forceinline__ void mma_tf32(float c[4],
        unsigned a0, unsigned a1, unsigned a2, unsigned a3,
        unsigned b0, unsigned b1) {
    asm volatile(
        "mma.sync.aligned.m16n8k8.row.col.f32.tf32.tf32.f32 "
        "{%0,%1,%2,%3}, {%4,%5,%6,%7}, {%8,%9}, {%0,%1,%2,%3};\n"
        : "+f"(c[0]), "+f"(c[1]), "+f"(c[2]), "+f"(c[3])
        : "r"(a0), "r"(a1), "r"(a2), "r"(a3), "r"(b0), "r"(b1));
}
__device__ __forceinline__ void mma_f16(float c[4],
        unsigned a0, unsigned a1, unsigned a2, unsigned a3,
        unsigned b0, unsigned b1) {
    asm volatile(
        "mma.sync.aligned.m16n8k16.row.col.f32.f16.f16.f32 "
        "{%0,%1,%2,%3}, {%4,%5,%6,%7}, {%8,%9}, {%0,%1,%2,%3};\n"
        : "+f"(c[0]), "+f"(c[1]), "+f"(c[2]), "+f"(c[3])
        : "r"(a0), "r"(a1), "r"(a2), "r"(a3), "r"(b0), "r"(b1));
}
__device__ __forceinline__ void ldsm_x4(unsigned& r0, unsigned& r1,
                                        unsigned& r2, unsigned& r3, unsigned addr) {
    asm volatile("ldmatrix.sync.aligned.m8n8.x4.shared.b16 {%0,%1,%2,%3}, [%4];"
        : "=r"(r0), "=r"(r1), "=r"(r2), "=r"(r3) : "r"(addr));
}
__device__ __forceinline__ void ldsm_x2(unsigned& r0, unsigned& r1, unsigned addr) {
    asm volatile("ldmatrix.sync.aligned.m8n8.x2.shared.b16 {%0,%1}, [%2];"
        : "=r"(r0), "=r"(r1) : "r"(addr));
}
__device__ __forceinline__ void cpa16(void* dst, const void* src) {
    unsigned ds = (unsigned)__cvta_generic_to_shared(dst);
    asm volatile("cp.async.cg.shared.global [%0], [%1], 16;" :: "r"(ds), "l"(src));
}
#define CP_COMMIT asm volatile("cp.async.commit_group;")
#define CP_WAIT1  asm volatile("cp.async.wait_group 1;")
#define CP_WAIT0  asm volatile("cp.async.wait_group 0;")
#define NSTAGE    3

// ---- tf32 k_xl geometry ----
#define A_KN_WORDS 4352          // [32 k][136]
#define B_KN_WORDS 4608          // [128][36]
#define STG_KN     (A_KN_WORDS + B_KN_WORDS)   // 8960 w

// ---- fp16 gemm geometry: rows of 72 halves (144 B) ----
#define HROW_W     36
#define H_OP_WORDS (128*HROW_W)                 // 4608 words per operand
#define STG_H      (2*H_OP_WORDS)               // 9216 words per stage

// tf32 chunk: A [k][136], B [m][36]
#define CHUNK_KN(pA, pB)                                                        \
    _Pragma("unroll")                                                            \
    for (int ks = 0; ks < 4; ks++) {                                             \
        int k8 = ks*8;                                                           \
        unsigned af[4][4], bf[4][2];                                             \
        _Pragma("unroll")                                                        \
        for (int mi = 0; mi < 4; mi++) {                                         \
            int r = wm + mi*16 + g;                                              \
            af[mi][0] = (pA)[(k8+t4  )*136 + r    ];                             \
            af[mi][1] = (pA)[(k8+t4  )*136 + r + 8];                             \
            af[mi][2] = (pA)[(k8+t4+4)*136 + r    ];                             \
            af[mi][3] = (pA)[(k8+t4+4)*136 + r + 8];                             \
        }                                                                        \
        _Pragma("unroll")                                                        \
        for (int ni = 0; ni < 4; ni++) {                                         \
            int rn = wn + ni*8 + g;                                              \
            bf[ni][0] = (pB)[rn*36 + k8+t4    ];                                 \
            bf[ni][1] = (pB)[rn*36 + k8+t4 + 4];                                 \
        }                                                                        \
        _Pragma("unroll")                                                        \
        for (int mi = 0; mi < 4; mi++)                                           \
            _Pragma("unroll")                                                    \
            for (int ni = 0; ni < 4; ni++)                                       \
                mma_tf32(c[mi][ni], af[mi][0], af[mi][1], af[mi][2],             \
                         af[mi][3], bf[ni][0], bf[ni][1]);                       \
    }

// fp16 chunk via ldmatrix. aB/bB are shared-space BYTE addresses of the
// A/B operand tiles ([128 rows][144 B rows]). Fragment mapping verified
// identical to the scalar form (a0..a3 = rows g/g+8 x k 2t4 / 8+2t4).
#define CHUNK_H_LDSM(aB, bB)                                                    \
    {                                                                            \
        unsigned aRow = ((lane>>3)&1)*8 + (lane&7);                              \
        unsigned aK   = (lane>>4)*16;                                            \
        unsigned bRow = (lane&7);                                                \
        unsigned bK   = ((lane>>3)&1)*16;                                        \
        _Pragma("unroll")                                                        \
        for (int ks = 0; ks < 4; ks++) {                                         \
            unsigned af[4][4], bf[4][2];                                         \
            _Pragma("unroll")                                                    \
            for (int mi = 0; mi < 4; mi++)                                       \
                ldsm_x4(af[mi][0], af[mi][1], af[mi][2], af[mi][3],              \
                        (aB) + (wm + mi*16 + aRow)*144 + ks*32 + aK);            \
            _Pragma("unroll")                                                    \
            for (int ni = 0; ni < 4; ni++)                                       \
                ldsm_x2(bf[ni][0], bf[ni][1],                                    \
                        (bB) + (wn + ni*8 + bRow)*144 + ks*32 + bK);             \
            _Pragma("unroll")                                                    \
            for (int mi = 0; mi < 4; mi++)                                       \
                _Pragma("unroll")                                                \
                for (int ni = 0; ni < 4; ni++)                                   \
                    mma_f16(c[mi][ni], af[mi][0], af[mi][1], af[mi][2],          \
                            af[mi][3], bf[ni][0], bf[ni][1]);                    \
        }                                                                        \
    }

// ---------------------------------------------------------------
// K_misc: fused norm + weight converts + pack + barrier reset.
// ---------------------------------------------------------------
__global__ void __launch_bounds__(256) k_misc(const float* __restrict__ emb,
                                              const float* __restrict__ aei,
                                              const float* __restrict__ aej,
                                              const float* __restrict__ w1,
                                              const float* __restrict__ w2,
                                              float* __restrict__ out, int mode) {
    int blk = blockIdx.x, tid = threadIdx.x;
    if (blk == 0 && tid == 0) d_bar = 0;        // reset gemm12 barrier
    if (blk < 256) {
        int half = tid >> 7, t = tid & 127;
        int n = blk*2 + half;
        float w  = emb[n*DD + t];
        float v0 = w*w, v1 = w*aei[t], v2 = w*aej[t];
        #pragma unroll
        for (int o = 16; o; o >>= 1) {
            v0 += __shfl_xor_sync(0xffffffffu, v0, o);
            v1 += __shfl_xor_sync(0xffffffffu, v1, o);
            v2 += __shfl_xor_sync(0xffffffffu, v2, o);
        }
        __shared__ float s0[2][4], s1[2][4], s2[2][4];
        int wid = t >> 5, lane = t & 31;
        if (lane == 0) { s0[half][wid]=v0; s1[half][wid]=v1; s2[half][wid]=v2; }
        __syncthreads();
        if (t == 0) {
            d_rinv[n] = rsqrtf(s0[half][0]+s0[half][1]+s0[half][2]+s0[half][3]);
            d_r[n] = s1[half][0]+s1[half][1]+s1[half][2]+s1[half][3];
            d_s[n] = s2[half][0]+s2[half][1]+s2[half][2]+s2[half][3];
        }
    } else if (blk < 768) {
        int idx = (blk - 256)*256 + tid;
        const int N1 = HIDN*NN/4;
        if (idx < N1) {
            float4 v = *(const float4*)(w1 + (size_t)idx*4);
            __half2* d2 = (__half2*)(d_w116 + (size_t)idx*4);
            d2[0] = __floats2half2_rn(v.x, v.y);
            d2[1] = __floats2half2_rn(v.z, v.w);
        } else {
            int j = idx - N1;
            float4 v = *(const float4*)(w2 + (size_t)j*4);
            __half2* d2 = (__half2*)(d_w216 + (size_t)j*4);
            d2[0] = __floats2half2_rn(v.x, v.y);
            d2[1] = __floats2half2_rn(v.z, v.w);
        }
    } else {
        int i = (blk - 768)*256 + tid;
        const int OUT0 = BB*DD*HIDN;
        if (i < NN*DD) out[OUT0 + i] = emb[i];
        (void)mode;
    }
}

// ---------------------------------------------------------------
// K1: cosine matrix — proven tiled form
// ---------------------------------------------------------------
__global__ void k_cos(const float* __restrict__ emb) {
    __shared__ float sAt[32][68];
    __shared__ float sBt[32][68];
    int i0 = blockIdx.y * 64, j0 = blockIdx.x * 64;
    int tid = threadIdx.x;
    int tx = tid & 15, ty = tid >> 4;
    float c[4][4] = {};
    for (int k0 = 0; k0 < DD; k0 += 32) {
        #pragma unroll
        for (int a = 0; a < 8; a++) {
            int idx = tid + a*256;
            int row = idx >> 5, kk = idx & 31;
            sAt[kk][row] = emb[(i0+row)*DD + k0 + kk];
            sBt[kk][row] = emb[(j0+row)*DD + k0 + kk];
        }
        __syncthreads();
        #pragma unroll
        for (int kk = 0; kk < 32; kk++) {
            float av[4], bv[4];
            *(float4*)av = *(const float4*)&sAt[kk][ty*4];
            *(float4*)bv = *(const float4*)&sBt[kk][tx*4];
            #pragma unroll
            for (int ii = 0; ii < 4; ii++)
                #pragma unroll
                for (int jj = 0; jj < 4; jj++)
                    c[ii][jj] += av[ii]*bv[jj];
        }
        __syncthreads();
    }
    float rj[4];
    #pragma unroll
    for (int jj = 0; jj < 4; jj++) rj[jj] = d_rinv[j0 + tx*4 + jj];
    #pragma unroll
    for (int ii = 0; ii < 4; ii++) {
        float ri = d_rinv[i0 + ty*4 + ii];
        float4 v;
        v.x = c[ii][0]*ri*rj[0]; v.y = c[ii][1]*ri*rj[1];
        v.z = c[ii][2]*ri*rj[2]; v.w = c[ii][3]*ri*rj[3];
        *(float4*)&d_cosm[(i0 + ty*4 + ii)*NN + j0 + tx*4] = v;
    }
}

// ---------------------------------------------------------------
// K2: top-20 per row (+ optional topk pack into out tail)
// ---------------------------------------------------------------
__global__ void k_topk(float* __restrict__ out, int mode) {
    int row  = (blockIdx.x*256 + threadIdx.x) >> 5;
    int lane = threadIdx.x & 31;
    float v[16];
    #pragma unroll
    for (int j = 0; j < 16; j++) v[j] = d_cosm[row*NN + lane + 32*j];
    for (int t = 0; t < KTOP; t++) {
        float bv = v[0]; int bj = 0;
        #pragma unroll
        for (int j = 1; j < 16; j++)
            if (v[j] > bv) { bv = v[j]; bj = j; }
        int bidx = lane + 32*bj;
        #pragma unroll
        for (int o = 16; o; o >>= 1) {
            float ov = __shfl_xor_sync(0xffffffffu, bv, o);
            int   oi = __shfl_xor_sync(0xffffffffu, bidx, o);
            if (ov > bv || (ov == bv && oi < bidx)) { bv = ov; bidx = oi; }
        }
        if (lane == 0) {
            d_topk[row*KTOP + t] = bidx;
            if (mode) out[BB*DD*HIDN + NN*DD + row*KTOP + t] = (float)bidx;
        }
        #pragma unroll
        for (int j = 0; j < 16; j++)
            if (lane + 32*j == bidx) v[j] = -INFINITY;
    }
}

// ---------------------------------------------------------------
// K3: xl (tf32 MMA, 3-stage) + fused p/q epilogue.
// ---------------------------------------------------------------
__global__ void __launch_bounds__(256, 2) k_xl(const float* __restrict__ data,
                                               const float* __restrict__ linw,
                                               const float* __restrict__ ai,
                                               const float* __restrict__ aj) {
    extern __shared__ unsigned smu[];
    __shared__ float spq[DD][2];
    int b = blockIdx.y, n0 = blockIdx.x * 128;
    int tid = threadIdx.x;
    int w = tid >> 5, lane = tid & 31;
    int g = lane >> 2, t4 = lane & 3;
    int wm = (w & 1) * 64, wn = (w >> 1) * 32;
    if (tid < DD) { spq[tid][0] = 0.f; spq[tid][1] = 0.f; }
    float c[4][4][4] = {};

    #define XL_LOAD(st, f0)                                                      \
        {                                                                        \
            unsigned* pA = smu + (st)*STG_KN;                                    \
            unsigned* pB = pA + A_KN_WORDS;                                      \
            _Pragma("unroll")                                                    \
            for (int a = 0; a < 4; a++) {                                        \
                int idx = tid + a*256;                                           \
                int kk = idx >> 5, n4 = idx & 31;                                \
                cpa16(pA + kk*136 + n4*4,                                        \
                      data + ((size_t)b*FIN + (f0) + kk)*NN + n0 + n4*4);        \
            }                                                                    \
            _Pragma("unroll")                                                    \
            for (int a = 0; a < 4; a++) {                                        \
                int idx = tid + a*256;                                           \
                int dd = idx >> 3, k4 = idx & 7;                                 \
                cpa16(pB + dd*36 + k4*4, linw + dd*FIN + (f0) + k4*4);           \
            }                                                                    \
        }

    XL_LOAD(0, 0) CP_COMMIT;
    XL_LOAD(1, 32) CP_COMMIT;
    #pragma unroll 1
    for (int it = 0; it < FIN/32; it++) {
        if (it + 1 < FIN/32) { CP_WAIT1; } else { CP_WAIT0; }
        __syncthreads();
        if (it + 2 < FIN/32) { XL_LOAD((it+2)%NSTAGE, (it+2)*32) CP_COMMIT; }
        unsigned* pA = smu + (it%NSTAGE)*STG_KN;
        unsigned* pB = pA + A_KN_WORDS;
        CHUNK_KN(pA, pB)
    }
    #undef XL_LOAD

    float pv[8] = {}, qv[8] = {};
    #pragma unroll
    for (int mi = 0; mi < 4; mi++)
        #pragma unroll
        for (int ni = 0; ni < 4; ni++) {
            int row = n0 + wm + mi*16 + g, col = wn + ni*8 + t4*2;
            size_t i0 = ((size_t)b*NN + row    )*DD + col;
            size_t i1 = ((size_t)b*NN + row + 8)*DD + col;
            *(__half2*)&d_xl16[i0] = __floats2half2_rn(c[mi][ni][0], c[mi][ni][1]);
            *(__half2*)&d_xl16[i1] = __floats2half2_rn(c[mi][ni][2], c[mi][ni][3]);
            float a0 = ai[col], a1 = ai[col+1];
            float j0 = aj[col], j1 = aj[col+1];
            pv[mi*2  ] += c[mi][ni][0]*a0 + c[mi][ni][1]*a1;
            pv[mi*2+1] += c[mi][ni][2]*a0 + c[mi][ni][3]*a1;
            qv[mi*2  ] += c[mi][ni][0]*j0 + c[mi][ni][1]*j1;
            qv[mi*2+1] += c[mi][ni][2]*j0 + c[mi][ni][3]*j1;
        }
    #pragma unroll
    for (int r = 0; r < 8; r++) {
        pv[r] += __shfl_xor_sync(0xffffffffu, pv[r], 1);
        pv[r] += __shfl_xor_sync(0xffffffffu, pv[r], 2);
        qv[r] += __shfl_xor_sync(0xffffffffu, qv[r], 1);
        qv[r] += __shfl_xor_sync(0xffffffffu, qv[r], 2);
    }
    if (t4 == 0) {
        #pragma unroll
        for (int mi = 0; mi < 4; mi++) {
            int r0 = wm + mi*16 + g;
            atomicAdd(&spq[r0][0],   pv[mi*2]);
            atomicAdd(&spq[r0][1],   qv[mi*2]);
            atomicAdd(&spq[r0+8][0], pv[mi*2+1]);
            atomicAdd(&spq[r0+8][1], qv[mi*2+1]);
        }
    }
    __syncthreads();
    if (tid < 2*DD) {
        int row = tid >> 1, which = tid & 1;
        float v = spq[row][which];
        if (which == 0) d_p[b*NN + n0 + row] = v;
        else            d_q[b*NN + n0 + row] = v;
    }
}

// ---------------------------------------------------------------
// K5: attention with smem-cached xl16 batch slice + gts staging.
// ---------------------------------------------------------------
#define GTS_PITCH 264
__global__ void __launch_bounds__(256, 1) k_attn2(const float* __restrict__ emb,
                                                  const float* __restrict__ gbias,
                                                  const float* __restrict__ gamma,
                                                  const float* __restrict__ beta) {
    extern __shared__ __half smh[];
    __half* xlc = smh;                 // [512][128] fp16 = 131072 B
    __half* gts = smh + NN*DD;         // [128][GTS_PITCH] = 67584 B
    int b = blockIdx.x >> 1, nhalf = blockIdx.x & 1;
    int n0 = nhalf * 256;
    int tid = threadIdx.x, wrp = tid >> 5, lane = tid & 31;

    const __half* src = d_xl16 + (size_t)b*NN*DD;
    #pragma unroll
    for (int a = 0; a < 32; a++) {
        int idx = tid + a*256;
        cpa16(xlc + idx*8, src + idx*8);
    }
    CP_COMMIT; CP_WAIT0;
    __syncthreads();

    const float inv = rsqrtf(1.0f + 1e-5f);
    for (int i = 0; i < 32; i++) {
        int n = n0 + wrp*32 + i;
        int widx = b*NN + n;
        int src_k = 0; float alpha = -1e30f;
        if (lane < KTOP) {
            src_k = d_topk[n*KTOP + lane];
            alpha = d_p[widx] + d_r[n] + d_q[b*NN + src_k] + d_s[src_k];
            alpha = alpha > 0.f ? alpha : 0.2f*alpha;
        }
        float m = alpha;
        #pragma unroll
        for (int o = 16; o; o >>= 1) m = fmaxf(m, __shfl_xor_sync(0xffffffffu, m, o));
        float ex = (lane < KTOP) ? expf(alpha - m) : 0.f;
        float sm = ex;
        #pragma unroll
        for (int o = 16; o; o >>= 1) sm += __shfl_xor_sync(0xffffffffu, sm, o);
        float aw = ex / sm;

        float2 acc0 = {0.f,0.f}, acc1 = {0.f,0.f};
        #pragma unroll
        for (int k = 0; k < KTOP; k++) {
            int   sk = __shfl_sync(0xffffffffu, src_k, k);
            float ak = __shfl_sync(0xffffffffu, aw,  k);
            const __half2* xr = (const __half2*)(xlc + sk*DD);
            float2 f0 = __half22float2(xr[lane]);
            float2 f1 = __half22float2(xr[lane + 32]);
            acc0.x += ak*f0.x; acc0.y += ak*f0.y;
            acc1.x += ak*f1.x; acc1.y += ak*f1.y;
        }
        int d0 = 2*lane, d1 = 2*lane + 64;
        float h0 = fmaxf((acc0.x + gbias[d0  ])*(gamma[d0  ]*inv) + beta[d0  ], 0.f) * emb[n*DD + d0];
        float h1 = fmaxf((acc0.y + gbias[d0+1])*(gamma[d0+1]*inv) + beta[d0+1], 0.f) * emb[n*DD + d0+1];
        float h2 = fmaxf((acc1.x + gbias[d1  ])*(gamma[d1  ]*inv) + beta[d1  ], 0.f) * emb[n*DD + d1];
        float h3 = fmaxf((acc1.y + gbias[d1+1])*(gamma[d1+1]*inv) + beta[d1+1], 0.f) * emb[n*DD + d1+1];
        int nn = n - n0;
        gts[(d0  )*GTS_PITCH + nn] = __float2half(h0);
        gts[(d0+1)*GTS_PITCH + nn] = __float2half(h1);
        gts[(d1  )*GTS_PITCH + nn] = __float2half(h2);
        gts[(d1+1)*GTS_PITCH + nn] = __float2half(h3);
    }
    __syncthreads();
    for (int row = wrp; row < DD; row += 8) {
        *(uint4*)(d_gT16 + ((size_t)b*DD + row)*NN + n0 + lane*8) =
            *(uint4*)(gts + row*GTS_PITCH + lane*8);
    }
}

// ---------------------------------------------------------------
// K67: FUSED gemm1 + global barrier + gemm2, ldmatrix mainloop.
// ---------------------------------------------------------------
__global__ void __launch_bounds__(256, 2) k_gemm12(const float* __restrict__ b2,
                                                   float* __restrict__ out) {
    extern __shared__ unsigned smu[];
    int b = blockIdx.y, h0 = blockIdx.x * 128;
    int tid = threadIdx.x;
    int w = tid >> 5, lane = tid & 31;
    int g = lane >> 2, t4 = lane & 3;
    int wm = (w & 1) * 64, wn = (w >> 1) * 32;
    unsigned smemBase = (unsigned)__cvta_generic_to_shared(smu);

    // ---------------- phase 1: o1 = gT @ w1^T ----------------
    {
        float c[4][4][4] = {};
        #define G1_LOAD(st, k0)                                                  \
            {                                                                    \
                unsigned* pA = smu + (st)*STG_H;                                 \
                unsigned* pB = pA + H_OP_WORDS;                                  \
                _Pragma("unroll")                                                \
                for (int a = 0; a < 4; a++) {                                    \
                    int idx = tid + a*256;                                       \
                    int row = idx >> 3, seg = idx & 7;                           \
                    cpa16(pA + row*HROW_W + seg*4,                               \
                          d_gT16 + ((size_t)b*DD + row)*NN + (k0) + seg*8);      \
                }                                                                \
                _Pragma("unroll")                                                \
                for (int a = 0; a < 4; a++) {                                    \
                    int idx = tid + a*256;                                       \
                    int row = idx >> 3, seg = idx & 7;                           \
                    cpa16(pB + row*HROW_W + seg*4,                               \
                          d_w116 + (size_t)(h0 + row)*NN + (k0) + seg*8);        \
                }                                                                \
            }
        G1_LOAD(0, 0) CP_COMMIT;
        G1_LOAD(1, 64) CP_COMMIT;
        #pragma unroll 1
        for (int it = 0; it < NN/64; it++) {
            if (it + 1 < NN/64) { CP_WAIT1; } else { CP_WAIT0; }
            __syncthreads();
            if (it + 2 < NN/64) { G1_LOAD((it+2)%NSTAGE, (it+2)*64) CP_COMMIT; }
            unsigned aB = smemBase + ((it%NSTAGE)*STG_H)*4;
            unsigned bB = aB + H_OP_WORDS*4;
            CHUNK_H_LDSM(aB, bB)
        }
        #undef G1_LOAD
        #pragma unroll
        for (int mi = 0; mi < 4; mi++)
            #pragma unroll
            for (int ni = 0; ni < 4; ni++) {
                int row = wm + mi*16 + g, col = h0 + wn + ni*8 + t4*2;
                *(__half2*)&d_o116[((size_t)b*DD + row    )*HIDN + col] =
                    __floats2half2_rn(c[mi][ni][0], c[mi][ni][1]);
                *(__half2*)&d_o116[((size_t)b*DD + row + 8)*HIDN + col] =
                    __floats2half2_rn(c[mi][ni][2], c[mi][ni][3]);
            }
    }

    // ---------------- global barrier (all 256 CTAs) ----------------
    __syncthreads();
    __threadfence();
    if (tid == 0) {
        atomicAdd(&d_bar, 1);
        while (*(volatile int*)&d_bar < 256) { }
    }
    __syncthreads();
    __threadfence();

    // ---------------- phase 2: out = sigmoid(o1 @ w2^T + b2) -------
    {
        int h20 = h0;
        float c[4][4][4] = {};
        #define G2_LOAD(st, k0)                                                  \
            {                                                                    \
                unsigned* pA = smu + (st)*STG_H;                                 \
                unsigned* pB = pA + H_OP_WORDS;                                  \
                _Pragma("unroll")                                                \
                for (int a = 0; a < 4; a++) {                                    \
                    int idx = tid + a*256;                                       \
                    int row = idx >> 3, seg = idx & 7;                           \
                    cpa16(pA + row*HROW_W + seg*4,                               \
                          d_o116 + ((size_t)b*DD + row)*HIDN + (k0) + seg*8);    \
                }                                                                \
                _Pragma("unroll")                                                \
                for (int a = 0; a < 4; a++) {                                    \
                    int idx = tid + a*256;                                       \
                    int row = idx >> 3, seg = idx & 7;                           \
                    cpa16(pB + row*HROW_W + seg*4,                               \
                          d_w216 + (size_t)(h20 + row)*HIDN + (k0) + seg*8);     \
                }                                                                \
            }
        G2_LOAD(0, 0) CP_COMMIT;
        G2_LOAD(1, 64) CP_COMMIT;
        #pragma unroll 1
        for (int it = 0; it < HIDN/64; it++) {
            if (it + 1 < HIDN/64) { CP_WAIT1; } else { CP_WAIT0; }
            __syncthreads();
            if (it + 2 < HIDN/64) { G2_LOAD((it+2)%NSTAGE, (it+2)*64) CP_COMMIT; }
            unsigned aB = smemBase + ((it%NSTAGE)*STG_H)*4;
            unsigned bB = aB + H_OP_WORDS*4;
            CHUNK_H_LDSM(aB, bB)
        }
        #undef G2_LOAD
        #pragma unroll
        for (int mi = 0; mi < 4; mi++)
            #pragma unroll
            for (int ni = 0; ni < 4; ni++) {
                int row = wm + mi*16 + g, col = h20 + wn + ni*8 + t4*2;
                float bb0 = b2[col], bb1 = b2[col + 1];
                float2 v0, v1;
                v0.x = 1.0f/(1.0f + expf(-(c[mi][ni][0] + bb0)));
                v0.y = 1.0f/(1.0f + expf(-(c[mi][ni][1] + bb1)));
                v1.x = 1.0f/(1.0f + expf(-(c[mi][ni][2] + bb0)));
                v1.y = 1.0f/(1.0f + expf(-(c[mi][ni][3] + bb1)));
                *(float2*)&out[((size_t)b*DD + row    )*HIDN + col] = v0;
                *(float2*)&out[((size_t)b*DD + row + 8)*HIDN + col] = v1;
            }
    }
}

extern "C" void kernel_launch(void* const* d_in, const int* in_sizes, int n_in,
                              void* d_out, int out_size) {
    const float* data  = (const float*)d_in[0];
    const float* emb   = (const float*)d_in[1];
    const float* linw  = (const float*)d_in[2];
    const float* ai    = (const float*)d_in[3];
    const float* aj    = (const float*)d_in[4];
    const float* aei   = (const float*)d_in[5];
    const float* aej   = (const float*)d_in[6];
    const float* gbias = (const float*)d_in[7];
    const float* gamma = (const float*)d_in[8];
    const float* beta  = (const float*)d_in[9];
    const float* w1    = (const float*)d_in[10];
    const float* w2    = (const float*)d_in[11];
    const float* b2    = (const float*)d_in[12];
    float* out = (float*)d_out;

    static cudaStream_t s2 = nullptr;
    static cudaEvent_t evFork = nullptr, evJoin = nullptr;
    static bool init_done = false;
    const int smem_kn   = NSTAGE*STG_KN*4;           // 107520 B
    const int smem_h    = NSTAGE*STG_H*4;            // 110592 B
    const int smem_attn = (NN*DD + DD*GTS_PITCH)*2;  // 198656 B
    if (!init_done) {
        cudaFuncSetAttribute(k_xl,     cudaFuncAttributeMaxDynamicSharedMemorySize, smem_kn);
        cudaFuncSetAttribute(k_gemm12, cudaFuncAttributeMaxDynamicSharedMemorySize, smem_h);
        cudaFuncSetAttribute(k_attn2,  cudaFuncAttributeMaxDynamicSharedMemorySize, smem_attn);
        cudaStreamCreateWithFlags(&s2, cudaStreamNonBlocking);
        cudaEventCreateWithFlags(&evFork, cudaEventDisableTiming);
        cudaEventCreateWithFlags(&evJoin, cudaEventDisableTiming);
        init_done = true;
    }

    const int OUT0 = BB*DD*HIDN;
    int tail = (out_size >= OUT0 + NN*DD) ? 1 : 0;
    int mode = (out_size >= OUT0 + NN*DD + NN*KTOP) ? 1 : 0;

    cudaEventRecord(evFork, 0);
    cudaStreamWaitEvent(s2, evFork, 0);

    int misc_blocks = 768 + (tail ? 256 : 0);
    k_misc<<<misc_blocks, 256, 0, s2>>>(emb, aei, aej, w1, w2, out, mode);
    k_cos <<<dim3(8, 8), 256, 0, s2>>>(emb);
    k_topk<<<NN/8, 256, 0, s2>>>(out, mode);
    cudaEventRecord(evJoin, s2);

    k_xl<<<dim3(4, BB), 256, smem_kn>>>(data, linw, ai, aj);

    cudaStreamWaitEvent(0, evJoin, 0);
    k_attn2<<<2*BB, 256, smem_attn>>>(emb, gbias, gamma, beta);
    k_gemm12<<<dim3(4, BB), 256, smem_h>>>(b2, out);
}

// round 15
// speedup vs baseline: 1.4889x; 1.0910x over previous
#include <cuda_runtime.h>
#include <cuda_fp16.h>
#include <math.h>

#define BB   64
#define NN   512
#define FIN  256
#define DD   128
#define KTOP 20
#define HIDN 512

// ---- scratch (device globals; no allocations) ----
static __device__ __half d_xl16[BB*NN*DD];     // [b,n,d] lin(x), fp16
static __device__ __half d_gT16[BB*DD*NN];     // [b,d,n] gated GCN output (transposed), fp16
static __device__ __half d_o116[BB*DD*HIDN];   // [b,d,h] first linear, fp16
static __device__ __half d_w116[HIDN*NN];      // w1 fp16
static __device__ __half d_w216[HIDN*HIDN];    // w2 fp16
static __device__ float  d_p [BB*NN];
static __device__ float  d_q [BB*NN];
static __device__ float  d_rinv[NN];
static __device__ float  d_r [NN];
static __device__ float  d_s [NN];
static __device__ float  d_cosm[NN*NN];
static __device__ int    d_topk[NN*KTOP];
static __device__ int    d_bar;                // global barrier for k_gemm12

// ---------------- MMA / cp.async / ldmatrix helpers ----------------
__device__ __forceinline__ void mma_tf32(float c[4],
        unsigned a0, unsigned a1, unsigned a2, unsigned a3,
        unsigned b0, unsigned b1) {
    asm volatile(
        "mma.sync.aligned.m16n8k8.row.col.f32.tf32.tf32.f32 "
        "{%0,%1,%2,%3}, {%4,%5,%6,%7}, {%8,%9}, {%0,%1,%2,%3};\n"
        : "+f"(c[0]), "+f"(c[1]), "+f"(c[2]), "+f"(c[3])
        : "r"(a0), "r"(a1), "r"(a2), "r"(a3), "r"(b0), "r"(b1));
}
__device__ __forceinline__ void mma_f16(float c[4],
        unsigned a0, unsigned a1, unsigned a2, unsigned a3,
        unsigned b0, unsigned b1) {
    asm volatile(
        "mma.sync.aligned.m16n8k16.row.col.f32.f16.f16.f32 "
        "{%0,%1,%2,%3}, {%4,%5,%6,%7}, {%8,%9}, {%0,%1,%2,%3};\n"
        : "+f"(c[0]), "+f"(c[1]), "+f"(c[2]), "+f"(c[3])
        : "r"(a0), "r"(a1), "r"(a2), "r"(a3), "r"(b0), "r"(b1));
}
__device__ __forceinline__ void ldsm_x4(unsigned& r0, unsigned& r1,
                                        unsigned& r2, unsigned& r3, unsigned addr) {
    asm volatile("ldmatrix.sync.aligned.m8n8.x4.shared.b16 {%0,%1,%2,%3}, [%4];"
        : "=r"(r0), "=r"(r1), "=r"(r2), "=r"(r3) : "r"(addr));
}
__device__ __forceinline__ void ldsm_x2(unsigned& r0, unsigned& r1, unsigned addr) {
    asm volatile("ldmatrix.sync.aligned.m8n8.x2.shared.b16 {%0,%1}, [%2];"
        : "=r"(r0), "=r"(r1) : "r"(addr));
}
__device__ __forceinline__ void cpa16(void* dst, const void* src) {
    unsigned ds = (unsigned)__cvta_generic_to_shared(dst);
    asm volatile("cp.async.cg.shared.global [%0], [%1], 16;" :: "r"(ds), "l"(src));
}
#define CP_COMMIT asm volatile("cp.async.commit_group;")
#define CP_WAIT1  asm volatile("cp.async.wait_group 1;")
#define CP_WAIT0  asm volatile("cp.async.wait_group 0;")
#define NSTAGE    3

// ---- tf32 k_xl geometry ----
#define A_KN_WORDS 4352          // [32 k][136]
#define B_KN_WORDS 4608          // [128][36]
#define STG_KN     (A_KN_WORDS + B_KN_WORDS)   // 8960 w

// ---- fp16 gemm geometry: rows of 72 halves (144 B) ----
#define HROW_W     36
#define H_OP_WORDS (128*HROW_W)                 // 4608 words per operand
#define STG_H      (2*H_OP_WORDS)               // 9216 words per stage

// tf32 chunk: A [k][136], B [m][36]
#define CHUNK_KN(pA, pB)                                                        \
    _Pragma("unroll")                                                            \
    for (int ks = 0; ks < 4; ks++) {                                             \
        int k8 = ks*8;                                                           \
        unsigned af[4][4], bf[4][2];                                             \
        _Pragma("unroll")                                                        \
        for (int mi = 0; mi < 4; mi++) {                                         \
            int r = wm + mi*16 + g;                                              \
            af[mi][0] = (pA)[(k8+t4  )*136 + r    ];                             \
            af[mi][1] = (pA)[(k8+t4  )*136 + r + 8];                             \
            af[mi][2] = (pA)[(k8+t4+4)*136 + r    ];                             \
            af[mi][3] = (pA)[(k8+t4+4)*136 + r + 8];                             \
        }                                                                        \
        _Pragma("unroll")                                                        \
        for (int ni = 0; ni < 4; ni++) {                                         \
            int rn = wn + ni*8 + g;                                              \
            bf[ni][0] = (pB)[rn*36 + k8+t4    ];                                 \
            bf[ni][1] = (pB)[rn*36 + k8+t4 + 4];                                 \
        }                                                                        \
        _Pragma("unroll")                                                        \
        for (int mi = 0; mi < 4; mi++)                                           \
            _Pragma("unroll")                                                    \
            for (int ni = 0; ni < 4; ni++)                                       \
                mma_tf32(c[mi][ni], af[mi][0], af[mi][1], af[mi][2],             \
                         af[mi][3], bf[ni][0], bf[ni][1]);                       \
    }

// fp16 chunk via ldmatrix (mapping verified vs scalar form).
#define CHUNK_H_LDSM(aB, bB)                                                    \
    {                                                                            \
        unsigned aRow = ((lane>>3)&1)*8 + (lane&7);                              \
        unsigned aK   = (lane>>4)*16;                                            \
        unsigned bRow = (lane&7);                                                \
        unsigned bK   = ((lane>>3)&1)*16;                                        \
        _Pragma("unroll")                                                        \
        for (int ks = 0; ks < 4; ks++) {                                         \
            unsigned af[4][4], bf[4][2];                                         \
            _Pragma("unroll")                                                    \
            for (int mi = 0; mi < 4; mi++)                                       \
                ldsm_x4(af[mi][0], af[mi][1], af[mi][2], af[mi][3],              \
                        (aB) + (wm + mi*16 + aRow)*144 + ks*32 + aK);            \
            _Pragma("unroll")                                                    \
            for (int ni = 0; ni < 4; ni++)                                       \
                ldsm_x2(bf[ni][0], bf[ni][1],                                    \
                        (bB) + (wn + ni*8 + bRow)*144 + ks*32 + bK);             \
            _Pragma("unroll")                                                    \
            for (int mi = 0; mi < 4; mi++)                                       \
                _Pragma("unroll")                                                \
                for (int ni = 0; ni < 4; ni++)                                   \
                    mma_f16(c[mi][ni], af[mi][0], af[mi][1], af[mi][2],          \
                            af[mi][3], bf[ni][0], bf[ni][1]);                    \
        }                                                                        \
    }

// ---------------------------------------------------------------
// K_misc: fused norm + weight converts + pack + barrier reset.
// ---------------------------------------------------------------
__global__ void __launch_bounds__(256) k_misc(const float* __restrict__ emb,
                                              const float* __restrict__ aei,
                                              const float* __restrict__ aej,
                                              const float* __restrict__ w1,
                                              const float* __restrict__ w2,
                                              float* __restrict__ out, int mode) {
    int blk = blockIdx.x, tid = threadIdx.x;
    if (blk == 0 && tid == 0) d_bar = 0;        // reset gemm12 barrier
    if (blk < 256) {
        int half = tid >> 7, t = tid & 127;
        int n = blk*2 + half;
        float w  = emb[n*DD + t];
        float v0 = w*w, v1 = w*aei[t], v2 = w*aej[t];
        #pragma unroll
        for (int o = 16; o; o >>= 1) {
            v0 += __shfl_xor_sync(0xffffffffu, v0, o);
            v1 += __shfl_xor_sync(0xffffffffu, v1, o);
            v2 += __shfl_xor_sync(0xffffffffu, v2, o);
        }
        __shared__ float s0[2][4], s1[2][4], s2[2][4];
        int wid = t >> 5, lane = t & 31;
        if (lane == 0) { s0[half][wid]=v0; s1[half][wid]=v1; s2[half][wid]=v2; }
        __syncthreads();
        if (t == 0) {
            d_rinv[n] = rsqrtf(s0[half][0]+s0[half][1]+s0[half][2]+s0[half][3]);
            d_r[n] = s1[half][0]+s1[half][1]+s1[half][2]+s1[half][3];
            d_s[n] = s2[half][0]+s2[half][1]+s2[half][2]+s2[half][3];
        }
    } else if (blk < 768) {
        int idx = (blk - 256)*256 + tid;
        const int N1 = HIDN*NN/4;
        if (idx < N1) {
            float4 v = *(const float4*)(w1 + (size_t)idx*4);
            __half2* d2 = (__half2*)(d_w116 + (size_t)idx*4);
            d2[0] = __floats2half2_rn(v.x, v.y);
            d2[1] = __floats2half2_rn(v.z, v.w);
        } else {
            int j = idx - N1;
            float4 v = *(const float4*)(w2 + (size_t)j*4);
            __half2* d2 = (__half2*)(d_w216 + (size_t)j*4);
            d2[0] = __floats2half2_rn(v.x, v.y);
            d2[1] = __floats2half2_rn(v.z, v.w);
        }
    } else {
        int i = (blk - 768)*256 + tid;
        const int OUT0 = BB*DD*HIDN;
        if (i < NN*DD) out[OUT0 + i] = emb[i];
        (void)mode;
    }
}

// ---------------------------------------------------------------
// K1: cosine matrix — 32(i) x 64(j) tiles, grid (8,16) = 128 CTAs
//     (same fp32 arithmetic; 2x the parallelism of the 64x64 form)
// ---------------------------------------------------------------
__global__ void __launch_bounds__(256) k_cos(const float* __restrict__ emb) {
    __shared__ float sAt[32][36];   // [k][i32]
    __shared__ float sBt[32][68];   // [k][j64]
    int i0 = blockIdx.y * 32, j0 = blockIdx.x * 64;
    int tid = threadIdx.x;
    int tx = tid & 15, ty = tid >> 4;    // tx: 4 j's, ty: 2 i's
    float c[2][4] = {};
    for (int k0 = 0; k0 < DD; k0 += 32) {
        #pragma unroll
        for (int a = 0; a < 4; a++) {        // sAt: 32k x 32i = 1024
            int idx = tid + a*256;
            int row = idx >> 5, kk = idx & 31;
            sAt[kk][row] = emb[(i0+row)*DD + k0 + kk];
        }
        #pragma unroll
        for (int a = 0; a < 8; a++) {        // sBt: 32k x 64j = 2048
            int idx = tid + a*256;
            int row = idx >> 5, kk = idx & 31;
            sBt[kk][row] = emb[(j0+row)*DD + k0 + kk];
        }
        __syncthreads();
        #pragma unroll
        for (int kk = 0; kk < 32; kk++) {
            float av[2], bv[4];
            *(float2*)av = *(const float2*)&sAt[kk][ty*2];
            *(float4*)bv = *(const float4*)&sBt[kk][tx*4];
            #pragma unroll
            for (int ii = 0; ii < 2; ii++)
                #pragma unroll
                for (int jj = 0; jj < 4; jj++)
                    c[ii][jj] += av[ii]*bv[jj];
        }
        __syncthreads();
    }
    float rj[4];
    #pragma unroll
    for (int jj = 0; jj < 4; jj++) rj[jj] = d_rinv[j0 + tx*4 + jj];
    #pragma unroll
    for (int ii = 0; ii < 2; ii++) {
        float ri = d_rinv[i0 + ty*2 + ii];
        float4 v;
        v.x = c[ii][0]*ri*rj[0]; v.y = c[ii][1]*ri*rj[1];
        v.z = c[ii][2]*ri*rj[2]; v.w = c[ii][3]*ri*rj[3];
        *(float4*)&d_cosm[(i0 + ty*2 + ii)*NN + j0 + tx*4] = v;
    }
}

// ---------------------------------------------------------------
// K2: top-20 per row (+ optional topk pack into out tail)
// ---------------------------------------------------------------
__global__ void k_topk(float* __restrict__ out, int mode) {
    int row  = (blockIdx.x*256 + threadIdx.x) >> 5;
    int lane = threadIdx.x & 31;
    float v[16];
    #pragma unroll
    for (int j = 0; j < 16; j++) v[j] = d_cosm[row*NN + lane + 32*j];
    for (int t = 0; t < KTOP; t++) {
        float bv = v[0]; int bj = 0;
        #pragma unroll
        for (int j = 1; j < 16; j++)
            if (v[j] > bv) { bv = v[j]; bj = j; }
        int bidx = lane + 32*bj;
        #pragma unroll
        for (int o = 16; o; o >>= 1) {
            float ov = __shfl_xor_sync(0xffffffffu, bv, o);
            int   oi = __shfl_xor_sync(0xffffffffu, bidx, o);
            if (ov > bv || (ov == bv && oi < bidx)) { bv = ov; bidx = oi; }
        }
        if (lane == 0) {
            d_topk[row*KTOP + t] = bidx;
            if (mode) out[BB*DD*HIDN + NN*DD + row*KTOP + t] = (float)bidx;
        }
        #pragma unroll
        for (int j = 0; j < 16; j++)
            if (lane + 32*j == bidx) v[j] = -INFINITY;
    }
}

// ---------------------------------------------------------------
// K3: xl (tf32 MMA, 3-stage) + fused p/q epilogue.
// ---------------------------------------------------------------
__global__ void __launch_bounds__(256, 2) k_xl(const float* __restrict__ data,
                                               const float* __restrict__ linw,
                                               const float* __restrict__ ai,
                                               const float* __restrict__ aj) {
    extern __shared__ unsigned smu[];
    __shared__ float spq[DD][2];
    int b = blockIdx.y, n0 = blockIdx.x * 128;
    int tid = threadIdx.x;
    int w = tid >> 5, lane = tid & 31;
    int g = lane >> 2, t4 = lane & 3;
    int wm = (w & 1) * 64, wn = (w >> 1) * 32;
    if (tid < DD) { spq[tid][0] = 0.f; spq[tid][1] = 0.f; }
    float c[4][4][4] = {};

    #define XL_LOAD(st, f0)                                                      \
        {                                                                        \
            unsigned* pA = smu + (st)*STG_KN;                                    \
            unsigned* pB = pA + A_KN_WORDS;                                      \
            _Pragma("unroll")                                                    \
            for (int a = 0; a < 4; a++) {                                        \
                int idx = tid + a*256;                                           \
                int kk = idx >> 5, n4 = idx & 31;                                \
                cpa16(pA + kk*136 + n4*4,                                        \
                      data + ((size_t)b*FIN + (f0) + kk)*NN + n0 + n4*4);        \
            }                                                                    \
            _Pragma("unroll")                                                    \
            for (int a = 0; a < 4; a++) {                                        \
                int idx = tid + a*256;                                           \
                int dd = idx >> 3, k4 = idx & 7;                                 \
                cpa16(pB + dd*36 + k4*4, linw + dd*FIN + (f0) + k4*4);           \
            }                                                                    \
        }

    XL_LOAD(0, 0) CP_COMMIT;
    XL_LOAD(1, 32) CP_COMMIT;
    #pragma unroll 1
    for (int it = 0; it < FIN/32; it++) {
        if (it + 1 < FIN/32) { CP_WAIT1; } else { CP_WAIT0; }
        __syncthreads();
        if (it + 2 < FIN/32) { XL_LOAD((it+2)%NSTAGE, (it+2)*32) CP_COMMIT; }
        unsigned* pA = smu + (it%NSTAGE)*STG_KN;
        unsigned* pB = pA + A_KN_WORDS;
        CHUNK_KN(pA, pB)
    }
    #undef XL_LOAD

    float pv[8] = {}, qv[8] = {};
    #pragma unroll
    for (int mi = 0; mi < 4; mi++)
        #pragma unroll
        for (int ni = 0; ni < 4; ni++) {
            int row = n0 + wm + mi*16 + g, col = wn + ni*8 + t4*2;
            size_t i0 = ((size_t)b*NN + row    )*DD + col;
            size_t i1 = ((size_t)b*NN + row + 8)*DD + col;
            *(__half2*)&d_xl16[i0] = __floats2half2_rn(c[mi][ni][0], c[mi][ni][1]);
            *(__half2*)&d_xl16[i1] = __floats2half2_rn(c[mi][ni][2], c[mi][ni][3]);
            float a0 = ai[col], a1 = ai[col+1];
            float j0 = aj[col], j1 = aj[col+1];
            pv[mi*2  ] += c[mi][ni][0]*a0 + c[mi][ni][1]*a1;
            pv[mi*2+1] += c[mi][ni][2]*a0 + c[mi][ni][3]*a1;
            qv[mi*2  ] += c[mi][ni][0]*j0 + c[mi][ni][1]*j1;
            qv[mi*2+1] += c[mi][ni][2]*j0 + c[mi][ni][3]*j1;
        }
    #pragma unroll
    for (int r = 0; r < 8; r++) {
        pv[r] += __shfl_xor_sync(0xffffffffu, pv[r], 1);
        pv[r] += __shfl_xor_sync(0xffffffffu, pv[r], 2);
        qv[r] += __shfl_xor_sync(0xffffffffu, qv[r], 1);
        qv[r] += __shfl_xor_sync(0xffffffffu, qv[r], 2);
    }
    if (t4 == 0) {
        #pragma unroll
        for (int mi = 0; mi < 4; mi++) {
            int r0 = wm + mi*16 + g;
            atomicAdd(&spq[r0][0],   pv[mi*2]);
            atomicAdd(&spq[r0][1],   qv[mi*2]);
            atomicAdd(&spq[r0+8][0], pv[mi*2+1]);
            atomicAdd(&spq[r0+8][1], qv[mi*2+1]);
        }
    }
    __syncthreads();
    if (tid < 2*DD) {
        int row = tid >> 1, which = tid & 1;
        float v = spq[row][which];
        if (which == 0) d_p[b*NN + n0 + row] = v;
        else            d_q[b*NN + n0 + row] = v;
    }
}

// ---------------------------------------------------------------
// K5: attention with smem-cached xl16 batch slice + gts staging.
// ---------------------------------------------------------------
#define GTS_PITCH 264
__global__ void __launch_bounds__(256, 1) k_attn2(const float* __restrict__ emb,
                                                  const float* __restrict__ gbias,
                                                  const float* __restrict__ gamma,
                                                  const float* __restrict__ beta) {
    extern __shared__ __half smh[];
    __half* xlc = smh;                 // [512][128] fp16 = 131072 B
    __half* gts = smh + NN*DD;         // [128][GTS_PITCH] = 67584 B
    int b = blockIdx.x >> 1, nhalf = blockIdx.x & 1;
    int n0 = nhalf * 256;
    int tid = threadIdx.x, wrp = tid >> 5, lane = tid & 31;

    const __half* src = d_xl16 + (size_t)b*NN*DD;
    #pragma unroll
    for (int a = 0; a < 32; a++) {
        int idx = tid + a*256;
        cpa16(xlc + idx*8, src + idx*8);
    }
    CP_COMMIT; CP_WAIT0;
    __syncthreads();

    const float inv = rsqrtf(1.0f + 1e-5f);
    for (int i = 0; i < 32; i++) {
        int n = n0 + wrp*32 + i;
        int widx = b*NN + n;
        int src_k = 0; float alpha = -1e30f;
        if (lane < KTOP) {
            src_k = d_topk[n*KTOP + lane];
            alpha = d_p[widx] + d_r[n] + d_q[b*NN + src_k] + d_s[src_k];
            alpha = alpha > 0.f ? alpha : 0.2f*alpha;
        }
        float m = alpha;
        #pragma unroll
        for (int o = 16; o; o >>= 1) m = fmaxf(m, __shfl_xor_sync(0xffffffffu, m, o));
        float ex = (lane < KTOP) ? __expf(alpha - m) : 0.f;
        float sm = ex;
        #pragma unroll
        for (int o = 16; o; o >>= 1) sm += __shfl_xor_sync(0xffffffffu, sm, o);
        float aw = __fdividef(ex, sm);

        float2 acc0 = {0.f,0.f}, acc1 = {0.f,0.f};
        #pragma unroll
        for (int k = 0; k < KTOP; k++) {
            int   sk = __shfl_sync(0xffffffffu, src_k, k);
            float ak = __shfl_sync(0xffffffffu, aw,  k);
            const __half2* xr = (const __half2*)(xlc + sk*DD);
            float2 f0 = __half22float2(xr[lane]);
            float2 f1 = __half22float2(xr[lane + 32]);
            acc0.x += ak*f0.x; acc0.y += ak*f0.y;
            acc1.x += ak*f1.x; acc1.y += ak*f1.y;
        }
        int d0 = 2*lane, d1 = 2*lane + 64;
        float h0 = fmaxf((acc0.x + gbias[d0  ])*(gamma[d0  ]*inv) + beta[d0  ], 0.f) * emb[n*DD + d0];
        float h1 = fmaxf((acc0.y + gbias[d0+1])*(gamma[d0+1]*inv) + beta[d0+1], 0.f) * emb[n*DD + d0+1];
        float h2 = fmaxf((acc1.x + gbias[d1  ])*(gamma[d1  ]*inv) + beta[d1  ], 0.f) * emb[n*DD + d1];
        float h3 = fmaxf((acc1.y + gbias[d1+1])*(gamma[d1+1]*inv) + beta[d1+1], 0.f) * emb[n*DD + d1+1];
        int nn = n - n0;
        gts[(d0  )*GTS_PITCH + nn] = __float2half(h0);
        gts[(d0+1)*GTS_PITCH + nn] = __float2half(h1);
        gts[(d1  )*GTS_PITCH + nn] = __float2half(h2);
        gts[(d1+1)*GTS_PITCH + nn] = __float2half(h3);
    }
    __syncthreads();
    for (int row = wrp; row < DD; row += 8) {
        *(uint4*)(d_gT16 + ((size_t)b*DD + row)*NN + n0 + lane*8) =
            *(uint4*)(gts + row*GTS_PITCH + lane*8);
    }
}

// ---------------------------------------------------------------
// K67: FUSED gemm1 + global barrier + gemm2, ldmatrix mainloop.
// ---------------------------------------------------------------
__global__ void __launch_bounds__(256, 2) k_gemm12(const float* __restrict__ b2,
                                                   float* __restrict__ out) {
    extern __shared__ unsigned smu[];
    int b = blockIdx.y, h0 = blockIdx.x * 128;
    int tid = threadIdx.x;
    int w = tid >> 5, lane = tid & 31;
    int g = lane >> 2, t4 = lane & 3;
    int wm = (w & 1) * 64, wn = (w >> 1) * 32;
    unsigned smemBase = (unsigned)__cvta_generic_to_shared(smu);

    // ---------------- phase 1: o1 = gT @ w1^T ----------------
    {
        float c[4][4][4] = {};
        #define G1_LOAD(st, k0)                                                  \
            {                                                                    \
                unsigned* pA = smu + (st)*STG_H;                                 \
                unsigned* pB = pA + H_OP_WORDS;                                  \
                _Pragma("unroll")                                                \
                for (int a = 0; a < 4; a++) {                                    \
                    int idx = tid + a*256;                                       \
                    int row = idx >> 3, seg = idx & 7;                           \
                    cpa16(pA + row*HROW_W + seg*4,                               \
                          d_gT16 + ((size_t)b*DD + row)*NN + (k0) + seg*8);      \
                }                                                                \
                _Pragma("unroll")                                                \
                for (int a = 0; a < 4; a++) {                                    \
                    int idx = tid + a*256;                                       \
                    int row = idx >> 3, seg = idx & 7;                           \
                    cpa16(pB + row*HROW_W + seg*4,                               \
                          d_w116 + (size_t)(h0 + row)*NN + (k0) + seg*8);        \
                }                                                                \
            }
        G1_LOAD(0, 0) CP_COMMIT;
        G1_LOAD(1, 64) CP_COMMIT;
        #pragma unroll 1
        for (int it = 0; it < NN/64; it++) {
            if (it + 1 < NN/64) { CP_WAIT1; } else { CP_WAIT0; }
            __syncthreads();
            if (it + 2 < NN/64) { G1_LOAD((it+2)%NSTAGE, (it+2)*64) CP_COMMIT; }
            unsigned aB = smemBase + ((it%NSTAGE)*STG_H)*4;
            unsigned bB = aB + H_OP_WORDS*4;
            CHUNK_H_LDSM(aB, bB)
        }
        #undef G1_LOAD
        #pragma unroll
        for (int mi = 0; mi < 4; mi++)
            #pragma unroll
            for (int ni = 0; ni < 4; ni++) {
                int row = wm + mi*16 + g, col = h0 + wn + ni*8 + t4*2;
                *(__half2*)&d_o116[((size_t)b*DD + row    )*HIDN + col] =
                    __floats2half2_rn(c[mi][ni][0], c[mi][ni][1]);
                *(__half2*)&d_o116[((size_t)b*DD + row + 8)*HIDN + col] =
                    __floats2half2_rn(c[mi][ni][2], c[mi][ni][3]);
            }
    }

    // ---------------- global barrier (all 256 CTAs) ----------------
    __syncthreads();
    __threadfence();
    if (tid == 0) {
        atomicAdd(&d_bar, 1);
        while (*(volatile int*)&d_bar < 256) { }
    }
    __syncthreads();
    __threadfence();

    // ---------------- phase 2: out = sigmoid(o1 @ w2^T + b2) -------
    {
        int h20 = h0;
        float c[4][4][4] = {};
        #define G2_LOAD(st, k0)                                                  \
            {                                                                    \
                unsigned* pA = smu + (st)*STG_H;                                 \
                unsigned* pB = pA + H_OP_WORDS;                                  \
                _Pragma("unroll")                                                \
                for (int a = 0; a < 4; a++) {                                    \
                    int idx = tid + a*256;                                       \
                    int row = idx >> 3, seg = idx & 7;                           \
                    cpa16(pA + row*HROW_W + seg*4,                               \
                          d_o116 + ((size_t)b*DD + row)*HIDN + (k0) + seg*8);    \
                }                                                                \
                _Pragma("unroll")                                                \
                for (int a = 0; a < 4; a++) {                                    \
                    int idx = tid + a*256;                                       \
                    int row = idx >> 3, seg = idx & 7;                           \
                    cpa16(pB + row*HROW_W + seg*4,                               \
                          d_w216 + (size_t)(h20 + row)*HIDN + (k0) + seg*8);     \
                }                                                                \
            }
        G2_LOAD(0, 0) CP_COMMIT;
        G2_LOAD(1, 64) CP_COMMIT;
        #pragma unroll 1
        for (int it = 0; it < HIDN/64; it++) {
            if (it + 1 < HIDN/64) { CP_WAIT1; } else { CP_WAIT0; }
            __syncthreads();
            if (it + 2 < HIDN/64) { G2_LOAD((it+2)%NSTAGE, (it+2)*64) CP_COMMIT; }
            unsigned aB = smemBase + ((it%NSTAGE)*STG_H)*4;
            unsigned bB = aB + H_OP_WORDS*4;
            CHUNK_H_LDSM(aB, bB)
        }
        #undef G2_LOAD
        #pragma unroll
        for (int mi = 0; mi < 4; mi++)
            #pragma unroll
            for (int ni = 0; ni < 4; ni++) {
                int row = wm + mi*16 + g, col = h20 + wn + ni*8 + t4*2;
                float bb0 = b2[col], bb1 = b2[col + 1];
                float2 v0, v1;
                v0.x = __fdividef(1.0f, 1.0f + __expf(-(c[mi][ni][0] + bb0)));
                v0.y = __fdividef(1.0f, 1.0f + __expf(-(c[mi][ni][1] + bb1)));
                v1.x = __fdividef(1.0f, 1.0f + __expf(-(c[mi][ni][2] + bb0)));
                v1.y = __fdividef(1.0f, 1.0f + __expf(-(c[mi][ni][3] + bb1)));
                *(float2*)&out[((size_t)b*DD + row    )*HIDN + col] = v0;
                *(float2*)&out[((size_t)b*DD + row + 8)*HIDN + col] = v1;
            }
    }
}

extern "C" void kernel_launch(void* const* d_in, const int* in_sizes, int n_in,
                              void* d_out, int out_size) {
    const float* data  = (const float*)d_in[0];
    const float* emb   = (const float*)d_in[1];
    const float* linw  = (const float*)d_in[2];
    const float* ai    = (const float*)d_in[3];
    const float* aj    = (const float*)d_in[4];
    const float* aei   = (const float*)d_in[5];
    const float* aej   = (const float*)d_in[6];
    const float* gbias = (const float*)d_in[7];
    const float* gamma = (const float*)d_in[8];
    const float* beta  = (const float*)d_in[9];
    const float* w1    = (const float*)d_in[10];
    const float* w2    = (const float*)d_in[11];
    const float* b2    = (const float*)d_in[12];
    float* out = (float*)d_out;

    static cudaStream_t s2 = nullptr;
    static cudaEvent_t evFork = nullptr, evJoin = nullptr;
    static bool init_done = false;
    const int smem_kn   = NSTAGE*STG_KN*4;           // 107520 B
    const int smem_h    = NSTAGE*STG_H*4;            // 110592 B
    const int smem_attn = (NN*DD + DD*GTS_PITCH)*2;  // 198656 B
    if (!init_done) {
        cudaFuncSetAttribute(k_xl,     cudaFuncAttributeMaxDynamicSharedMemorySize, smem_kn);
        cudaFuncSetAttribute(k_gemm12, cudaFuncAttributeMaxDynamicSharedMemorySize, smem_h);
        cudaFuncSetAttribute(k_attn2,  cudaFuncAttributeMaxDynamicSharedMemorySize, smem_attn);
        cudaStreamCreateWithFlags(&s2, cudaStreamNonBlocking);
        cudaEventCreateWithFlags(&evFork, cudaEventDisableTiming);
        cudaEventCreateWithFlags(&evJoin, cudaEventDisableTiming);
        init_done = true;
    }

    const int OUT0 = BB*DD*HIDN;
    int tail = (out_size >= OUT0 + NN*DD) ? 1 : 0;
    int mode = (out_size >= OUT0 + NN*DD + NN*KTOP) ? 1 : 0;

    cudaEventRecord(evFork, 0);
    cudaStreamWaitEvent(s2, evFork, 0);

    int misc_blocks = 768 + (tail ? 256 : 0);
    k_misc<<<misc_blocks, 256, 0, s2>>>(emb, aei, aej, w1, w2, out, mode);
    k_cos <<<dim3(8, 16), 256, 0, s2>>>(emb);
    k_topk<<<NN/8, 256, 0, s2>>>(out, mode);
    cudaEventRecord(evJoin, s2);

    k_xl<<<dim3(4, BB), 256, smem_kn>>>(data, linw, ai, aj);

    cudaStreamWaitEvent(0, evJoin, 0);
    k_attn2<<<2*BB, 256, smem_attn>>>(emb, gbias, gamma, beta);
    k_gemm12<<<dim3(4, BB), 256, smem_h>>>(b2, out);
}

// round 16
// speedup vs baseline: 1.6567x; 1.1127x over previous
#include <cuda_runtime.h>
#include <cuda_fp16.h>
#include <math.h>

#define BB   64
#define NN   512
#define FIN  256
#define DD   128
#define KTOP 20
#define HIDN 512

// ---- scratch (device globals; no allocations) ----
static __device__ __half d_xl16[BB*NN*DD];     // [b,n,d] lin(x), fp16
static __device__ __half d_gT16[BB*DD*NN];     // [b,d,n] gated GCN output (transposed), fp16
static __device__ __half d_w12T[NN*HIDN];      // [n][h2] = sum_h w1[h,n]*w2[h2,h], fp16
static __device__ float  d_p [BB*NN];
static __device__ float  d_q [BB*NN];
static __device__ float  d_rinv[NN];
static __device__ float  d_r [NN];
static __device__ float  d_s [NN];
static __device__ float  d_cosm[NN*NN];
static __device__ int    d_topk[NN*KTOP];

// ---------------- MMA / cp.async / ldmatrix helpers ----------------
__device__ __forceinline__ void mma_tf32(float c[4],
        unsigned a0, unsigned a1, unsigned a2, unsigned a3,
        unsigned b0, unsigned b1) {
    asm volatile(
        "mma.sync.aligned.m16n8k8.row.col.f32.tf32.tf32.f32 "
        "{%0,%1,%2,%3}, {%4,%5,%6,%7}, {%8,%9}, {%0,%1,%2,%3};\n"
        : "+f"(c[0]), "+f"(c[1]), "+f"(c[2]), "+f"(c[3])
        : "r"(a0), "r"(a1), "r"(a2), "r"(a3), "r"(b0), "r"(b1));
}
__device__ __forceinline__ void mma_f16(float c[4],
        unsigned a0, unsigned a1, unsigned a2, unsigned a3,
        unsigned b0, unsigned b1) {
    asm volatile(
        "mma.sync.aligned.m16n8k16.row.col.f32.f16.f16.f32 "
        "{%0,%1,%2,%3}, {%4,%5,%6,%7}, {%8,%9}, {%0,%1,%2,%3};\n"
        : "+f"(c[0]), "+f"(c[1]), "+f"(c[2]), "+f"(c[3])
        : "r"(a0), "r"(a1), "r"(a2), "r"(a3), "r"(b0), "r"(b1));
}
__device__ __forceinline__ void ldsm_x4(unsigned& r0, unsigned& r1,
                                        unsigned& r2, unsigned& r3, unsigned addr) {
    asm volatile("ldmatrix.sync.aligned.m8n8.x4.shared.b16 {%0,%1,%2,%3}, [%4];"
        : "=r"(r0), "=r"(r1), "=r"(r2), "=r"(r3) : "r"(addr));
}
__device__ __forceinline__ void ldsm_x2t(unsigned& r0, unsigned& r1, unsigned addr) {
    asm volatile("ldmatrix.sync.aligned.m8n8.x2.trans.shared.b16 {%0,%1}, [%2];"
        : "=r"(r0), "=r"(r1) : "r"(addr));
}
__device__ __forceinline__ void cpa16(void* dst, const void* src) {
    unsigned ds = (unsigned)__cvta_generic_to_shared(dst);
    asm volatile("cp.async.cg.shared.global [%0], [%1], 16;" :: "r"(ds), "l"(src));
}
#define CP_COMMIT asm volatile("cp.async.commit_group;")
#define CP_WAIT1  asm volatile("cp.async.wait_group 1;")
#define CP_WAIT0  asm volatile("cp.async.wait_group 0;")
#define NSTAGE    3

// ---- tf32 k_xl geometry ----
#define A_KN_WORDS 4352          // [32 k][136]
#define B_KN_WORDS 4608          // [128][36]
#define STG_KN     (A_KN_WORDS + B_KN_WORDS)   // 8960 w

// ---- W12 (tf32) geometry: 64(n) x 128(h2) tiles, K-chunk 32 ----
#define W12_A_W  2304            // [32 k][72w]
#define W12_STG  6912            // + [128][36w]

// ---- final gemm geometry ----
#define GF_A_W   4608            // A: [128 d][36w] (72 halves, 144 B pitch)
#define GF_B_W   4352            // B: [64 k][68w]  (136 halves, 272 B pitch)
#define GF_STG   (GF_A_W + GF_B_W)   // 8960 w

// tf32 chunk (128m): A [k][136], B [m][36]
#define CHUNK_KN(pA, pB)                                                        \
    _Pragma("unroll")                                                            \
    for (int ks = 0; ks < 4; ks++) {                                             \
        int k8 = ks*8;                                                           \
        unsigned af[4][4], bf[4][2];                                             \
        _Pragma("unroll")                                                        \
        for (int mi = 0; mi < 4; mi++) {                                         \
            int r = wm + mi*16 + g;                                              \
            af[mi][0] = (pA)[(k8+t4  )*136 + r    ];                             \
            af[mi][1] = (pA)[(k8+t4  )*136 + r + 8];                             \
            af[mi][2] = (pA)[(k8+t4+4)*136 + r    ];                             \
            af[mi][3] = (pA)[(k8+t4+4)*136 + r + 8];                             \
        }                                                                        \
        _Pragma("unroll")                                                        \
        for (int ni = 0; ni < 4; ni++) {                                         \
            int rn = wn + ni*8 + g;                                              \
            bf[ni][0] = (pB)[rn*36 + k8+t4    ];                                 \
            bf[ni][1] = (pB)[rn*36 + k8+t4 + 4];                                 \
        }                                                                        \
        _Pragma("unroll")                                                        \
        for (int mi = 0; mi < 4; mi++)                                           \
            _Pragma("unroll")                                                    \
            for (int ni = 0; ni < 4; ni++)                                       \
                mma_tf32(c[mi][ni], af[mi][0], af[mi][1], af[mi][2],             \
                         af[mi][3], bf[ni][0], bf[ni][1]);                       \
    }

// ---------------------------------------------------------------
// K_misc: fused norm + pack
// ---------------------------------------------------------------
__global__ void __launch_bounds__(256) k_misc(const float* __restrict__ emb,
                                              const float* __restrict__ aei,
                                              const float* __restrict__ aej,
                                              float* __restrict__ out) {
    int blk = blockIdx.x, tid = threadIdx.x;
    if (blk < 256) {
        int half = tid >> 7, t = tid & 127;
        int n = blk*2 + half;
        float w  = emb[n*DD + t];
        float v0 = w*w, v1 = w*aei[t], v2 = w*aej[t];
        #pragma unroll
        for (int o = 16; o; o >>= 1) {
            v0 += __shfl_xor_sync(0xffffffffu, v0, o);
            v1 += __shfl_xor_sync(0xffffffffu, v1, o);
            v2 += __shfl_xor_sync(0xffffffffu, v2, o);
        }
        __shared__ float s0[2][4], s1[2][4], s2[2][4];
        int wid = t >> 5, lane = t & 31;
        if (lane == 0) { s0[half][wid]=v0; s1[half][wid]=v1; s2[half][wid]=v2; }
        __syncthreads();
        if (t == 0) {
            d_rinv[n] = rsqrtf(s0[half][0]+s0[half][1]+s0[half][2]+s0[half][3]);
            d_r[n] = s1[half][0]+s1[half][1]+s1[half][2]+s1[half][3];
            d_s[n] = s2[half][0]+s2[half][1]+s2[half][2]+s2[half][3];
        }
    } else {
        int i = (blk - 256)*256 + tid;
        const int OUT0 = BB*DD*HIDN;
        if (i < NN*DD) out[OUT0 + i] = emb[i];
    }
}

// ---------------------------------------------------------------
// K_w12 (tf32): W12T[n][h2] = sum_h w1[h,n] * w2[h2,h]
//   A = w1 rows (k=h, m=n contiguous) -> [k][72w];  B = w2 rows -> [128][36w]
//   grid (4 h2-tiles, 8 n-tiles) = 32 CTAs; runs on its own stream,
//   depends only on inputs -> fully overlapped with xl/attn.
// ---------------------------------------------------------------
__global__ void __launch_bounds__(256) k_w12(const float* __restrict__ w1,
                                             const float* __restrict__ w2) {
    extern __shared__ unsigned smu[];
    int h20 = blockIdx.x * 128, n0 = blockIdx.y * 64;
    int tid = threadIdx.x;
    int w = tid >> 5, lane = tid & 31;
    int g = lane >> 2, t4 = lane & 3;
    int wm = (w & 1) * 32, wn = (w >> 1) * 32;
    float c[2][4][4] = {};

    #define W_LOAD(st, k0)                                                       \
        {                                                                        \
            unsigned* pA = smu + (st)*W12_STG;                                   \
            unsigned* pB = pA + W12_A_W;                                         \
            _Pragma("unroll")                                                    \
            for (int a = 0; a < 2; a++) {                                        \
                int idx = tid + a*256;                                           \
                int kk = idx >> 4, n4 = idx & 15;                                \
                cpa16(pA + kk*72 + n4*4, w1 + (size_t)((k0)+kk)*NN + n0 + n4*4); \
            }                                                                    \
            _Pragma("unroll")                                                    \
            for (int a = 0; a < 4; a++) {                                        \
                int idx = tid + a*256;                                           \
                int dd = idx >> 3, k4 = idx & 7;                                 \
                cpa16(pB + dd*36 + k4*4, w2 + (size_t)(h20+dd)*HIDN + (k0) + k4*4); \
            }                                                                    \
        }

    W_LOAD(0, 0) CP_COMMIT;
    W_LOAD(1, 32) CP_COMMIT;
    #pragma unroll 1
    for (int it = 0; it < HIDN/32; it++) {
        if (it + 1 < HIDN/32) { CP_WAIT1; } else { CP_WAIT0; }
        __syncthreads();
        if (it + 2 < HIDN/32) { W_LOAD((it+2)%NSTAGE, (it+2)*32) CP_COMMIT; }
        unsigned* pA = smu + (it%NSTAGE)*W12_STG;
        unsigned* pB = pA + W12_A_W;
        #pragma unroll
        for (int ks = 0; ks < 4; ks++) {
            int k8 = ks*8;
            unsigned af[2][4], bf[4][2];
            #pragma unroll
            for (int mi = 0; mi < 2; mi++) {
                int r = wm + mi*16 + g;
                af[mi][0] = pA[(k8+t4  )*72 + r    ];
                af[mi][1] = pA[(k8+t4  )*72 + r + 8];
                af[mi][2] = pA[(k8+t4+4)*72 + r    ];
                af[mi][3] = pA[(k8+t4+4)*72 + r + 8];
            }
            #pragma unroll
            for (int ni = 0; ni < 4; ni++) {
                int rn = wn + ni*8 + g;
                bf[ni][0] = pB[rn*36 + k8+t4    ];
                bf[ni][1] = pB[rn*36 + k8+t4 + 4];
            }
            #pragma unroll
            for (int mi = 0; mi < 2; mi++)
                #pragma unroll
                for (int ni = 0; ni < 4; ni++)
                    mma_tf32(c[mi][ni], af[mi][0], af[mi][1], af[mi][2],
                             af[mi][3], bf[ni][0], bf[ni][1]);
        }
    }
    #undef W_LOAD
    #pragma unroll
    for (int mi = 0; mi < 2; mi++)
        #pragma unroll
        for (int ni = 0; ni < 4; ni++) {
            int row = n0 + wm + mi*16 + g, col = h20 + wn + ni*8 + t4*2;
            *(__half2*)&d_w12T[(size_t)(row    )*HIDN + col] =
                __floats2half2_rn(c[mi][ni][0], c[mi][ni][1]);
            *(__half2*)&d_w12T[(size_t)(row + 8)*HIDN + col] =
                __floats2half2_rn(c[mi][ni][2], c[mi][ni][3]);
        }
}

// ---------------------------------------------------------------
// K1: cosine matrix — 32(i) x 64(j) tiles, grid (8,16)
// ---------------------------------------------------------------
__global__ void __launch_bounds__(256) k_cos(const float* __restrict__ emb) {
    __shared__ float sAt[32][36];
    __shared__ float sBt[32][68];
    int i0 = blockIdx.y * 32, j0 = blockIdx.x * 64;
    int tid = threadIdx.x;
    int tx = tid & 15, ty = tid >> 4;
    float c[2][4] = {};
    for (int k0 = 0; k0 < DD; k0 += 32) {
        #pragma unroll
        for (int a = 0; a < 4; a++) {
            int idx = tid + a*256;
            int row = idx >> 5, kk = idx & 31;
            sAt[kk][row] = emb[(i0+row)*DD + k0 + kk];
        }
        #pragma unroll
        for (int a = 0; a < 8; a++) {
            int idx = tid + a*256;
            int row = idx >> 5, kk = idx & 31;
            sBt[kk][row] = emb[(j0+row)*DD + k0 + kk];
        }
        __syncthreads();
        #pragma unroll
        for (int kk = 0; kk < 32; kk++) {
            float av[2], bv[4];
            *(float2*)av = *(const float2*)&sAt[kk][ty*2];
            *(float4*)bv = *(const float4*)&sBt[kk][tx*4];
            #pragma unroll
            for (int ii = 0; ii < 2; ii++)
                #pragma unroll
                for (int jj = 0; jj < 4; jj++)
                    c[ii][jj] += av[ii]*bv[jj];
        }
        __syncthreads();
    }
    float rj[4];
    #pragma unroll
    for (int jj = 0; jj < 4; jj++) rj[jj] = d_rinv[j0 + tx*4 + jj];
    #pragma unroll
    for (int ii = 0; ii < 2; ii++) {
        float ri = d_rinv[i0 + ty*2 + ii];
        float4 v;
        v.x = c[ii][0]*ri*rj[0]; v.y = c[ii][1]*ri*rj[1];
        v.z = c[ii][2]*ri*rj[2]; v.w = c[ii][3]*ri*rj[3];
        *(float4*)&d_cosm[(i0 + ty*2 + ii)*NN + j0 + tx*4] = v;
    }
}

// ---------------------------------------------------------------
// K2: top-20 per row (+ optional topk pack into out tail)
// ---------------------------------------------------------------
__global__ void k_topk(float* __restrict__ out, int mode) {
    int row  = (blockIdx.x*256 + threadIdx.x) >> 5;
    int lane = threadIdx.x & 31;
    float v[16];
    #pragma unroll
    for (int j = 0; j < 16; j++) v[j] = d_cosm[row*NN + lane + 32*j];
    for (int t = 0; t < KTOP; t++) {
        float bv = v[0]; int bj = 0;
        #pragma unroll
        for (int j = 1; j < 16; j++)
            if (v[j] > bv) { bv = v[j]; bj = j; }
        int bidx = lane + 32*bj;
        #pragma unroll
        for (int o = 16; o; o >>= 1) {
            float ov = __shfl_xor_sync(0xffffffffu, bv, o);
            int   oi = __shfl_xor_sync(0xffffffffu, bidx, o);
            if (ov > bv || (ov == bv && oi < bidx)) { bv = ov; bidx = oi; }
        }
        if (lane == 0) {
            d_topk[row*KTOP + t] = bidx;
            if (mode) out[BB*DD*HIDN + NN*DD + row*KTOP + t] = (float)bidx;
        }
        #pragma unroll
        for (int j = 0; j < 16; j++)
            if (lane + 32*j == bidx) v[j] = -INFINITY;
    }
}

// ---------------------------------------------------------------
// K3: xl (tf32 MMA, 3-stage) + fused p/q epilogue.
// ---------------------------------------------------------------
__global__ void __launch_bounds__(256, 2) k_xl(const float* __restrict__ data,
                                               const float* __restrict__ linw,
                                               const float* __restrict__ ai,
                                               const float* __restrict__ aj) {
    extern __shared__ unsigned smu[];
    __shared__ float spq[DD][2];
    int b = blockIdx.y, n0 = blockIdx.x * 128;
    int tid = threadIdx.x;
    int w = tid >> 5, lane = tid & 31;
    int g = lane >> 2, t4 = lane & 3;
    int wm = (w & 1) * 64, wn = (w >> 1) * 32;
    if (tid < DD) { spq[tid][0] = 0.f; spq[tid][1] = 0.f; }
    float c[4][4][4] = {};

    #define XL_LOAD(st, f0)                                                      \
        {                                                                        \
            unsigned* pA = smu + (st)*STG_KN;                                    \
            unsigned* pB = pA + A_KN_WORDS;                                      \
            _Pragma("unroll")                                                    \
            for (int a = 0; a < 4; a++) {                                        \
                int idx = tid + a*256;                                           \
                int kk = idx >> 5, n4 = idx & 31;                                \
                cpa16(pA + kk*136 + n4*4,                                        \
                      data + ((size_t)b*FIN + (f0) + kk)*NN + n0 + n4*4);        \
            }                                                                    \
            _Pragma("unroll")                                                    \
            for (int a = 0; a < 4; a++) {                                        \
                int idx = tid + a*256;                                           \
                int dd = idx >> 3, k4 = idx & 7;                                 \
                cpa16(pB + dd*36 + k4*4, linw + dd*FIN + (f0) + k4*4);           \
            }                                                                    \
        }

    XL_LOAD(0, 0) CP_COMMIT;
    XL_LOAD(1, 32) CP_COMMIT;
    #pragma unroll 1
    for (int it = 0; it < FIN/32; it++) {
        if (it + 1 < FIN/32) { CP_WAIT1; } else { CP_WAIT0; }
        __syncthreads();
        if (it + 2 < FIN/32) { XL_LOAD((it+2)%NSTAGE, (it+2)*32) CP_COMMIT; }
        unsigned* pA = smu + (it%NSTAGE)*STG_KN;
        unsigned* pB = pA + A_KN_WORDS;
        CHUNK_KN(pA, pB)
    }
    #undef XL_LOAD

    float pv[8] = {}, qv[8] = {};
    #pragma unroll
    for (int mi = 0; mi < 4; mi++)
        #pragma unroll
        for (int ni = 0; ni < 4; ni++) {
            int row = n0 + wm + mi*16 + g, col = wn + ni*8 + t4*2;
            size_t i0 = ((size_t)b*NN + row    )*DD + col;
            size_t i1 = ((size_t)b*NN + row + 8)*DD + col;
            *(__half2*)&d_xl16[i0] = __floats2half2_rn(c[mi][ni][0], c[mi][ni][1]);
            *(__half2*)&d_xl16[i1] = __floats2half2_rn(c[mi][ni][2], c[mi][ni][3]);
            float a0 = ai[col], a1 = ai[col+1];
            float j0 = aj[col], j1 = aj[col+1];
            pv[mi*2  ] += c[mi][ni][0]*a0 + c[mi][ni][1]*a1;
            pv[mi*2+1] += c[mi][ni][2]*a0 + c[mi][ni][3]*a1;
            qv[mi*2  ] += c[mi][ni][0]*j0 + c[mi][ni][1]*j1;
            qv[mi*2+1] += c[mi][ni][2]*j0 + c[mi][ni][3]*j1;
        }
    #pragma unroll
    for (int r = 0; r < 8; r++) {
        pv[r] += __shfl_xor_sync(0xffffffffu, pv[r], 1);
        pv[r] += __shfl_xor_sync(0xffffffffu, pv[r], 2);
        qv[r] += __shfl_xor_sync(0xffffffffu, qv[r], 1);
        qv[r] += __shfl_xor_sync(0xffffffffu, qv[r], 2);
    }
    if (t4 == 0) {
        #pragma unroll
        for (int mi = 0; mi < 4; mi++) {
            int r0 = wm + mi*16 + g;
            atomicAdd(&spq[r0][0],   pv[mi*2]);
            atomicAdd(&spq[r0][1],   qv[mi*2]);
            atomicAdd(&spq[r0+8][0], pv[mi*2+1]);
            atomicAdd(&spq[r0+8][1], qv[mi*2+1]);
        }
    }
    __syncthreads();
    if (tid < 2*DD) {
        int row = tid >> 1, which = tid & 1;
        float v = spq[row][which];
        if (which == 0) d_p[b*NN + n0 + row] = v;
        else            d_q[b*NN + n0 + row] = v;
    }
}

// ---------------------------------------------------------------
// K5: attention with smem-cached xl16 batch slice + gts staging.
// ---------------------------------------------------------------
#define GTS_PITCH 264
__global__ void __launch_bounds__(256, 1) k_attn2(const float* __restrict__ emb,
                                                  const float* __restrict__ gbias,
                                                  const float* __restrict__ gamma,
                                                  const float* __restrict__ beta) {
    extern __shared__ __half smh[];
    __half* xlc = smh;                 // [512][128] fp16 = 131072 B
    __half* gts = smh + NN*DD;         // [128][GTS_PITCH] = 67584 B
    int b = blockIdx.x >> 1, nhalf = blockIdx.x & 1;
    int n0 = nhalf * 256;
    int tid = threadIdx.x, wrp = tid >> 5, lane = tid & 31;

    const __half* src = d_xl16 + (size_t)b*NN*DD;
    #pragma unroll
    for (int a = 0; a < 32; a++) {
        int idx = tid + a*256;
        cpa16(xlc + idx*8, src + idx*8);
    }
    CP_COMMIT; CP_WAIT0;
    __syncthreads();

    const float inv = rsqrtf(1.0f + 1e-5f);
    for (int i = 0; i < 32; i++) {
        int n = n0 + wrp*32 + i;
        int widx = b*NN + n;
        int src_k = 0; float alpha = -1e30f;
        if (lane < KTOP) {
            src_k = d_topk[n*KTOP + lane];
            alpha = d_p[widx] + d_r[n] + d_q[b*NN + src_k] + d_s[src_k];
            alpha = alpha > 0.f ? alpha : 0.2f*alpha;
        }
        float m = alpha;
        #pragma unroll
        for (int o = 16; o; o >>= 1) m = fmaxf(m, __shfl_xor_sync(0xffffffffu, m, o));
        float ex = (lane < KTOP) ? __expf(alpha - m) : 0.f;
        float sm = ex;
        #pragma unroll
        for (int o = 16; o; o >>= 1) sm += __shfl_xor_sync(0xffffffffu, sm, o);
        float aw = __fdividef(ex, sm);

        float2 acc0 = {0.f,0.f}, acc1 = {0.f,0.f};
        #pragma unroll
        for (int k = 0; k < KTOP; k++) {
            int   sk = __shfl_sync(0xffffffffu, src_k, k);
            float ak = __shfl_sync(0xffffffffu, aw,  k);
            const __half2* xr = (const __half2*)(xlc + sk*DD);
            float2 f0 = __half22float2(xr[lane]);
            float2 f1 = __half22float2(xr[lane + 32]);
            acc0.x += ak*f0.x; acc0.y += ak*f0.y;
            acc1.x += ak*f1.x; acc1.y += ak*f1.y;
        }
        int d0 = 2*lane, d1 = 2*lane + 64;
        float h0 = fmaxf((acc0.x + gbias[d0  ])*(gamma[d0  ]*inv) + beta[d0  ], 0.f) * emb[n*DD + d0];
        float h1 = fmaxf((acc0.y + gbias[d0+1])*(gamma[d0+1]*inv) + beta[d0+1], 0.f) * emb[n*DD + d0+1];
        float h2 = fmaxf((acc1.x + gbias[d1  ])*(gamma[d1  ]*inv) + beta[d1  ], 0.f) * emb[n*DD + d1];
        float h3 = fmaxf((acc1.y + gbias[d1+1])*(gamma[d1+1]*inv) + beta[d1+1], 0.f) * emb[n*DD + d1+1];
        int nn = n - n0;
        gts[(d0  )*GTS_PITCH + nn] = __float2half(h0);
        gts[(d0+1)*GTS_PITCH + nn] = __float2half(h1);
        gts[(d1  )*GTS_PITCH + nn] = __float2half(h2);
        gts[(d1+1)*GTS_PITCH + nn] = __float2half(h3);
    }
    __syncthreads();
    for (int row = wrp; row < DD; row += 8) {
        *(uint4*)(d_gT16 + ((size_t)b*DD + row)*NN + n0 + lane*8) =
            *(uint4*)(gts + row*GTS_PITCH + lane*8);
    }
}

// ---------------------------------------------------------------
// K_gfin (fp16 MMA): out[b,d,h2] = sigmoid(sum_n gT[b,d,n]*W12T[n,h2] + b2)
//   A: gT [d][n] via ldmatrix (144 B pitch); B: W12T [n(k)][h2] via
//   ldmatrix.trans (272 B pitch).  K = 512, chunk 64, 8 iters, 3-stage.
// ---------------------------------------------------------------
__global__ void __launch_bounds__(256, 2) k_gfin(const float* __restrict__ b2,
                                                 float* __restrict__ out) {
    extern __shared__ unsigned smu[];
    int b = blockIdx.y, h20 = blockIdx.x * 128;
    int tid = threadIdx.x;
    int w = tid >> 5, lane = tid & 31;
    int g = lane >> 2, t4 = lane & 3;
    int wm = (w & 1) * 64, wn = (w >> 1) * 32;
    unsigned smemBase = (unsigned)__cvta_generic_to_shared(smu);
    float c[4][4][4] = {};

    #define GF_LOAD(st, k0)                                                      \
        {                                                                        \
            unsigned* pA = smu + (st)*GF_STG;                                    \
            unsigned* pB = pA + GF_A_W;                                          \
            _Pragma("unroll")                                                    \
            for (int a = 0; a < 4; a++) {                                        \
                int idx = tid + a*256;                                           \
                int row = idx >> 3, seg = idx & 7;                               \
                cpa16(pA + row*36 + seg*4,                                       \
                      d_gT16 + ((size_t)b*DD + row)*NN + (k0) + seg*8);          \
            }                                                                    \
            _Pragma("unroll")                                                    \
            for (int a = 0; a < 4; a++) {                                        \
                int idx = tid + a*256;                                           \
                int row = idx >> 4, seg = idx & 15;                              \
                cpa16(pB + row*68 + seg*4,                                       \
                      d_w12T + (size_t)((k0)+row)*HIDN + h20 + seg*8);           \
            }                                                                    \
        }

    GF_LOAD(0, 0) CP_COMMIT;
    GF_LOAD(1, 64) CP_COMMIT;
    #pragma unroll 1
    for (int it = 0; it < NN/64; it++) {
        if (it + 1 < NN/64) { CP_WAIT1; } else { CP_WAIT0; }
        __syncthreads();
        if (it + 2 < NN/64) { GF_LOAD((it+2)%NSTAGE, (it+2)*64) CP_COMMIT; }
        unsigned aB = smemBase + ((it%NSTAGE)*GF_STG)*4;
        unsigned bB = aB + GF_A_W*4;
        unsigned aRow = ((lane>>3)&1)*8 + (lane&7);
        unsigned aK   = (lane>>4)*16;
        unsigned bR   = lane & 15;
        #pragma unroll
        for (int ks = 0; ks < 4; ks++) {
            unsigned af[4][4], bf[4][2];
            #pragma unroll
            for (int mi = 0; mi < 4; mi++)
                ldsm_x4(af[mi][0], af[mi][1], af[mi][2], af[mi][3],
                        aB + (wm + mi*16 + aRow)*144 + ks*32 + aK);
            #pragma unroll
            for (int ni = 0; ni < 4; ni++)
                ldsm_x2t(bf[ni][0], bf[ni][1],
                         bB + (ks*16 + bR)*272 + (wn + ni*8)*2);
            #pragma unroll
            for (int mi = 0; mi < 4; mi++)
                #pragma unroll
                for (int ni = 0; ni < 4; ni++)
                    mma_f16(c[mi][ni], af[mi][0], af[mi][1], af[mi][2],
                            af[mi][3], bf[ni][0], bf[ni][1]);
        }
    }
    #undef GF_LOAD
    #pragma unroll
    for (int mi = 0; mi < 4; mi++)
        #pragma unroll
        for (int ni = 0; ni < 4; ni++) {
            int row = wm + mi*16 + g, col = h20 + wn + ni*8 + t4*2;
            float bb0 = b2[col], bb1 = b2[col + 1];
            float2 v0, v1;
            v0.x = __fdividef(1.0f, 1.0f + __expf(-(c[mi][ni][0] + bb0)));
            v0.y = __fdividef(1.0f, 1.0f + __expf(-(c[mi][ni][1] + bb1)));
            v1.x = __fdividef(1.0f, 1.0f + __expf(-(c[mi][ni][2] + bb0)));
            v1.y = __fdividef(1.0f, 1.0f + __expf(-(c[mi][ni][3] + bb1)));
            *(float2*)&out[((size_t)b*DD + row    )*HIDN + col] = v0;
            *(float2*)&out[((size_t)b*DD + row + 8)*HIDN + col] = v1;
        }
}

extern "C" void kernel_launch(void* const* d_in, const int* in_sizes, int n_in,
                              void* d_out, int out_size) {
    const float* data  = (const float*)d_in[0];
    const float* emb   = (const float*)d_in[1];
    const float* linw  = (const float*)d_in[2];
    const float* ai    = (const float*)d_in[3];
    const float* aj    = (const float*)d_in[4];
    const float* aei   = (const float*)d_in[5];
    const float* aej   = (const float*)d_in[6];
    const float* gbias = (const float*)d_in[7];
    const float* gamma = (const float*)d_in[8];
    const float* beta  = (const float*)d_in[9];
    const float* w1    = (const float*)d_in[10];
    const float* w2    = (const float*)d_in[11];
    const float* b2    = (const float*)d_in[12];
    float* out = (float*)d_out;

    static cudaStream_t s2 = nullptr, s3 = nullptr;
    static cudaEvent_t evFork = nullptr, evJoin = nullptr, evW12 = nullptr;
    static bool init_done = false;
    const int smem_kn   = NSTAGE*STG_KN*4;           // 107520 B
    const int smem_gf   = NSTAGE*GF_STG*4;           // 107520 B
    const int smem_w12  = NSTAGE*W12_STG*4;          // 82944 B
    const int smem_attn = (NN*DD + DD*GTS_PITCH)*2;  // 198656 B
    if (!init_done) {
        cudaFuncSetAttribute(k_xl,    cudaFuncAttributeMaxDynamicSharedMemorySize, smem_kn);
        cudaFuncSetAttribute(k_gfin,  cudaFuncAttributeMaxDynamicSharedMemorySize, smem_gf);
        cudaFuncSetAttribute(k_w12,   cudaFuncAttributeMaxDynamicSharedMemorySize, smem_w12);
        cudaFuncSetAttribute(k_attn2, cudaFuncAttributeMaxDynamicSharedMemorySize, smem_attn);
        cudaStreamCreateWithFlags(&s2, cudaStreamNonBlocking);
        cudaStreamCreateWithFlags(&s3, cudaStreamNonBlocking);
        cudaEventCreateWithFlags(&evFork, cudaEventDisableTiming);
        cudaEventCreateWithFlags(&evJoin, cudaEventDisableTiming);
        cudaEventCreateWithFlags(&evW12,  cudaEventDisableTiming);
        init_done = true;
    }

    const int OUT0 = BB*DD*HIDN;
    int tail = (out_size >= OUT0 + NN*DD) ? 1 : 0;
    int mode = (out_size >= OUT0 + NN*DD + NN*KTOP) ? 1 : 0;

    cudaEventRecord(evFork, 0);
    cudaStreamWaitEvent(s2, evFork, 0);
    cudaStreamWaitEvent(s3, evFork, 0);

    // s3: W12 (inputs only) — overlapped with everything up to the final gemm
    k_w12<<<dim3(4, 8), 256, smem_w12, s3>>>(w1, w2);
    cudaEventRecord(evW12, s3);

    // s2: attn deps
    int misc_blocks = 256 + (tail ? 256 : 0);
    k_misc<<<misc_blocks, 256, 0, s2>>>(emb, aei, aej, out);
    k_cos <<<dim3(8, 16), 256, 0, s2>>>(emb);
    k_topk<<<NN/8, 256, 0, s2>>>(out, mode);
    cudaEventRecord(evJoin, s2);

    // s0: main path
    k_xl<<<dim3(4, BB), 256, smem_kn>>>(data, linw, ai, aj);

    cudaStreamWaitEvent(0, evJoin, 0);
    k_attn2<<<2*BB, 256, smem_attn>>>(emb, gbias, gamma, beta);

    cudaStreamWaitEvent(0, evW12, 0);
    k_gfin<<<dim3(4, BB), 256, smem_gf>>>(b2, out);
}